// round 4
// baseline (speedup 1.0000x reference)
#include <cuda_runtime.h>
#include <cuda_fp16.h>
#include <cuda_bf16.h>
#include <cstdint>

#define NN 100000
#define EE 1600000
#define SCAN_B 1024
#define NB ((NN + SCAN_B - 1) / SCAN_B)   // 98

typedef unsigned long long u64;
typedef unsigned int u32;

// ---------------- scratch (device globals; no allocation allowed) ----------
__device__ __nv_bfloat16 g_xh[NN * 128];   // bf16-hi of x
__device__ __nv_bfloat16 g_xl[NN * 128];   // bf16-lo of x
__device__ __nv_bfloat16 g_ah[NN * 128];   // bf16-hi of h (GEMM A operand)
__device__ __nv_bfloat16 g_al[NN * 128];   // bf16-lo of h
__device__ __nv_bfloat16 g_wh[5 * 128 * 128];  // W^T bf16-hi (slot 0=W_in, 1..4=Wl)
__device__ __nv_bfloat16 g_wl[5 * 128 * 128];  // W^T bf16-lo
__device__ uint2 g_h2h[NN * 32];           // fp16 copy of h2 rows
__device__ float g_as[NN];
__device__ float g_ad[NN];
__device__ int   g_deg[NN];
__device__ int   g_incl[NN];
__device__ int   g_cursor[NN];
__device__ int   g_rowptr[NN + 1];
__device__ int   g_srcs[EE];
__device__ int   g_bsums[128];

// ---------------- small helpers --------------------------------------------
__device__ __forceinline__ u32 bf2(float a, float b) {
    __nv_bfloat162 t = __floats2bfloat162_rn(a, b);
    return *reinterpret_cast<u32*>(&t);
}
__device__ __forceinline__ u32 hf2(float a, float b) {
    __half2 t = __floats2half2_rn(a, b);
    return *reinterpret_cast<u32*>(&t);
}
__device__ __forceinline__ float bf_res(float v) {   // residual after bf16-hi
    return v - __bfloat162float(__float2bfloat16_rn(v));
}

// mma.sync m16n8k16 bf16 x fp32-acc (baseline sm_80+ instruction; no *_a arch)
__device__ __forceinline__ void mma16816(
    float& c0, float& c1, float& c2, float& c3,
    u32 a0, u32 a1, u32 a2, u32 a3, u32 b0, u32 b1)
{
    asm volatile(
        "mma.sync.aligned.m16n8k16.row.col.f32.bf16.bf16.f32 "
        "{%0,%1,%2,%3}, {%4,%5,%6,%7}, {%8,%9}, {%0,%1,%2,%3};"
        : "+f"(c0), "+f"(c1), "+f"(c2), "+f"(c3)
        : "r"(a0), "r"(a1), "r"(a2), "r"(a3), "r"(b0), "r"(b1));
}

// ---------------- CSR construction -----------------------------------------
__global__ void k_zero() {
    int i = blockIdx.x * blockDim.x + threadIdx.x;
    if (i < NN) { g_deg[i] = 0; g_cursor[i] = 0; }
}
__global__ void k_hist(const int* __restrict__ ei) {
    int e = blockIdx.x * blockDim.x + threadIdx.x;
    if (e < EE) atomicAdd(&g_deg[ei[EE + e]], 1);
}
__global__ void k_scan_block() {
    __shared__ int sh[SCAN_B];
    int i = blockIdx.x * SCAN_B + threadIdx.x;
    int v = (i < NN) ? g_deg[i] : 0;
    sh[threadIdx.x] = v;
    __syncthreads();
    for (int off = 1; off < SCAN_B; off <<= 1) {
        int t = 0;
        if (threadIdx.x >= off) t = sh[threadIdx.x - off];
        __syncthreads();
        if (threadIdx.x >= off) sh[threadIdx.x] += t;
        __syncthreads();
    }
    if (i < NN) g_incl[i] = sh[threadIdx.x];
    if (threadIdx.x == SCAN_B - 1) g_bsums[blockIdx.x] = sh[SCAN_B - 1];
}
__global__ void k_scan_bsums() {
    __shared__ int sh[128];
    int t = threadIdx.x;
    sh[t] = (t < NB) ? g_bsums[t] : 0;
    __syncthreads();
    for (int off = 1; off < 128; off <<= 1) {
        int v = 0;
        if (t >= off) v = sh[t - off];
        __syncthreads();
        if (t >= off) sh[t] += v;
        __syncthreads();
    }
    if (t < NB) g_bsums[t] = sh[t];
}
__global__ void k_scan_fix() {
    int i = blockIdx.x * SCAN_B + threadIdx.x;
    if (i < NN) {
        int off = (blockIdx.x > 0) ? g_bsums[blockIdx.x - 1] : 0;
        g_rowptr[i + 1] = g_incl[i] + off;
    }
    if (i == 0) g_rowptr[0] = 0;
}
__global__ void k_scatter(const int* __restrict__ ei) {
    int e = blockIdx.x * blockDim.x + threadIdx.x;
    if (e >= EE) return;
    int s = ei[e];
    int d = ei[EE + e];
    int pos = g_rowptr[d] + atomicAdd(&g_cursor[d], 1);
    g_srcs[pos] = s;
}

// ---------------- weight prep: transpose + bf16 hi/lo split ----------------
__global__ void k_prep_w(const float* __restrict__ W_in, const float* __restrict__ Wl) {
    int idx = blockIdx.x * blockDim.x + threadIdx.x;   // over 5*16384
    if (idx >= 5 * 16384) return;
    int l = idx >> 14;
    int r = idx & 16383;
    int n = r >> 7;
    int k = r & 127;
    float v = (l == 0) ? W_in[k * 128 + n] : Wl[(l - 1) * 16384 + k * 128 + n];
    __nv_bfloat16 hi = __float2bfloat16_rn(v);
    g_wh[l * 16384 + n * 128 + k] = hi;
    g_wl[l * 16384 + n * 128 + k] = __float2bfloat16_rn(v - __bfloat162float(hi));
}

// ---------------- x -> bf16 hi/lo -------------------------------------------
__global__ void k_convert_x(const float* __restrict__ x) {
    int idx = blockIdx.x * blockDim.x + threadIdx.x;   // over NN*32 float4s
    if (idx >= NN * 32) return;
    float4 v = ((const float4*)x)[idx];
    uint2 hi, lo;
    hi.x = bf2(v.x, v.y); hi.y = bf2(v.z, v.w);
    lo.x = bf2(bf_res(v.x), bf_res(v.y)); lo.y = bf2(bf_res(v.z), bf_res(v.w));
    ((uint2*)g_xh)[idx] = hi;
    ((uint2*)g_xl)[idx] = lo;
}

// ---------------- HMMA GEMM: tile M=128, N=128, K=128, split bf16 ----------
// 8 warps; each warp computes 16 rows x 128 cols with mma.sync.m16n8k16.
// mode 0: out = leaky(acc + bias, 0.01) -> bf16 hi/lo into g_ah/g_al
// mode 1: att dots -> g_as/g_ad; fp16 row copy -> g_h2h
__global__ __launch_bounds__(256) void mma_gemm(
    const __nv_bfloat16* __restrict__ Ah, const __nv_bfloat16* __restrict__ Al,
    int wslot, int mode,
    const float* __restrict__ bias,
    const float* __restrict__ attS, const float* __restrict__ attD)
{
    const int tid  = threadIdx.x;
    const int warp = tid >> 5;
    const int lane = tid & 31;
    const int g = lane >> 2;       // group 0..7
    const int t = lane & 3;        // tid-in-group

    const int rowg = blockIdx.x * 128 + warp * 16 + g;   // rows for c0/c1
    const int rowh = rowg + 8;                           // rows for c2/c3
    const int r0 = (rowg < NN) ? rowg : (NN - 1);        // clamped load rows
    const int r1 = (rowh < NN) ? rowh : (NN - 1);

    const u32* __restrict__ a_hi0 = (const u32*)Ah + (size_t)r0 * 64;
    const u32* __restrict__ a_hi1 = (const u32*)Ah + (size_t)r1 * 64;
    const u32* __restrict__ a_lo0 = (const u32*)Al + (size_t)r0 * 64;
    const u32* __restrict__ a_lo1 = (const u32*)Al + (size_t)r1 * 64;
    const u32* __restrict__ wh = (const u32*)(g_wh + (size_t)wslot * 16384);
    const u32* __restrict__ wl = (const u32*)(g_wl + (size_t)wslot * 16384);

    float acc[16][4];
#pragma unroll
    for (int nb = 0; nb < 16; ++nb)
#pragma unroll
        for (int j = 0; j < 4; ++j) acc[nb][j] = 0.f;

    for (int ks = 0; ks < 8; ++ks) {       // k0 = ks*16
        const int kw = ks * 8 + t;         // u32 index of k-pair (cols 2t,2t+1)
        u32 ah0 = a_hi0[kw],     ah1 = a_hi1[kw];
        u32 ah2 = a_hi0[kw + 4], ah3 = a_hi1[kw + 4];
        u32 al0 = a_lo0[kw],     al1 = a_lo1[kw];
        u32 al2 = a_lo0[kw + 4], al3 = a_lo1[kw + 4];
#pragma unroll
        for (int nb = 0; nb < 16; ++nb) {
            const int nrow = nb * 8 + g;           // B column (output col group)
            u32 bh0 = wh[nrow * 64 + kw];
            u32 bh1 = wh[nrow * 64 + kw + 4];
            u32 bl0 = wl[nrow * 64 + kw];
            u32 bl1 = wl[nrow * 64 + kw + 4];
            mma16816(acc[nb][0], acc[nb][1], acc[nb][2], acc[nb][3],
                     ah0, ah1, ah2, ah3, bh0, bh1);
            mma16816(acc[nb][0], acc[nb][1], acc[nb][2], acc[nb][3],
                     ah0, ah1, ah2, ah3, bl0, bl1);
            mma16816(acc[nb][0], acc[nb][1], acc[nb][2], acc[nb][3],
                     al0, al1, al2, al3, bh0, bh1);
        }
    }

    // -------- epilogue --------
    const bool vg = rowg < NN;
    const bool vh = rowh < NN;

    if (mode == 0) {
        u32* dhg = (u32*)g_ah + (size_t)rowg * 64;
        u32* dlg = (u32*)g_al + (size_t)rowg * 64;
        u32* dhh = (u32*)g_ah + (size_t)rowh * 64;
        u32* dlh = (u32*)g_al + (size_t)rowh * 64;
#pragma unroll
        for (int nb = 0; nb < 16; ++nb) {
            const int c0 = nb * 8 + 2 * t;
            float b0 = __ldg(bias + c0), b1 = __ldg(bias + c0 + 1);
            float f0 = acc[nb][0] + b0, f1 = acc[nb][1] + b1;
            float f2 = acc[nb][2] + b0, f3 = acc[nb][3] + b1;
            f0 = (f0 > 0.f) ? f0 : 0.01f * f0;
            f1 = (f1 > 0.f) ? f1 : 0.01f * f1;
            f2 = (f2 > 0.f) ? f2 : 0.01f * f2;
            f3 = (f3 > 0.f) ? f3 : 0.01f * f3;
            const int ui = nb * 4 + t;
            if (vg) {
                dhg[ui] = bf2(f0, f1);
                dlg[ui] = bf2(bf_res(f0), bf_res(f1));
            }
            if (vh) {
                dhh[ui] = bf2(f2, f3);
                dlh[ui] = bf2(bf_res(f2), bf_res(f3));
            }
        }
    } else {
        float sg = 0.f, dg = 0.f, sh = 0.f, dh = 0.f;
        u32* hg = (u32*)g_h2h + (size_t)rowg * 64;
        u32* hh = (u32*)g_h2h + (size_t)rowh * 64;
#pragma unroll
        for (int nb = 0; nb < 16; ++nb) {
            const int c0 = nb * 8 + 2 * t;
            float s0 = __ldg(attS + c0), s1 = __ldg(attS + c0 + 1);
            float d0 = __ldg(attD + c0), d1 = __ldg(attD + c0 + 1);
            float f0 = acc[nb][0], f1 = acc[nb][1];
            float f2 = acc[nb][2], f3 = acc[nb][3];
            sg += f0 * s0 + f1 * s1;
            dg += f0 * d0 + f1 * d1;
            sh += f2 * s0 + f3 * s1;
            dh += f2 * d0 + f3 * d1;
            const int ui = nb * 4 + t;
            if (vg) hg[ui] = hf2(f0, f1);
            if (vh) hh[ui] = hf2(f2, f3);
        }
        // reduce over the 4 lanes of each group (lane bits 0..1)
#pragma unroll
        for (int o = 1; o <= 2; o <<= 1) {
            sg += __shfl_xor_sync(0xffffffffu, sg, o);
            dg += __shfl_xor_sync(0xffffffffu, dg, o);
            sh += __shfl_xor_sync(0xffffffffu, sh, o);
            dh += __shfl_xor_sync(0xffffffffu, dh, o);
        }
        if (t == 0) {
            if (vg) { g_as[rowg] = sg; g_ad[rowg] = dg; }
            if (vh) { g_as[rowh] = sh; g_ad[rowh] = dh; }
        }
    }
}

// ------- warp-per-node: online softmax aggregate + bias + LN + leaky --------
// outf != null (last layer): write fp32 to outf; else write bf16 hi/lo pair
__global__ __launch_bounds__(256) void k_agg(
    const float* __restrict__ bias, const float* __restrict__ gamma,
    const float* __restrict__ beta, float* __restrict__ outf)
{
    int v = (blockIdx.x * blockDim.x + threadIdx.x) >> 5;
    int lane = threadIdx.x & 31;
    if (v >= NN) return;

    int beg = g_rowptr[v];
    int end = g_rowptr[v + 1];
    float adv = g_ad[v];

    float mx = -1e30f, dn = 0.f;
    for (int j = beg + lane; j < end; j += 32) {
        float e = g_as[g_srcs[j]] + adv;
        e = (e > 0.f) ? e : 0.2f * e;
        float mn = fmaxf(mx, e);
        dn = dn * __expf(mx - mn) + __expf(e - mn);
        mx = mn;
    }
#pragma unroll
    for (int o = 16; o > 0; o >>= 1) {
        float mo = __shfl_xor_sync(0xffffffffu, mx, o);
        float do_ = __shfl_xor_sync(0xffffffffu, dn, o);
        float mn = fmaxf(mx, mo);
        dn = dn * __expf(mx - mn) + do_ * __expf(mo - mn);
        mx = mn;
    }
    float winv = (end > beg) ? 1.f / (dn + 1e-16f) : 0.f;

    float4 acc = make_float4(0.f, 0.f, 0.f, 0.f);
    for (int j = beg; j < end; ++j) {
        int s = g_srcs[j];
        float e = g_as[s] + adv;
        e = (e > 0.f) ? e : 0.2f * e;
        float w = __expf(e - mx) * winv;
        uint2 hv = g_h2h[(size_t)s * 32 + lane];
        __half2 h0 = *reinterpret_cast<__half2*>(&hv.x);
        __half2 h1 = *reinterpret_cast<__half2*>(&hv.y);
        float2 f0 = __half22float2(h0);
        float2 f1 = __half22float2(h1);
        acc.x += w * f0.x; acc.y += w * f0.y;
        acc.z += w * f1.x; acc.w += w * f1.y;
    }

    float4 b4 = ((const float4*)bias)[lane];
    acc.x += b4.x; acc.y += b4.y; acc.z += b4.z; acc.w += b4.w;

    float sum = acc.x + acc.y + acc.z + acc.w;
    float sq  = acc.x * acc.x + acc.y * acc.y + acc.z * acc.z + acc.w * acc.w;
#pragma unroll
    for (int o = 16; o > 0; o >>= 1) {
        sum += __shfl_xor_sync(0xffffffffu, sum, o);
        sq  += __shfl_xor_sync(0xffffffffu, sq, o);
    }
    float mu = sum * (1.f / 128.f);
    float var = sq * (1.f / 128.f) - mu * mu;
    float rstd = rsqrtf(var + 1e-5f);

    float4 g4 = ((const float4*)gamma)[lane];
    float4 be4 = ((const float4*)beta)[lane];
    float4 o4;
    o4.x = (acc.x - mu) * rstd * g4.x + be4.x;
    o4.y = (acc.y - mu) * rstd * g4.y + be4.y;
    o4.z = (acc.z - mu) * rstd * g4.z + be4.z;
    o4.w = (acc.w - mu) * rstd * g4.w + be4.w;
    o4.x = (o4.x > 0.f) ? o4.x : 0.01f * o4.x;
    o4.y = (o4.y > 0.f) ? o4.y : 0.01f * o4.y;
    o4.z = (o4.z > 0.f) ? o4.z : 0.01f * o4.z;
    o4.w = (o4.w > 0.f) ? o4.w : 0.01f * o4.w;

    if (outf) {
        ((float4*)(outf + (size_t)v * 128))[lane] = o4;
    } else {
        uint2 hi, lo;
        hi.x = bf2(o4.x, o4.y); hi.y = bf2(o4.z, o4.w);
        lo.x = bf2(bf_res(o4.x), bf_res(o4.y)); lo.y = bf2(bf_res(o4.z), bf_res(o4.w));
        ((uint2*)g_ah)[(size_t)v * 32 + lane] = hi;
        ((uint2*)g_al)[(size_t)v * 32 + lane] = lo;
    }
}

// ---------------- launcher --------------------------------------------------
extern "C" void kernel_launch(void* const* d_in, const int* in_sizes, int n_in,
                              void* d_out, int out_size) {
    const float* x       = (const float*)d_in[0];
    const int*   ei      = (const int*)  d_in[1];
    const float* W_in    = (const float*)d_in[2];
    const float* b_in    = (const float*)d_in[3];
    const float* Wl      = (const float*)d_in[4];
    const float* att_src = (const float*)d_in[5];
    const float* att_dst = (const float*)d_in[6];
    const float* bias_l  = (const float*)d_in[7];
    const float* gamma   = (const float*)d_in[8];
    const float* beta    = (const float*)d_in[9];
    float* out = (float*)d_out;

    const int gemm_blocks = (NN + 127) / 128;         // 782
    const int node_warp_blocks = (NN + 7) / 8;        // 12500

    __nv_bfloat16 *pxh = nullptr, *pxl = nullptr, *pah = nullptr, *pal = nullptr;
    cudaGetSymbolAddress((void**)&pxh, g_xh);
    cudaGetSymbolAddress((void**)&pxl, g_xl);
    cudaGetSymbolAddress((void**)&pah, g_ah);
    cudaGetSymbolAddress((void**)&pal, g_al);

    // order chosen so the ncu-profiled launch (#3) is the tensor GEMM
    k_prep_w<<<(5 * 16384 + 255) / 256, 256>>>(W_in, Wl);            // 0
    k_convert_x<<<(NN * 32 + 255) / 256, 256>>>(x);                  // 1
    k_zero<<<(NN + 1023) / 1024, 1024>>>();                          // 2
    mma_gemm<<<gemm_blocks, 256>>>(pxh, pxl, 0, 0, b_in,             // 3 <- profiled
                                   nullptr, nullptr);
    k_hist<<<(EE + 255) / 256, 256>>>(ei);                           // 4
    k_scan_block<<<NB, SCAN_B>>>();                                  // 5
    k_scan_bsums<<<1, 128>>>();                                      // 6
    k_scan_fix<<<NB, SCAN_B>>>();                                    // 7
    k_scatter<<<(EE + 255) / 256, 256>>>(ei);                        // 8

    for (int i = 0; i < 4; i++) {
        mma_gemm<<<gemm_blocks, 256>>>(pah, pal, i + 1, 1, nullptr,
                                       att_src + i * 128, att_dst + i * 128);
        float* dst = (i == 3) ? out : nullptr;
        k_agg<<<node_warp_blocks, 256>>>(bias_l + i * 128, gamma + i * 128,
                                         beta + i * 128, dst);
    }
}

// round 5
// speedup vs baseline: 1.5537x; 1.5537x over previous
#include <cuda_runtime.h>
#include <cuda_fp16.h>
#include <cuda_bf16.h>
#include <cstdint>

#define NN 100000
#define EE 1600000
#define SCAN_B 1024
#define NB ((NN + SCAN_B - 1) / SCAN_B)   // 98

typedef unsigned long long u64;
typedef unsigned int u32;

// ---------------- scratch (device globals; no allocation allowed) ----------
__device__ __nv_bfloat16 g_xh[NN * 128];   // bf16-hi of x
__device__ __nv_bfloat16 g_xl[NN * 128];   // bf16-lo of x
__device__ __nv_bfloat16 g_ah[NN * 128];   // bf16-hi of h (GEMM A operand)
__device__ __nv_bfloat16 g_al[NN * 128];   // bf16-lo of h
__device__ __nv_bfloat16 g_wh[5 * 128 * 128];  // W^T bf16-hi (slot 0=W_in, 1..4=Wl)
__device__ __nv_bfloat16 g_wl[5 * 128 * 128];  // W^T bf16-lo
__device__ uint4 g_bfrag[5 * 16 * 8 * 32];     // W fragments: {bh0,bh1,bl0,bl1} per lane
__device__ uint2 g_h2h[NN * 32];           // fp16 copy of h2 rows
__device__ float g_as[NN];
__device__ float g_ad[NN];
__device__ int   g_deg[NN];
__device__ int   g_incl[NN];
__device__ int   g_cursor[NN];
__device__ int   g_rowptr[NN + 1];
__device__ int   g_srcs[EE];
__device__ int   g_bsums[128];

// ---------------- small helpers --------------------------------------------
__device__ __forceinline__ u32 bf2(float a, float b) {
    __nv_bfloat162 t = __floats2bfloat162_rn(a, b);
    return *reinterpret_cast<u32*>(&t);
}
__device__ __forceinline__ u32 hf2(float a, float b) {
    __half2 t = __floats2half2_rn(a, b);
    return *reinterpret_cast<u32*>(&t);
}
__device__ __forceinline__ float bf_res(float v) {   // residual after bf16-hi
    return v - __bfloat162float(__float2bfloat16_rn(v));
}

// mma.sync m16n8k16 bf16 x fp32-acc (baseline sm_80+ instruction; no *_a arch)
__device__ __forceinline__ void mma16816(
    float& c0, float& c1, float& c2, float& c3,
    u32 a0, u32 a1, u32 a2, u32 a3, u32 b0, u32 b1)
{
    asm volatile(
        "mma.sync.aligned.m16n8k16.row.col.f32.bf16.bf16.f32 "
        "{%0,%1,%2,%3}, {%4,%5,%6,%7}, {%8,%9}, {%0,%1,%2,%3};"
        : "+f"(c0), "+f"(c1), "+f"(c2), "+f"(c3)
        : "r"(a0), "r"(a1), "r"(a2), "r"(a3), "r"(b0), "r"(b1));
}

// ---------------- CSR construction -----------------------------------------
__global__ void k_zero() {
    int i = blockIdx.x * blockDim.x + threadIdx.x;
    if (i < NN) { g_deg[i] = 0; g_cursor[i] = 0; }
}
__global__ void k_hist(const int* __restrict__ ei) {
    int e = blockIdx.x * blockDim.x + threadIdx.x;
    if (e < EE) atomicAdd(&g_deg[ei[EE + e]], 1);
}
__global__ void k_scan_block() {
    __shared__ int sh[SCAN_B];
    int i = blockIdx.x * SCAN_B + threadIdx.x;
    int v = (i < NN) ? g_deg[i] : 0;
    sh[threadIdx.x] = v;
    __syncthreads();
    for (int off = 1; off < SCAN_B; off <<= 1) {
        int t = 0;
        if (threadIdx.x >= off) t = sh[threadIdx.x - off];
        __syncthreads();
        if (threadIdx.x >= off) sh[threadIdx.x] += t;
        __syncthreads();
    }
    if (i < NN) g_incl[i] = sh[threadIdx.x];
    if (threadIdx.x == SCAN_B - 1) g_bsums[blockIdx.x] = sh[SCAN_B - 1];
}
__global__ void k_scan_bsums() {
    __shared__ int sh[128];
    int t = threadIdx.x;
    sh[t] = (t < NB) ? g_bsums[t] : 0;
    __syncthreads();
    for (int off = 1; off < 128; off <<= 1) {
        int v = 0;
        if (t >= off) v = sh[t - off];
        __syncthreads();
        if (t >= off) sh[t] += v;
        __syncthreads();
    }
    if (t < NB) g_bsums[t] = sh[t];
}
__global__ void k_scan_fix() {
    int i = blockIdx.x * SCAN_B + threadIdx.x;
    if (i < NN) {
        int off = (blockIdx.x > 0) ? g_bsums[blockIdx.x - 1] : 0;
        g_rowptr[i + 1] = g_incl[i] + off;
    }
    if (i == 0) g_rowptr[0] = 0;
}
__global__ void k_scatter(const int* __restrict__ ei) {
    int e = blockIdx.x * blockDim.x + threadIdx.x;
    if (e >= EE) return;
    int s = ei[e];
    int d = ei[EE + e];
    int pos = g_rowptr[d] + atomicAdd(&g_cursor[d], 1);
    g_srcs[pos] = s;
}

// ---------------- weight prep: transpose + bf16 hi/lo split ----------------
__global__ void k_prep_w(const float* __restrict__ W_in, const float* __restrict__ Wl) {
    int idx = blockIdx.x * blockDim.x + threadIdx.x;   // over 5*16384
    if (idx >= 5 * 16384) return;
    int l = idx >> 14;
    int r = idx & 16383;
    int n = r >> 7;
    int k = r & 127;
    float v = (l == 0) ? W_in[k * 128 + n] : Wl[(l - 1) * 16384 + k * 128 + n];
    __nv_bfloat16 hi = __float2bfloat16_rn(v);
    g_wh[l * 16384 + n * 128 + k] = hi;
    g_wl[l * 16384 + n * 128 + k] = __float2bfloat16_rn(v - __bfloat162float(hi));
}

// ---- pack W into per-lane mma fragment layout: uint4 {bh0,bh1,bl0,bl1} ----
__global__ void k_prep_bfrag() {
    int idx = blockIdx.x * blockDim.x + threadIdx.x;   // over 5*16*8*32 = 20480
    if (idx >= 5 * 16 * 8 * 32) return;
    int lane = idx & 31;
    int ks = (idx >> 5) & 7;
    int nb = (idx >> 8) & 15;
    int l = idx >> 12;
    int g = lane >> 2;
    int t = lane & 3;
    int n = nb * 8 + g;
    int kw = ks * 8 + t;
    const u32* wh = (const u32*)(g_wh + (size_t)l * 16384);
    const u32* wl = (const u32*)(g_wl + (size_t)l * 16384);
    uint4 f;
    f.x = wh[n * 64 + kw];
    f.y = wh[n * 64 + kw + 4];
    f.z = wl[n * 64 + kw];
    f.w = wl[n * 64 + kw + 4];
    g_bfrag[idx] = f;
}

// ---------------- x -> bf16 hi/lo -------------------------------------------
__global__ void k_convert_x(const float* __restrict__ x) {
    int idx = blockIdx.x * blockDim.x + threadIdx.x;   // over NN*32 float4s
    if (idx >= NN * 32) return;
    float4 v = ((const float4*)x)[idx];
    uint2 hi, lo;
    hi.x = bf2(v.x, v.y); hi.y = bf2(v.z, v.w);
    lo.x = bf2(bf_res(v.x), bf_res(v.y)); lo.y = bf2(bf_res(v.z), bf_res(v.w));
    ((uint2*)g_xh)[idx] = hi;
    ((uint2*)g_xl)[idx] = lo;
}

// ---------------- HMMA GEMM: tile M=128, N=128, K=128, split bf16 ----------
// 8 warps; each warp computes 16 rows x 128 cols with mma.sync.m16n8k16.
// B fragments come pre-packed (one coalesced LDG.128 per (nb,ks)).
// mode 0: out = leaky(acc + bias, 0.01) -> bf16 hi/lo into g_ah/g_al
// mode 1: att dots -> g_as/g_ad; fp16 row copy -> g_h2h
__global__ __launch_bounds__(256) void mma_gemm(
    const __nv_bfloat16* __restrict__ Ah, const __nv_bfloat16* __restrict__ Al,
    int wslot, int mode,
    const float* __restrict__ bias,
    const float* __restrict__ attS, const float* __restrict__ attD)
{
    const int tid  = threadIdx.x;
    const int warp = tid >> 5;
    const int lane = tid & 31;
    const int g = lane >> 2;       // group 0..7
    const int t = lane & 3;        // tid-in-group

    const int rowg = blockIdx.x * 128 + warp * 16 + g;   // rows for c0/c1
    const int rowh = rowg + 8;                           // rows for c2/c3
    const int r0 = (rowg < NN) ? rowg : (NN - 1);        // clamped load rows
    const int r1 = (rowh < NN) ? rowh : (NN - 1);

    const u32* __restrict__ a_hi0 = (const u32*)Ah + (size_t)r0 * 64;
    const u32* __restrict__ a_hi1 = (const u32*)Ah + (size_t)r1 * 64;
    const u32* __restrict__ a_lo0 = (const u32*)Al + (size_t)r0 * 64;
    const u32* __restrict__ a_lo1 = (const u32*)Al + (size_t)r1 * 64;
    const uint4* __restrict__ bf = g_bfrag + (size_t)wslot * 16 * 8 * 32;

    float acc[16][4];
#pragma unroll
    for (int nb = 0; nb < 16; ++nb)
#pragma unroll
        for (int j = 0; j < 4; ++j) acc[nb][j] = 0.f;

    for (int ks = 0; ks < 8; ++ks) {       // k0 = ks*16
        const int kw = ks * 8 + t;         // u32 index of k-pair (cols 2t,2t+1)
        u32 ah0 = a_hi0[kw],     ah1 = a_hi1[kw];
        u32 ah2 = a_hi0[kw + 4], ah3 = a_hi1[kw + 4];
        u32 al0 = a_lo0[kw],     al1 = a_lo1[kw];
        u32 al2 = a_lo0[kw + 4], al3 = a_lo1[kw + 4];
#pragma unroll
        for (int nb = 0; nb < 16; ++nb) {
            uint4 b = bf[(nb * 8 + ks) * 32 + lane];
            mma16816(acc[nb][0], acc[nb][1], acc[nb][2], acc[nb][3],
                     ah0, ah1, ah2, ah3, b.x, b.y);
            mma16816(acc[nb][0], acc[nb][1], acc[nb][2], acc[nb][3],
                     ah0, ah1, ah2, ah3, b.z, b.w);
            mma16816(acc[nb][0], acc[nb][1], acc[nb][2], acc[nb][3],
                     al0, al1, al2, al3, b.x, b.y);
        }
    }

    // -------- epilogue --------
    const bool vg = rowg < NN;
    const bool vh = rowh < NN;

    if (mode == 0) {
        u32* dhg = (u32*)g_ah + (size_t)rowg * 64;
        u32* dlg = (u32*)g_al + (size_t)rowg * 64;
        u32* dhh = (u32*)g_ah + (size_t)rowh * 64;
        u32* dlh = (u32*)g_al + (size_t)rowh * 64;
#pragma unroll
        for (int nb = 0; nb < 16; ++nb) {
            const int c0 = nb * 8 + 2 * t;
            float b0 = __ldg(bias + c0), b1 = __ldg(bias + c0 + 1);
            float f0 = acc[nb][0] + b0, f1 = acc[nb][1] + b1;
            float f2 = acc[nb][2] + b0, f3 = acc[nb][3] + b1;
            f0 = (f0 > 0.f) ? f0 : 0.01f * f0;
            f1 = (f1 > 0.f) ? f1 : 0.01f * f1;
            f2 = (f2 > 0.f) ? f2 : 0.01f * f2;
            f3 = (f3 > 0.f) ? f3 : 0.01f * f3;
            const int ui = nb * 4 + t;
            if (vg) {
                dhg[ui] = bf2(f0, f1);
                dlg[ui] = bf2(bf_res(f0), bf_res(f1));
            }
            if (vh) {
                dhh[ui] = bf2(f2, f3);
                dlh[ui] = bf2(bf_res(f2), bf_res(f3));
            }
        }
    } else {
        float sg = 0.f, dg = 0.f, sh = 0.f, dh = 0.f;
        u32* hg = (u32*)g_h2h + (size_t)rowg * 64;
        u32* hh = (u32*)g_h2h + (size_t)rowh * 64;
#pragma unroll
        for (int nb = 0; nb < 16; ++nb) {
            const int c0 = nb * 8 + 2 * t;
            float s0 = __ldg(attS + c0), s1 = __ldg(attS + c0 + 1);
            float d0 = __ldg(attD + c0), d1 = __ldg(attD + c0 + 1);
            float f0 = acc[nb][0], f1 = acc[nb][1];
            float f2 = acc[nb][2], f3 = acc[nb][3];
            sg += f0 * s0 + f1 * s1;
            dg += f0 * d0 + f1 * d1;
            sh += f2 * s0 + f3 * s1;
            dh += f2 * d0 + f3 * d1;
            const int ui = nb * 4 + t;
            if (vg) hg[ui] = hf2(f0, f1);
            if (vh) hh[ui] = hf2(f2, f3);
        }
        // reduce over the 4 lanes of each group (lane bits 0..1)
#pragma unroll
        for (int o = 1; o <= 2; o <<= 1) {
            sg += __shfl_xor_sync(0xffffffffu, sg, o);
            dg += __shfl_xor_sync(0xffffffffu, dg, o);
            sh += __shfl_xor_sync(0xffffffffu, sh, o);
            dh += __shfl_xor_sync(0xffffffffu, dh, o);
        }
        if (t == 0) {
            if (vg) { g_as[rowg] = sg; g_ad[rowg] = dg; }
            if (vh) { g_as[rowh] = sh; g_ad[rowh] = dh; }
        }
    }
}

// ------- warp-per-node: online softmax aggregate + bias + LN + leaky --------
// outf != null (last layer): write fp32 to outf; else write bf16 hi/lo pair
__global__ __launch_bounds__(256) void k_agg(
    const float* __restrict__ bias, const float* __restrict__ gamma,
    const float* __restrict__ beta, float* __restrict__ outf)
{
    int v = (blockIdx.x * blockDim.x + threadIdx.x) >> 5;
    int lane = threadIdx.x & 31;
    if (v >= NN) return;

    int beg = g_rowptr[v];
    int end = g_rowptr[v + 1];
    float adv = g_ad[v];

    float mx = -1e30f, dn = 0.f;
    for (int j = beg + lane; j < end; j += 32) {
        float e = g_as[g_srcs[j]] + adv;
        e = (e > 0.f) ? e : 0.2f * e;
        float mn = fmaxf(mx, e);
        dn = dn * __expf(mx - mn) + __expf(e - mn);
        mx = mn;
    }
#pragma unroll
    for (int o = 16; o > 0; o >>= 1) {
        float mo = __shfl_xor_sync(0xffffffffu, mx, o);
        float do_ = __shfl_xor_sync(0xffffffffu, dn, o);
        float mn = fmaxf(mx, mo);
        dn = dn * __expf(mx - mn) + do_ * __expf(mo - mn);
        mx = mn;
    }
    float winv = (end > beg) ? 1.f / (dn + 1e-16f) : 0.f;

    float4 acc = make_float4(0.f, 0.f, 0.f, 0.f);
    for (int j = beg; j < end; ++j) {
        int s = g_srcs[j];
        float e = g_as[s] + adv;
        e = (e > 0.f) ? e : 0.2f * e;
        float w = __expf(e - mx) * winv;
        uint2 hv = g_h2h[(size_t)s * 32 + lane];
        __half2 h0 = *reinterpret_cast<__half2*>(&hv.x);
        __half2 h1 = *reinterpret_cast<__half2*>(&hv.y);
        float2 f0 = __half22float2(h0);
        float2 f1 = __half22float2(h1);
        acc.x += w * f0.x; acc.y += w * f0.y;
        acc.z += w * f1.x; acc.w += w * f1.y;
    }

    float4 b4 = ((const float4*)bias)[lane];
    acc.x += b4.x; acc.y += b4.y; acc.z += b4.z; acc.w += b4.w;

    float sum = acc.x + acc.y + acc.z + acc.w;
    float sq  = acc.x * acc.x + acc.y * acc.y + acc.z * acc.z + acc.w * acc.w;
#pragma unroll
    for (int o = 16; o > 0; o >>= 1) {
        sum += __shfl_xor_sync(0xffffffffu, sum, o);
        sq  += __shfl_xor_sync(0xffffffffu, sq, o);
    }
    float mu = sum * (1.f / 128.f);
    float var = sq * (1.f / 128.f) - mu * mu;
    float rstd = rsqrtf(var + 1e-5f);

    float4 g4 = ((const float4*)gamma)[lane];
    float4 be4 = ((const float4*)beta)[lane];
    float4 o4;
    o4.x = (acc.x - mu) * rstd * g4.x + be4.x;
    o4.y = (acc.y - mu) * rstd * g4.y + be4.y;
    o4.z = (acc.z - mu) * rstd * g4.z + be4.z;
    o4.w = (acc.w - mu) * rstd * g4.w + be4.w;
    o4.x = (o4.x > 0.f) ? o4.x : 0.01f * o4.x;
    o4.y = (o4.y > 0.f) ? o4.y : 0.01f * o4.y;
    o4.z = (o4.z > 0.f) ? o4.z : 0.01f * o4.z;
    o4.w = (o4.w > 0.f) ? o4.w : 0.01f * o4.w;

    if (outf) {
        ((float4*)(outf + (size_t)v * 128))[lane] = o4;
    } else {
        uint2 hi, lo;
        hi.x = bf2(o4.x, o4.y); hi.y = bf2(o4.z, o4.w);
        lo.x = bf2(bf_res(o4.x), bf_res(o4.y)); lo.y = bf2(bf_res(o4.z), bf_res(o4.w));
        ((uint2*)g_ah)[(size_t)v * 32 + lane] = hi;
        ((uint2*)g_al)[(size_t)v * 32 + lane] = lo;
    }
}

// ---------------- launcher --------------------------------------------------
extern "C" void kernel_launch(void* const* d_in, const int* in_sizes, int n_in,
                              void* d_out, int out_size) {
    const float* x       = (const float*)d_in[0];
    const int*   ei      = (const int*)  d_in[1];
    const float* W_in    = (const float*)d_in[2];
    const float* b_in    = (const float*)d_in[3];
    const float* Wl      = (const float*)d_in[4];
    const float* att_src = (const float*)d_in[5];
    const float* att_dst = (const float*)d_in[6];
    const float* bias_l  = (const float*)d_in[7];
    const float* gamma   = (const float*)d_in[8];
    const float* beta    = (const float*)d_in[9];
    float* out = (float*)d_out;

    const int gemm_blocks = (NN + 127) / 128;         // 782
    const int node_warp_blocks = (NN + 7) / 8;        // 12500

    __nv_bfloat16 *pxh = nullptr, *pxl = nullptr, *pah = nullptr, *pal = nullptr;
    cudaGetSymbolAddress((void**)&pxh, g_xh);
    cudaGetSymbolAddress((void**)&pxl, g_xl);
    cudaGetSymbolAddress((void**)&pah, g_ah);
    cudaGetSymbolAddress((void**)&pal, g_al);

    // order keeps the profiled launch (#3) on the GEMM
    k_prep_w<<<(5 * 16384 + 255) / 256, 256>>>(W_in, Wl);            // 0
    k_prep_bfrag<<<(20480 + 255) / 256, 256>>>();                    // 1
    k_convert_x<<<(NN * 32 + 255) / 256, 256>>>(x);                  // 2
    mma_gemm<<<gemm_blocks, 256>>>(pxh, pxl, 0, 0, b_in,             // 3 <- profiled
                                   nullptr, nullptr);
    k_zero<<<(NN + 1023) / 1024, 1024>>>();                          // 4
    k_hist<<<(EE + 255) / 256, 256>>>(ei);                           // 5
    k_scan_block<<<NB, SCAN_B>>>();                                  // 6
    k_scan_bsums<<<1, 128>>>();                                      // 7
    k_scan_fix<<<NB, SCAN_B>>>();                                    // 8
    k_scatter<<<(EE + 255) / 256, 256>>>(ei);                        // 9

    for (int i = 0; i < 4; i++) {
        mma_gemm<<<gemm_blocks, 256>>>(pah, pal, i + 1, 1, nullptr,
                                       att_src + i * 128, att_dst + i * 128);
        float* dst = (i == 3) ? out : nullptr;
        k_agg<<<node_warp_blocks, 256>>>(bias_l + i * 128, gamma + i * 128,
                                         beta + i * 128, dst);
    }
}

// round 6
// speedup vs baseline: 1.8814x; 1.2109x over previous
#include <cuda_runtime.h>
#include <cuda_fp16.h>
#include <cuda_bf16.h>
#include <cstdint>

#define NN 100000
#define EE 1600000
#define SCAN_B 1024
#define NB ((NN + SCAN_B - 1) / SCAN_B)   // 98

typedef unsigned long long u64;
typedef unsigned int u32;

// ---------------- scratch (device globals; no allocation allowed) ----------
// A operand, packed per row in mma-fragment order:
// g_ap[row*32 + ks*4 + t] = uint4{ hi[kw], hi[kw+4], lo[kw], lo[kw+4] }, kw=ks*8+t
__device__ uint4 g_ap[NN * 32];
__device__ __nv_bfloat16 g_wh[5 * 128 * 128];  // W^T bf16-hi (slot 0=W_in, 1..4=Wl)
__device__ __nv_bfloat16 g_wl[5 * 128 * 128];  // W^T bf16-lo
__device__ uint4 g_bfrag[5 * 16 * 8 * 32];     // W fragments: {bh0,bh1,bl0,bl1} per lane
__device__ uint2 g_h2h[NN * 32];           // fp16 copy of h2 rows
__device__ float g_as[NN];
__device__ float g_ad[NN];
__device__ int   g_deg[NN];
__device__ int   g_incl[NN];
__device__ int   g_cursor[NN];
__device__ int   g_rowptr[NN + 1];
__device__ int   g_srcs[EE];
__device__ int   g_bsums[128];

// ---------------- small helpers --------------------------------------------
__device__ __forceinline__ u32 bf2(float a, float b) {
    __nv_bfloat162 t = __floats2bfloat162_rn(a, b);
    return *reinterpret_cast<u32*>(&t);
}
__device__ __forceinline__ u32 hf2(float a, float b) {
    __half2 t = __floats2half2_rn(a, b);
    return *reinterpret_cast<u32*>(&t);
}
__device__ __forceinline__ float bf_res(float v) {   // residual after bf16-hi
    return v - __bfloat162float(__float2bfloat16_rn(v));
}

// Shuffle a row (held as u32 pairs: lane l owns u32 indices 2l, 2l+1 of hi and lo)
// into the packed fragment uint4 for this lane's (ks = l>>2, t = l&3) slot.
__device__ __forceinline__ uint4 pack_row_frag(u32 hx, u32 hy, u32 lx, u32 ly, int lane) {
    const int src0 = ((lane >> 2) << 2) + ((lane & 3) >> 1);  // kw>>1
    const int sel = lane & 1;                                  // kw&1
    u32 h0a = __shfl_sync(0xffffffffu, hx, src0);
    u32 h0b = __shfl_sync(0xffffffffu, hy, src0);
    u32 h1a = __shfl_sync(0xffffffffu, hx, src0 + 2);
    u32 h1b = __shfl_sync(0xffffffffu, hy, src0 + 2);
    u32 l0a = __shfl_sync(0xffffffffu, lx, src0);
    u32 l0b = __shfl_sync(0xffffffffu, ly, src0);
    u32 l1a = __shfl_sync(0xffffffffu, lx, src0 + 2);
    u32 l1b = __shfl_sync(0xffffffffu, ly, src0 + 2);
    uint4 r;
    r.x = sel ? h0b : h0a;
    r.y = sel ? h1b : h1a;
    r.z = sel ? l0b : l0a;
    r.w = sel ? l1b : l1a;
    return r;
}

// mma.sync m16n8k16 bf16 x fp32-acc (baseline sm_80+ instruction; no *_a arch)
__device__ __forceinline__ void mma16816(
    float& c0, float& c1, float& c2, float& c3,
    u32 a0, u32 a1, u32 a2, u32 a3, u32 b0, u32 b1)
{
    asm volatile(
        "mma.sync.aligned.m16n8k16.row.col.f32.bf16.bf16.f32 "
        "{%0,%1,%2,%3}, {%4,%5,%6,%7}, {%8,%9}, {%0,%1,%2,%3};"
        : "+f"(c0), "+f"(c1), "+f"(c2), "+f"(c3)
        : "r"(a0), "r"(a1), "r"(a2), "r"(a3), "r"(b0), "r"(b1));
}

// ---------------- CSR construction -----------------------------------------
__global__ void k_zero() {
    int i = blockIdx.x * blockDim.x + threadIdx.x;
    if (i < NN) { g_deg[i] = 0; g_cursor[i] = 0; }
}
__global__ void k_hist(const int* __restrict__ ei) {
    int e = blockIdx.x * blockDim.x + threadIdx.x;
    if (e < EE) atomicAdd(&g_deg[ei[EE + e]], 1);
}
__global__ void k_scan_block() {
    __shared__ int sh[SCAN_B];
    int i = blockIdx.x * SCAN_B + threadIdx.x;
    int v = (i < NN) ? g_deg[i] : 0;
    sh[threadIdx.x] = v;
    __syncthreads();
    for (int off = 1; off < SCAN_B; off <<= 1) {
        int t = 0;
        if (threadIdx.x >= off) t = sh[threadIdx.x - off];
        __syncthreads();
        if (threadIdx.x >= off) sh[threadIdx.x] += t;
        __syncthreads();
    }
    if (i < NN) g_incl[i] = sh[threadIdx.x];
    if (threadIdx.x == SCAN_B - 1) g_bsums[blockIdx.x] = sh[SCAN_B - 1];
}
__global__ void k_scan_bsums() {
    __shared__ int sh[128];
    int t = threadIdx.x;
    sh[t] = (t < NB) ? g_bsums[t] : 0;
    __syncthreads();
    for (int off = 1; off < 128; off <<= 1) {
        int v = 0;
        if (t >= off) v = sh[t - off];
        __syncthreads();
        if (t >= off) sh[t] += v;
        __syncthreads();
    }
    if (t < NB) g_bsums[t] = sh[t];
}
__global__ void k_scan_fix() {
    int i = blockIdx.x * SCAN_B + threadIdx.x;
    if (i < NN) {
        int off = (blockIdx.x > 0) ? g_bsums[blockIdx.x - 1] : 0;
        g_rowptr[i + 1] = g_incl[i] + off;
    }
    if (i == 0) g_rowptr[0] = 0;
}
__global__ void k_scatter(const int* __restrict__ ei) {
    int e = blockIdx.x * blockDim.x + threadIdx.x;
    if (e >= EE) return;
    int s = ei[e];
    int d = ei[EE + e];
    int pos = g_rowptr[d] + atomicAdd(&g_cursor[d], 1);
    g_srcs[pos] = s;
}

// ---------------- weight prep: transpose + bf16 hi/lo split ----------------
__global__ void k_prep_w(const float* __restrict__ W_in, const float* __restrict__ Wl) {
    int idx = blockIdx.x * blockDim.x + threadIdx.x;   // over 5*16384
    if (idx >= 5 * 16384) return;
    int l = idx >> 14;
    int r = idx & 16383;
    int n = r >> 7;
    int k = r & 127;
    float v = (l == 0) ? W_in[k * 128 + n] : Wl[(l - 1) * 16384 + k * 128 + n];
    __nv_bfloat16 hi = __float2bfloat16_rn(v);
    g_wh[l * 16384 + n * 128 + k] = hi;
    g_wl[l * 16384 + n * 128 + k] = __float2bfloat16_rn(v - __bfloat162float(hi));
}

// ---- pack W into per-lane mma fragment layout: uint4 {bh0,bh1,bl0,bl1} ----
__global__ void k_prep_bfrag() {
    int idx = blockIdx.x * blockDim.x + threadIdx.x;   // over 5*16*8*32 = 20480
    if (idx >= 5 * 16 * 8 * 32) return;
    int lane = idx & 31;
    int ks = (idx >> 5) & 7;
    int nb = (idx >> 8) & 15;
    int l = idx >> 12;
    int g = lane >> 2;
    int t = lane & 3;
    int n = nb * 8 + g;
    int kw = ks * 8 + t;
    const u32* wh = (const u32*)(g_wh + (size_t)l * 16384);
    const u32* wl = (const u32*)(g_wl + (size_t)l * 16384);
    uint4 f;
    f.x = wh[n * 64 + kw];
    f.y = wh[n * 64 + kw + 4];
    f.z = wl[n * 64 + kw];
    f.w = wl[n * 64 + kw + 4];
    g_bfrag[idx] = f;
}

// ---------------- x -> packed bf16 hi/lo fragments (warp per row) ----------
__global__ __launch_bounds__(256) void k_convert_x(const float* __restrict__ x) {
    int row = (blockIdx.x * blockDim.x + threadIdx.x) >> 5;
    int lane = threadIdx.x & 31;
    if (row >= NN) return;
    float4 v = ((const float4*)x)[(size_t)row * 32 + lane];
    u32 hx = bf2(v.x, v.y), hy = bf2(v.z, v.w);
    u32 lx = bf2(bf_res(v.x), bf_res(v.y)), ly = bf2(bf_res(v.z), bf_res(v.w));
    g_ap[(size_t)row * 32 + lane] = pack_row_frag(hx, hy, lx, ly, lane);
}

// ---------------- HMMA GEMM: tile M=128, N=128, K=128, split bf16 ----------
// 8 warps; each warp computes 16 rows x 128 cols with mma.sync.m16n8k16.
// A comes pre-packed in fragment order (2 LDG.128 per ks per warp);
// B fragments staged in shared memory (LDS.128, 29-cyc latency).
// mode 0: out = leaky(acc + bias, 0.01) -> packed fragments into g_ap
// mode 1: att dots -> g_as/g_ad; fp16 row copy -> g_h2h
__global__ __launch_bounds__(256) void mma_gemm(
    int wslot, int mode,
    const float* __restrict__ bias,
    const float* __restrict__ attS, const float* __restrict__ attD)
{
    extern __shared__ uint4 sB[];   // 4096 uint4 = 64 KB
    const int tid  = threadIdx.x;
    const int warp = tid >> 5;
    const int lane = tid & 31;
    const int g = lane >> 2;       // group 0..7
    const int t = lane & 3;        // tid-in-group

    // cooperative load of this layer's B fragments into smem
    {
        const uint4* bf = g_bfrag + (size_t)wslot * 4096;
#pragma unroll
        for (int i = 0; i < 16; ++i)
            sB[i * 256 + tid] = bf[i * 256 + tid];
    }
    __syncthreads();

    const int rowg = blockIdx.x * 128 + warp * 16 + g;   // rows for c0/c1
    const int rowh = rowg + 8;                           // rows for c2/c3
    const int r0 = (rowg < NN) ? rowg : (NN - 1);        // clamped load rows
    const int r1 = (rowh < NN) ? rowh : (NN - 1);

    const uint4* __restrict__ ap0 = g_ap + (size_t)r0 * 32;
    const uint4* __restrict__ ap1 = g_ap + (size_t)r1 * 32;

    float acc[16][4];
#pragma unroll
    for (int nb = 0; nb < 16; ++nb)
#pragma unroll
        for (int j = 0; j < 4; ++j) acc[nb][j] = 0.f;

#pragma unroll
    for (int ks = 0; ks < 8; ++ks) {
        uint4 Ag = ap0[ks * 4 + t];   // {hi[kw], hi[kw+4], lo[kw], lo[kw+4]} row rg
        uint4 Ahh = ap1[ks * 4 + t];  // same for row rh
#pragma unroll
        for (int nb = 0; nb < 16; ++nb) {
            uint4 b = sB[(nb * 8 + ks) * 32 + lane];
            mma16816(acc[nb][0], acc[nb][1], acc[nb][2], acc[nb][3],
                     Ag.x, Ahh.x, Ag.y, Ahh.y, b.x, b.y);     // hi x Bh
            mma16816(acc[nb][0], acc[nb][1], acc[nb][2], acc[nb][3],
                     Ag.x, Ahh.x, Ag.y, Ahh.y, b.z, b.w);     // hi x Bl
            mma16816(acc[nb][0], acc[nb][1], acc[nb][2], acc[nb][3],
                     Ag.z, Ahh.z, Ag.w, Ahh.w, b.x, b.y);     // lo x Bh
        }
    }

    // -------- epilogue --------
    const bool vg = rowg < NN;
    const bool vh = rowh < NN;

    if (mode == 0) {
        // write next-layer A directly in packed fragment order (no shuffles:
        // lane (g,t) owns exactly the u32 col-pairs j = nb*4+t, and the packed
        // slot (ks', t) needs j = 2ks'*4+t and (2ks'+1)*4+t).
        uint4* apg = g_ap + (size_t)rowg * 32;
        uint4* aph = g_ap + (size_t)rowh * 32;
#pragma unroll
        for (int k = 0; k < 8; ++k) {
            const int nb0 = 2 * k, nb1 = 2 * k + 1;
            const int c0 = nb0 * 8 + 2 * t, c1 = nb1 * 8 + 2 * t;
            float b00 = __ldg(bias + c0), b01 = __ldg(bias + c0 + 1);
            float b10 = __ldg(bias + c1), b11 = __ldg(bias + c1 + 1);
            float f0 = acc[nb0][0] + b00, f1 = acc[nb0][1] + b01;
            float f2 = acc[nb0][2] + b00, f3 = acc[nb0][3] + b01;
            float f4 = acc[nb1][0] + b10, f5 = acc[nb1][1] + b11;
            float f6 = acc[nb1][2] + b10, f7 = acc[nb1][3] + b11;
            f0 = (f0 > 0.f) ? f0 : 0.01f * f0;
            f1 = (f1 > 0.f) ? f1 : 0.01f * f1;
            f2 = (f2 > 0.f) ? f2 : 0.01f * f2;
            f3 = (f3 > 0.f) ? f3 : 0.01f * f3;
            f4 = (f4 > 0.f) ? f4 : 0.01f * f4;
            f5 = (f5 > 0.f) ? f5 : 0.01f * f5;
            f6 = (f6 > 0.f) ? f6 : 0.01f * f6;
            f7 = (f7 > 0.f) ? f7 : 0.01f * f7;
            if (vg) {
                uint4 o;
                o.x = bf2(f0, f1);
                o.y = bf2(f4, f5);
                o.z = bf2(bf_res(f0), bf_res(f1));
                o.w = bf2(bf_res(f4), bf_res(f5));
                apg[k * 4 + t] = o;
            }
            if (vh) {
                uint4 o;
                o.x = bf2(f2, f3);
                o.y = bf2(f6, f7);
                o.z = bf2(bf_res(f2), bf_res(f3));
                o.w = bf2(bf_res(f6), bf_res(f7));
                aph[k * 4 + t] = o;
            }
        }
    } else {
        float sg = 0.f, dg = 0.f, sh = 0.f, dh = 0.f;
        u32* hg = (u32*)g_h2h + (size_t)rowg * 64;
        u32* hh = (u32*)g_h2h + (size_t)rowh * 64;
#pragma unroll
        for (int nb = 0; nb < 16; ++nb) {
            const int c0 = nb * 8 + 2 * t;
            float s0 = __ldg(attS + c0), s1 = __ldg(attS + c0 + 1);
            float d0 = __ldg(attD + c0), d1 = __ldg(attD + c0 + 1);
            float f0 = acc[nb][0], f1 = acc[nb][1];
            float f2 = acc[nb][2], f3 = acc[nb][3];
            sg += f0 * s0 + f1 * s1;
            dg += f0 * d0 + f1 * d1;
            sh += f2 * s0 + f3 * s1;
            dh += f2 * d0 + f3 * d1;
            const int ui = nb * 4 + t;
            if (vg) hg[ui] = hf2(f0, f1);
            if (vh) hh[ui] = hf2(f2, f3);
        }
#pragma unroll
        for (int o = 1; o <= 2; o <<= 1) {
            sg += __shfl_xor_sync(0xffffffffu, sg, o);
            dg += __shfl_xor_sync(0xffffffffu, dg, o);
            sh += __shfl_xor_sync(0xffffffffu, sh, o);
            dh += __shfl_xor_sync(0xffffffffu, dh, o);
        }
        if (t == 0) {
            if (vg) { g_as[rowg] = sg; g_ad[rowg] = dg; }
            if (vh) { g_as[rowh] = sh; g_ad[rowh] = dh; }
        }
    }
}

// ------- warp-per-node: online softmax aggregate + bias + LN + leaky --------
// outf != null (last layer): write fp32 to outf; else write packed fragments
__global__ __launch_bounds__(256) void k_agg(
    const float* __restrict__ bias, const float* __restrict__ gamma,
    const float* __restrict__ beta, float* __restrict__ outf)
{
    int v = (blockIdx.x * blockDim.x + threadIdx.x) >> 5;
    int lane = threadIdx.x & 31;
    if (v >= NN) return;

    int beg = g_rowptr[v];
    int end = g_rowptr[v + 1];
    float adv = g_ad[v];

    float mx = -1e30f, dn = 0.f;
    for (int j = beg + lane; j < end; j += 32) {
        float e = g_as[g_srcs[j]] + adv;
        e = (e > 0.f) ? e : 0.2f * e;
        float mn = fmaxf(mx, e);
        dn = dn * __expf(mx - mn) + __expf(e - mn);
        mx = mn;
    }
#pragma unroll
    for (int o = 16; o > 0; o >>= 1) {
        float mo = __shfl_xor_sync(0xffffffffu, mx, o);
        float do_ = __shfl_xor_sync(0xffffffffu, dn, o);
        float mn = fmaxf(mx, mo);
        dn = dn * __expf(mx - mn) + do_ * __expf(mo - mn);
        mx = mn;
    }
    float winv = (end > beg) ? 1.f / (dn + 1e-16f) : 0.f;

    float4 acc = make_float4(0.f, 0.f, 0.f, 0.f);
    for (int j = beg; j < end; ++j) {
        int s = g_srcs[j];
        float e = g_as[s] + adv;
        e = (e > 0.f) ? e : 0.2f * e;
        float w = __expf(e - mx) * winv;
        uint2 hv = g_h2h[(size_t)s * 32 + lane];
        __half2 h0 = *reinterpret_cast<__half2*>(&hv.x);
        __half2 h1 = *reinterpret_cast<__half2*>(&hv.y);
        float2 f0 = __half22float2(h0);
        float2 f1 = __half22float2(h1);
        acc.x += w * f0.x; acc.y += w * f0.y;
        acc.z += w * f1.x; acc.w += w * f1.y;
    }

    float4 b4 = ((const float4*)bias)[lane];
    acc.x += b4.x; acc.y += b4.y; acc.z += b4.z; acc.w += b4.w;

    float sum = acc.x + acc.y + acc.z + acc.w;
    float sq  = acc.x * acc.x + acc.y * acc.y + acc.z * acc.z + acc.w * acc.w;
#pragma unroll
    for (int o = 16; o > 0; o >>= 1) {
        sum += __shfl_xor_sync(0xffffffffu, sum, o);
        sq  += __shfl_xor_sync(0xffffffffu, sq, o);
    }
    float mu = sum * (1.f / 128.f);
    float var = sq * (1.f / 128.f) - mu * mu;
    float rstd = rsqrtf(var + 1e-5f);

    float4 g4 = ((const float4*)gamma)[lane];
    float4 be4 = ((const float4*)beta)[lane];
    float4 o4;
    o4.x = (acc.x - mu) * rstd * g4.x + be4.x;
    o4.y = (acc.y - mu) * rstd * g4.y + be4.y;
    o4.z = (acc.z - mu) * rstd * g4.z + be4.z;
    o4.w = (acc.w - mu) * rstd * g4.w + be4.w;
    o4.x = (o4.x > 0.f) ? o4.x : 0.01f * o4.x;
    o4.y = (o4.y > 0.f) ? o4.y : 0.01f * o4.y;
    o4.z = (o4.z > 0.f) ? o4.z : 0.01f * o4.z;
    o4.w = (o4.w > 0.f) ? o4.w : 0.01f * o4.w;

    if (outf) {
        ((float4*)(outf + (size_t)v * 128))[lane] = o4;
    } else {
        u32 hx = bf2(o4.x, o4.y), hy = bf2(o4.z, o4.w);
        u32 lx = bf2(bf_res(o4.x), bf_res(o4.y)), ly = bf2(bf_res(o4.z), bf_res(o4.w));
        g_ap[(size_t)v * 32 + lane] = pack_row_frag(hx, hy, lx, ly, lane);
    }
}

// ---------------- launcher --------------------------------------------------
extern "C" void kernel_launch(void* const* d_in, const int* in_sizes, int n_in,
                              void* d_out, int out_size) {
    const float* x       = (const float*)d_in[0];
    const int*   ei      = (const int*)  d_in[1];
    const float* W_in    = (const float*)d_in[2];
    const float* b_in    = (const float*)d_in[3];
    const float* Wl      = (const float*)d_in[4];
    const float* att_src = (const float*)d_in[5];
    const float* att_dst = (const float*)d_in[6];
    const float* bias_l  = (const float*)d_in[7];
    const float* gamma   = (const float*)d_in[8];
    const float* beta    = (const float*)d_in[9];
    float* out = (float*)d_out;

    const int SMEM_B = 65536;
    static int smem_set = 0;
    if (!smem_set) {
        cudaFuncSetAttribute(mma_gemm, cudaFuncAttributeMaxDynamicSharedMemorySize, SMEM_B);
        smem_set = 1;
    }

    const int gemm_blocks = (NN + 127) / 128;         // 782
    const int node_warp_blocks = (NN + 7) / 8;        // 12500

    // order keeps the profiled launch (#3) on the GEMM
    k_prep_w<<<(5 * 16384 + 255) / 256, 256>>>(W_in, Wl);            // 0
    k_prep_bfrag<<<(20480 + 255) / 256, 256>>>();                    // 1
    k_convert_x<<<node_warp_blocks, 256>>>(x);                       // 2
    mma_gemm<<<gemm_blocks, 256, SMEM_B>>>(0, 0, b_in,               // 3 <- profiled
                                           nullptr, nullptr);
    k_zero<<<(NN + 1023) / 1024, 1024>>>();                          // 4
    k_hist<<<(EE + 255) / 256, 256>>>(ei);                           // 5
    k_scan_block<<<NB, SCAN_B>>>();                                  // 6
    k_scan_bsums<<<1, 128>>>();                                      // 7
    k_scan_fix<<<NB, SCAN_B>>>();                                    // 8
    k_scatter<<<(EE + 255) / 256, 256>>>(ei);                        // 9

    for (int i = 0; i < 4; i++) {
        mma_gemm<<<gemm_blocks, 256, SMEM_B>>>(i + 1, 1, nullptr,
                                               att_src + i * 128, att_dst + i * 128);
        float* dst = (i == 3) ? out : nullptr;
        k_agg<<<node_warp_blocks, 256>>>(bias_l + i * 128, gamma + i * 128,
                                         beta + i * 128, dst);
    }
}

// round 7
// speedup vs baseline: 1.8862x; 1.0025x over previous
#include <cuda_runtime.h>
#include <cuda_fp16.h>
#include <cuda_bf16.h>
#include <cstdint>

#define NN 100000
#define EE 1600000
#define SCAN_B 1024
#define NB ((NN + SCAN_B - 1) / SCAN_B)   // 98

typedef unsigned long long u64;
typedef unsigned int u32;

// ---------------- scratch (device globals; no allocation allowed) ----------
// A operand, packed per row in mma-fragment order:
// g_ap[row*32 + ks*4 + t] = uint4{ hi[kw], hi[kw+4], lo[kw], lo[kw+4] }, kw=ks*8+t
__device__ uint4 g_ap[NN * 32];
__device__ uint4 g_bfrag[5 * 16 * 8 * 32];     // W fragments: {bh0,bh1,bl0,bl1} per lane
__device__ uint2 g_h2h[NN * 32];           // fp16 copy of h2 rows
__device__ float g_as[NN];
__device__ float g_ad[NN];
__device__ int   g_deg[NN];
__device__ int   g_incl[NN];
__device__ int   g_cursor[NN];
__device__ int   g_rowptr[NN + 1];
__device__ int   g_srcs[EE];
__device__ int   g_bsums[128];

// ---------------- small helpers --------------------------------------------
__device__ __forceinline__ u32 bf2(float a, float b) {
    __nv_bfloat162 t = __floats2bfloat162_rn(a, b);
    return *reinterpret_cast<u32*>(&t);
}
__device__ __forceinline__ u32 hf2(float a, float b) {
    __half2 t = __floats2half2_rn(a, b);
    return *reinterpret_cast<u32*>(&t);
}
__device__ __forceinline__ float bf_res(float v) {   // residual after bf16-hi
    return v - __bfloat162float(__float2bfloat16_rn(v));
}

// Shuffle a row (lane l owns u32 indices 2l, 2l+1 of hi and lo) into the
// packed fragment uint4 for this lane's (ks = l>>2, t = l&3) slot.
__device__ __forceinline__ uint4 pack_row_frag(u32 hx, u32 hy, u32 lx, u32 ly, int lane) {
    const int src0 = ((lane >> 2) << 2) + ((lane & 3) >> 1);  // kw>>1
    const int sel = lane & 1;                                  // kw&1
    u32 h0a = __shfl_sync(0xffffffffu, hx, src0);
    u32 h0b = __shfl_sync(0xffffffffu, hy, src0);
    u32 h1a = __shfl_sync(0xffffffffu, hx, src0 + 2);
    u32 h1b = __shfl_sync(0xffffffffu, hy, src0 + 2);
    u32 l0a = __shfl_sync(0xffffffffu, lx, src0);
    u32 l0b = __shfl_sync(0xffffffffu, ly, src0);
    u32 l1a = __shfl_sync(0xffffffffu, lx, src0 + 2);
    u32 l1b = __shfl_sync(0xffffffffu, ly, src0 + 2);
    uint4 r;
    r.x = sel ? h0b : h0a;
    r.y = sel ? h1b : h1a;
    r.z = sel ? l0b : l0a;
    r.w = sel ? l1b : l1a;
    return r;
}

// mma.sync m16n8k16 bf16 x fp32-acc (baseline sm_80+ instruction; no *_a arch)
__device__ __forceinline__ void mma16816(
    float& c0, float& c1, float& c2, float& c3,
    u32 a0, u32 a1, u32 a2, u32 a3, u32 b0, u32 b1)
{
    asm volatile(
        "mma.sync.aligned.m16n8k16.row.col.f32.bf16.bf16.f32 "
        "{%0,%1,%2,%3}, {%4,%5,%6,%7}, {%8,%9}, {%0,%1,%2,%3};"
        : "+f"(c0), "+f"(c1), "+f"(c2), "+f"(c3)
        : "r"(a0), "r"(a1), "r"(a2), "r"(a3), "r"(b0), "r"(b1));
}

// ---------------- CSR construction -----------------------------------------
__global__ void k_zero() {
    int i = blockIdx.x * blockDim.x + threadIdx.x;
    if (i < NN) { g_deg[i] = 0; g_cursor[i] = 0; }
}
__global__ void k_hist(const int* __restrict__ ei) {
    int e = blockIdx.x * blockDim.x + threadIdx.x;
    if (e < EE) atomicAdd(&g_deg[ei[EE + e]], 1);
}
__global__ void k_scan_block() {
    __shared__ int sh[SCAN_B];
    int i = blockIdx.x * SCAN_B + threadIdx.x;
    int v = (i < NN) ? g_deg[i] : 0;
    sh[threadIdx.x] = v;
    __syncthreads();
    for (int off = 1; off < SCAN_B; off <<= 1) {
        int t = 0;
        if (threadIdx.x >= off) t = sh[threadIdx.x - off];
        __syncthreads();
        if (threadIdx.x >= off) sh[threadIdx.x] += t;
        __syncthreads();
    }
    if (i < NN) g_incl[i] = sh[threadIdx.x];
    if (threadIdx.x == SCAN_B - 1) g_bsums[blockIdx.x] = sh[SCAN_B - 1];
}
__global__ void k_scan_bsums() {
    __shared__ int sh[128];
    int t = threadIdx.x;
    sh[t] = (t < NB) ? g_bsums[t] : 0;
    __syncthreads();
    for (int off = 1; off < 128; off <<= 1) {
        int v = 0;
        if (t >= off) v = sh[t - off];
        __syncthreads();
        if (t >= off) sh[t] += v;
        __syncthreads();
    }
    if (t < NB) g_bsums[t] = sh[t];
}
__global__ void k_scan_fix() {
    int i = blockIdx.x * SCAN_B + threadIdx.x;
    if (i < NN) {
        int off = (blockIdx.x > 0) ? g_bsums[blockIdx.x - 1] : 0;
        g_rowptr[i + 1] = g_incl[i] + off;
    }
    if (i == 0) g_rowptr[0] = 0;
}
__global__ void k_scatter(const int* __restrict__ ei) {
    int e = blockIdx.x * blockDim.x + threadIdx.x;
    if (e >= EE) return;
    int s = ei[e];
    int d = ei[EE + e];
    int pos = g_rowptr[d] + atomicAdd(&g_cursor[d], 1);
    g_srcs[pos] = s;
}

// ---- W -> per-lane mma fragment layout, straight from inputs --------------
// g_bfrag[l][nb*8+ks][lane] = {bh(kw), bh(kw+4), bl(kw), bl(kw+4)}, kw=ks*8+t,
// where bh(j) packs bf16-hi of (W[2j][n], W[2j+1][n]), n = nb*8 + (lane>>2).
__global__ void k_prep_bfrag(const float* __restrict__ W_in, const float* __restrict__ Wl) {
    int idx = blockIdx.x * blockDim.x + threadIdx.x;   // over 5*16*8*32 = 20480
    if (idx >= 5 * 16 * 8 * 32) return;
    int lane = idx & 31;
    int ks = (idx >> 5) & 7;
    int nb = (idx >> 8) & 15;
    int l = idx >> 12;
    int g = lane >> 2;
    int t = lane & 3;
    int n = nb * 8 + g;
    int kw = ks * 8 + t;
    const float* W = (l == 0) ? W_in : (Wl + (size_t)(l - 1) * 16384);
    float v00 = W[(2 * kw) * 128 + n];
    float v01 = W[(2 * kw + 1) * 128 + n];
    float v10 = W[(2 * kw + 8) * 128 + n];
    float v11 = W[(2 * kw + 9) * 128 + n];
    uint4 f;
    f.x = bf2(v00, v01);
    f.y = bf2(v10, v11);
    f.z = bf2(bf_res(v00), bf_res(v01));
    f.w = bf2(bf_res(v10), bf_res(v11));
    g_bfrag[idx] = f;
}

// ---------------- x -> packed bf16 hi/lo fragments (warp per row) ----------
__global__ __launch_bounds__(256) void k_convert_x(const float* __restrict__ x) {
    int row = (blockIdx.x * blockDim.x + threadIdx.x) >> 5;
    int lane = threadIdx.x & 31;
    if (row >= NN) return;
    float4 v = ((const float4*)x)[(size_t)row * 32 + lane];
    u32 hx = bf2(v.x, v.y), hy = bf2(v.z, v.w);
    u32 lx = bf2(bf_res(v.x), bf_res(v.y)), ly = bf2(bf_res(v.z), bf_res(v.w));
    g_ap[(size_t)row * 32 + lane] = pack_row_frag(hx, hy, lx, ly, lane);
}

// ---------------- HMMA GEMM: tile M=128, N=128, K=128, split bf16 ----------
__global__ __launch_bounds__(256) void mma_gemm(
    int wslot, int mode,
    const float* __restrict__ bias,
    const float* __restrict__ attS, const float* __restrict__ attD)
{
    extern __shared__ uint4 sB[];   // 4096 uint4 = 64 KB
    const int tid  = threadIdx.x;
    const int warp = tid >> 5;
    const int lane = tid & 31;
    const int g = lane >> 2;
    const int t = lane & 3;

    {
        const uint4* bf = g_bfrag + (size_t)wslot * 4096;
#pragma unroll
        for (int i = 0; i < 16; ++i)
            sB[i * 256 + tid] = bf[i * 256 + tid];
    }
    __syncthreads();

    const int rowg = blockIdx.x * 128 + warp * 16 + g;
    const int rowh = rowg + 8;
    const int r0 = (rowg < NN) ? rowg : (NN - 1);
    const int r1 = (rowh < NN) ? rowh : (NN - 1);

    const uint4* __restrict__ ap0 = g_ap + (size_t)r0 * 32;
    const uint4* __restrict__ ap1 = g_ap + (size_t)r1 * 32;

    float acc[16][4];
#pragma unroll
    for (int nb = 0; nb < 16; ++nb)
#pragma unroll
        for (int j = 0; j < 4; ++j) acc[nb][j] = 0.f;

#pragma unroll
    for (int ks = 0; ks < 8; ++ks) {
        uint4 Ag = ap0[ks * 4 + t];
        uint4 Ahh = ap1[ks * 4 + t];
#pragma unroll
        for (int nb = 0; nb < 16; ++nb) {
            uint4 b = sB[(nb * 8 + ks) * 32 + lane];
            mma16816(acc[nb][0], acc[nb][1], acc[nb][2], acc[nb][3],
                     Ag.x, Ahh.x, Ag.y, Ahh.y, b.x, b.y);
            mma16816(acc[nb][0], acc[nb][1], acc[nb][2], acc[nb][3],
                     Ag.x, Ahh.x, Ag.y, Ahh.y, b.z, b.w);
            mma16816(acc[nb][0], acc[nb][1], acc[nb][2], acc[nb][3],
                     Ag.z, Ahh.z, Ag.w, Ahh.w, b.x, b.y);
        }
    }

    const bool vg = rowg < NN;
    const bool vh = rowh < NN;

    if (mode == 0) {
        uint4* apg = g_ap + (size_t)rowg * 32;
        uint4* aph = g_ap + (size_t)rowh * 32;
#pragma unroll
        for (int k = 0; k < 8; ++k) {
            const int nb0 = 2 * k, nb1 = 2 * k + 1;
            const int c0 = nb0 * 8 + 2 * t, c1 = nb1 * 8 + 2 * t;
            float b00 = __ldg(bias + c0), b01 = __ldg(bias + c0 + 1);
            float b10 = __ldg(bias + c1), b11 = __ldg(bias + c1 + 1);
            float f0 = acc[nb0][0] + b00, f1 = acc[nb0][1] + b01;
            float f2 = acc[nb0][2] + b00, f3 = acc[nb0][3] + b01;
            float f4 = acc[nb1][0] + b10, f5 = acc[nb1][1] + b11;
            float f6 = acc[nb1][2] + b10, f7 = acc[nb1][3] + b11;
            f0 = (f0 > 0.f) ? f0 : 0.01f * f0;
            f1 = (f1 > 0.f) ? f1 : 0.01f * f1;
            f2 = (f2 > 0.f) ? f2 : 0.01f * f2;
            f3 = (f3 > 0.f) ? f3 : 0.01f * f3;
            f4 = (f4 > 0.f) ? f4 : 0.01f * f4;
            f5 = (f5 > 0.f) ? f5 : 0.01f * f5;
            f6 = (f6 > 0.f) ? f6 : 0.01f * f6;
            f7 = (f7 > 0.f) ? f7 : 0.01f * f7;
            if (vg) {
                uint4 o;
                o.x = bf2(f0, f1);
                o.y = bf2(f4, f5);
                o.z = bf2(bf_res(f0), bf_res(f1));
                o.w = bf2(bf_res(f4), bf_res(f5));
                apg[k * 4 + t] = o;
            }
            if (vh) {
                uint4 o;
                o.x = bf2(f2, f3);
                o.y = bf2(f6, f7);
                o.z = bf2(bf_res(f2), bf_res(f3));
                o.w = bf2(bf_res(f6), bf_res(f7));
                aph[k * 4 + t] = o;
            }
        }
    } else {
        float sg = 0.f, dg = 0.f, sh = 0.f, dh = 0.f;
        u32* hg = (u32*)g_h2h + (size_t)rowg * 64;
        u32* hh = (u32*)g_h2h + (size_t)rowh * 64;
#pragma unroll
        for (int nb = 0; nb < 16; ++nb) {
            const int c0 = nb * 8 + 2 * t;
            float s0 = __ldg(attS + c0), s1 = __ldg(attS + c0 + 1);
            float d0 = __ldg(attD + c0), d1 = __ldg(attD + c0 + 1);
            float f0 = acc[nb][0], f1 = acc[nb][1];
            float f2 = acc[nb][2], f3 = acc[nb][3];
            sg += f0 * s0 + f1 * s1;
            dg += f0 * d0 + f1 * d1;
            sh += f2 * s0 + f3 * s1;
            dh += f2 * d0 + f3 * d1;
            const int ui = nb * 4 + t;
            if (vg) hg[ui] = hf2(f0, f1);
            if (vh) hh[ui] = hf2(f2, f3);
        }
#pragma unroll
        for (int o = 1; o <= 2; o <<= 1) {
            sg += __shfl_xor_sync(0xffffffffu, sg, o);
            dg += __shfl_xor_sync(0xffffffffu, dg, o);
            sh += __shfl_xor_sync(0xffffffffu, sh, o);
            dh += __shfl_xor_sync(0xffffffffu, dh, o);
        }
        if (t == 0) {
            if (vg) { g_as[rowg] = sg; g_ad[rowg] = dg; }
            if (vh) { g_as[rowh] = sh; g_ad[rowh] = dh; }
        }
    }
}

// ------- warp-per-node softmax aggregate, 2 edges per iteration -------------
// lane = 16*eid + part: lane loads uint4 (16 B) of edge eid's source row;
// 16 lanes cover the 256 B fp16 row; one LDG.128 fetches two rows.
// outf != null (last layer): write fp32; else write packed bf16 fragments.
__global__ __launch_bounds__(256) void k_agg(
    const float* __restrict__ bias, const float* __restrict__ gamma,
    const float* __restrict__ beta, float* __restrict__ outf)
{
    __shared__ u32 s_hi[8][64];
    __shared__ u32 s_lo[8][64];

    const int warp = threadIdx.x >> 5;
    const int v = (blockIdx.x * blockDim.x + threadIdx.x) >> 5;
    const int lane = threadIdx.x & 31;
    if (v >= NN) return;

    const int beg = g_rowptr[v];
    const int end = g_rowptr[v + 1];
    const float adv = g_ad[v];

    // pass 1: online softmax stats (32-lane strided)
    float mx = -1e30f, dn = 0.f;
    for (int j = beg + lane; j < end; j += 32) {
        float e = g_as[g_srcs[j]] + adv;
        e = (e > 0.f) ? e : 0.2f * e;
        float mn = fmaxf(mx, e);
        dn = dn * __expf(mx - mn) + __expf(e - mn);
        mx = mn;
    }
#pragma unroll
    for (int o = 16; o > 0; o >>= 1) {
        float mo = __shfl_xor_sync(0xffffffffu, mx, o);
        float do_ = __shfl_xor_sync(0xffffffffu, dn, o);
        float mn = fmaxf(mx, mo);
        dn = dn * __expf(mx - mn) + do_ * __expf(mo - mn);
        mx = mn;
    }
    const float winv = (end > beg) ? 1.f / (dn + 1e-16f) : 0.f;

    // pass 2: payload accumulate, 2 edges per iteration
    const int part = lane & 15;
    const int eid = lane >> 4;
    float acc[8];
#pragma unroll
    for (int i = 0; i < 8; ++i) acc[i] = 0.f;

    for (int j0 = beg; j0 < end; j0 += 2) {
        const int j = j0 + eid;
        const bool val = j < end;
        const int s = g_srcs[val ? j : beg];
        float e = g_as[s] + adv;
        e = (e > 0.f) ? e : 0.2f * e;
        const float w = val ? __expf(e - mx) * winv : 0.f;
        uint4 hv = ((const uint4*)g_h2h)[(size_t)s * 16 + part];
        float2 f0 = __half22float2(*reinterpret_cast<__half2*>(&hv.x));
        float2 f1 = __half22float2(*reinterpret_cast<__half2*>(&hv.y));
        float2 f2 = __half22float2(*reinterpret_cast<__half2*>(&hv.z));
        float2 f3 = __half22float2(*reinterpret_cast<__half2*>(&hv.w));
        acc[0] += w * f0.x; acc[1] += w * f0.y;
        acc[2] += w * f1.x; acc[3] += w * f1.y;
        acc[4] += w * f2.x; acc[5] += w * f2.y;
        acc[6] += w * f3.x; acc[7] += w * f3.y;
    }
    // merge the two edge groups (lane ^ 16 holds the same columns)
#pragma unroll
    for (int i = 0; i < 8; ++i)
        acc[i] += __shfl_xor_sync(0xffffffffu, acc[i], 16);

    // + bias (cols 8*part .. 8*part+7)
    float4 b40 = ((const float4*)bias)[2 * part];
    float4 b41 = ((const float4*)bias)[2 * part + 1];
    acc[0] += b40.x; acc[1] += b40.y; acc[2] += b40.z; acc[3] += b40.w;
    acc[4] += b41.x; acc[5] += b41.y; acc[6] += b41.z; acc[7] += b41.w;

    // LayerNorm over 128 (reduce across the 16-lane group)
    float sum = 0.f, sq = 0.f;
#pragma unroll
    for (int i = 0; i < 8; ++i) { sum += acc[i]; sq += acc[i] * acc[i]; }
#pragma unroll
    for (int o = 1; o < 16; o <<= 1) {
        sum += __shfl_xor_sync(0xffffffffu, sum, o);
        sq  += __shfl_xor_sync(0xffffffffu, sq, o);
    }
    const float mu = sum * (1.f / 128.f);
    const float var = sq * (1.f / 128.f) - mu * mu;
    const float rstd = rsqrtf(var + 1e-5f);

    float4 g40 = ((const float4*)gamma)[2 * part];
    float4 g41 = ((const float4*)gamma)[2 * part + 1];
    float4 e40 = ((const float4*)beta)[2 * part];
    float4 e41 = ((const float4*)beta)[2 * part + 1];
    float gm[8] = {g40.x, g40.y, g40.z, g40.w, g41.x, g41.y, g41.z, g41.w};
    float bt[8] = {e40.x, e40.y, e40.z, e40.w, e41.x, e41.y, e41.z, e41.w};

    float o8[8];
#pragma unroll
    for (int i = 0; i < 8; ++i) {
        float t = (acc[i] - mu) * rstd * gm[i] + bt[i];
        o8[i] = (t > 0.f) ? t : 0.01f * t;
    }

    if (outf) {
        if (eid == 0) {
            float4* dst = (float4*)(outf + (size_t)v * 128);
            dst[2 * part]     = make_float4(o8[0], o8[1], o8[2], o8[3]);
            dst[2 * part + 1] = make_float4(o8[4], o8[5], o8[6], o8[7]);
        }
    } else {
        // stage hi/lo u32s in smem, read back in fragment order
        if (eid == 0) {
#pragma unroll
            for (int q = 0; q < 4; ++q) {
                float a = o8[2 * q], b = o8[2 * q + 1];
                s_hi[warp][4 * part + q] = bf2(a, b);
                s_lo[warp][4 * part + q] = bf2(bf_res(a), bf_res(b));
            }
        }
        __syncwarp();
        const int ks = lane >> 2;
        const int t = lane & 3;
        const int kw = ks * 8 + t;
        uint4 o;
        o.x = s_hi[warp][kw];
        o.y = s_hi[warp][kw + 4];
        o.z = s_lo[warp][kw];
        o.w = s_lo[warp][kw + 4];
        g_ap[(size_t)v * 32 + lane] = o;
    }
}

// ---------------- launcher --------------------------------------------------
extern "C" void kernel_launch(void* const* d_in, const int* in_sizes, int n_in,
                              void* d_out, int out_size) {
    const float* x       = (const float*)d_in[0];
    const int*   ei      = (const int*)  d_in[1];
    const float* W_in    = (const float*)d_in[2];
    const float* b_in    = (const float*)d_in[3];
    const float* Wl      = (const float*)d_in[4];
    const float* att_src = (const float*)d_in[5];
    const float* att_dst = (const float*)d_in[6];
    const float* bias_l  = (const float*)d_in[7];
    const float* gamma   = (const float*)d_in[8];
    const float* beta    = (const float*)d_in[9];
    float* out = (float*)d_out;

    const int SMEM_B = 65536;
    static int smem_set = 0;
    if (!smem_set) {
        cudaFuncSetAttribute(mma_gemm, cudaFuncAttributeMaxDynamicSharedMemorySize, SMEM_B);
        smem_set = 1;
    }

    const int gemm_blocks = (NN + 127) / 128;         // 782
    const int node_warp_blocks = (NN + 7) / 8;        // 12500

    // order keeps the profiled launch (#3) on the GEMM
    k_prep_bfrag<<<(20480 + 255) / 256, 256>>>(W_in, Wl);            // 0
    k_convert_x<<<node_warp_blocks, 256>>>(x);                       // 1
    k_zero<<<(NN + 1023) / 1024, 1024>>>();                          // 2
    mma_gemm<<<gemm_blocks, 256, SMEM_B>>>(0, 0, b_in,               // 3 <- profiled
                                           nullptr, nullptr);
    k_hist<<<(EE + 255) / 256, 256>>>(ei);                           // 4
    k_scan_block<<<NB, SCAN_B>>>();                                  // 5
    k_scan_bsums<<<1, 128>>>();                                      // 6
    k_scan_fix<<<NB, SCAN_B>>>();                                    // 7
    k_scatter<<<(EE + 255) / 256, 256>>>(ei);                        // 8

    for (int i = 0; i < 4; i++) {
        mma_gemm<<<gemm_blocks, 256, SMEM_B>>>(i + 1, 1, nullptr,
                                               att_src + i * 128, att_dst + i * 128);
        float* dst = (i == 3) ? out : nullptr;
        k_agg<<<node_warp_blocks, 256>>>(bias_l + i * 128, gamma + i * 128,
                                         beta + i * 128, dst);
    }
}

// round 8
// speedup vs baseline: 2.0114x; 1.0664x over previous
#include <cuda_runtime.h>
#include <cuda_fp16.h>
#include <cuda_bf16.h>
#include <cstdint>

#define NN 100000
#define EE 1600000
#define SCAN_B 1024
#define NB ((NN + SCAN_B - 1) / SCAN_B)   // 98

typedef unsigned long long u64;
typedef unsigned int u32;

// ---------------- scratch (device globals; no allocation allowed) ----------
// A operand, packed per row in mma-fragment order:
// g_ap[row*32 + ks*4 + t] = uint4{ hi[kw], hi[kw+4], lo[kw], lo[kw+4] }, kw=ks*8+t
__device__ uint4 g_ap[NN * 32];
__device__ uint4 g_bfrag[5 * 16 * 8 * 32];     // W fragments: {bh0,bh1,bl0,bl1} per lane
__device__ uint2 g_h2h[NN * 32];           // fp16 copy of h2 rows
__device__ float g_as[NN];
__device__ float g_ad[NN];
__device__ float g_ew[EE];                 // per-edge softmax numerator exp(leaky(e))
__device__ int   g_deg[NN];
__device__ int   g_incl[NN];
__device__ int   g_cursor[NN];
__device__ int   g_rowptr[NN + 1];
__device__ int   g_srcs[EE];
__device__ int   g_bsums[128];

// ---------------- small helpers --------------------------------------------
__device__ __forceinline__ u32 bf2(float a, float b) {
    __nv_bfloat162 t = __floats2bfloat162_rn(a, b);
    return *reinterpret_cast<u32*>(&t);
}
__device__ __forceinline__ u32 hf2(float a, float b) {
    __half2 t = __floats2half2_rn(a, b);
    return *reinterpret_cast<u32*>(&t);
}
__device__ __forceinline__ float bf_res(float v) {   // residual after bf16-hi
    return v - __bfloat162float(__float2bfloat16_rn(v));
}

// Shuffle a row (lane l owns u32 indices 2l, 2l+1 of hi and lo) into the
// packed fragment uint4 for this lane's (ks = l>>2, t = l&3) slot.
__device__ __forceinline__ uint4 pack_row_frag(u32 hx, u32 hy, u32 lx, u32 ly, int lane) {
    const int src0 = ((lane >> 2) << 2) + ((lane & 3) >> 1);  // kw>>1
    const int sel = lane & 1;                                  // kw&1
    u32 h0a = __shfl_sync(0xffffffffu, hx, src0);
    u32 h0b = __shfl_sync(0xffffffffu, hy, src0);
    u32 h1a = __shfl_sync(0xffffffffu, hx, src0 + 2);
    u32 h1b = __shfl_sync(0xffffffffu, hy, src0 + 2);
    u32 l0a = __shfl_sync(0xffffffffu, lx, src0);
    u32 l0b = __shfl_sync(0xffffffffu, ly, src0);
    u32 l1a = __shfl_sync(0xffffffffu, lx, src0 + 2);
    u32 l1b = __shfl_sync(0xffffffffu, ly, src0 + 2);
    uint4 r;
    r.x = sel ? h0b : h0a;
    r.y = sel ? h1b : h1a;
    r.z = sel ? l0b : l0a;
    r.w = sel ? l1b : l1a;
    return r;
}

// mma.sync m16n8k16 bf16 x fp32-acc (baseline sm_80+ instruction; no *_a arch)
__device__ __forceinline__ void mma16816(
    float& c0, float& c1, float& c2, float& c3,
    u32 a0, u32 a1, u32 a2, u32 a3, u32 b0, u32 b1)
{
    asm volatile(
        "mma.sync.aligned.m16n8k16.row.col.f32.bf16.bf16.f32 "
        "{%0,%1,%2,%3}, {%4,%5,%6,%7}, {%8,%9}, {%0,%1,%2,%3};"
        : "+f"(c0), "+f"(c1), "+f"(c2), "+f"(c3)
        : "r"(a0), "r"(a1), "r"(a2), "r"(a3), "r"(b0), "r"(b1));
}

// ---------------- CSR construction -----------------------------------------
__global__ void k_zero() {
    int i = blockIdx.x * blockDim.x + threadIdx.x;
    if (i < NN) { g_deg[i] = 0; g_cursor[i] = 0; }
}
__global__ void k_hist(const int* __restrict__ ei) {
    int e = blockIdx.x * blockDim.x + threadIdx.x;
    if (e < EE) atomicAdd(&g_deg[ei[EE + e]], 1);
}
__global__ void k_scan_block() {
    __shared__ int sh[SCAN_B];
    int i = blockIdx.x * SCAN_B + threadIdx.x;
    int v = (i < NN) ? g_deg[i] : 0;
    sh[threadIdx.x] = v;
    __syncthreads();
    for (int off = 1; off < SCAN_B; off <<= 1) {
        int t = 0;
        if (threadIdx.x >= off) t = sh[threadIdx.x - off];
        __syncthreads();
        if (threadIdx.x >= off) sh[threadIdx.x] += t;
        __syncthreads();
    }
    if (i < NN) g_incl[i] = sh[threadIdx.x];
    if (threadIdx.x == SCAN_B - 1) g_bsums[blockIdx.x] = sh[SCAN_B - 1];
}
__global__ void k_scan_bsums() {
    __shared__ int sh[128];
    int t = threadIdx.x;
    sh[t] = (t < NB) ? g_bsums[t] : 0;
    __syncthreads();
    for (int off = 1; off < 128; off <<= 1) {
        int v = 0;
        if (t >= off) v = sh[t - off];
        __syncthreads();
        if (t >= off) sh[t] += v;
        __syncthreads();
    }
    if (t < NB) g_bsums[t] = sh[t];
}
__global__ void k_scan_fix() {
    int i = blockIdx.x * SCAN_B + threadIdx.x;
    if (i < NN) {
        int off = (blockIdx.x > 0) ? g_bsums[blockIdx.x - 1] : 0;
        g_rowptr[i + 1] = g_incl[i] + off;
    }
    if (i == 0) g_rowptr[0] = 0;
}
__global__ void k_scatter(const int* __restrict__ ei) {
    int e = blockIdx.x * blockDim.x + threadIdx.x;
    if (e >= EE) return;
    int s = ei[e];
    int d = ei[EE + e];
    int pos = g_rowptr[d] + atomicAdd(&g_cursor[d], 1);
    g_srcs[pos] = s;
}

// ---- W -> per-lane mma fragment layout, straight from inputs --------------
__global__ void k_prep_bfrag(const float* __restrict__ W_in, const float* __restrict__ Wl) {
    int idx = blockIdx.x * blockDim.x + threadIdx.x;   // over 5*16*8*32 = 20480
    if (idx >= 5 * 16 * 8 * 32) return;
    int lane = idx & 31;
    int ks = (idx >> 5) & 7;
    int nb = (idx >> 8) & 15;
    int l = idx >> 12;
    int g = lane >> 2;
    int t = lane & 3;
    int n = nb * 8 + g;
    int kw = ks * 8 + t;
    const float* W = (l == 0) ? W_in : (Wl + (size_t)(l - 1) * 16384);
    float v00 = W[(2 * kw) * 128 + n];
    float v01 = W[(2 * kw + 1) * 128 + n];
    float v10 = W[(2 * kw + 8) * 128 + n];
    float v11 = W[(2 * kw + 9) * 128 + n];
    uint4 f;
    f.x = bf2(v00, v01);
    f.y = bf2(v10, v11);
    f.z = bf2(bf_res(v00), bf_res(v01));
    f.w = bf2(bf_res(v10), bf_res(v11));
    g_bfrag[idx] = f;
}

// ---------------- x -> packed bf16 hi/lo fragments (warp per row) ----------
__global__ __launch_bounds__(256) void k_convert_x(const float* __restrict__ x) {
    int row = (blockIdx.x * blockDim.x + threadIdx.x) >> 5;
    int lane = threadIdx.x & 31;
    if (row >= NN) return;
    float4 v = ((const float4*)x)[(size_t)row * 32 + lane];
    u32 hx = bf2(v.x, v.y), hy = bf2(v.z, v.w);
    u32 lx = bf2(bf_res(v.x), bf_res(v.y)), ly = bf2(bf_res(v.z), bf_res(v.w));
    g_ap[(size_t)row * 32 + lane] = pack_row_frag(hx, hy, lx, ly, lane);
}

// ---------------- HMMA GEMM: tile M=128, N=128, K=128, split bf16 ----------
__global__ __launch_bounds__(256) void mma_gemm(
    int wslot, int mode,
    const float* __restrict__ bias,
    const float* __restrict__ attS, const float* __restrict__ attD)
{
    extern __shared__ uint4 sB[];   // 4096 uint4 = 64 KB
    const int tid  = threadIdx.x;
    const int warp = tid >> 5;
    const int lane = tid & 31;
    const int g = lane >> 2;
    const int t = lane & 3;

    {
        const uint4* bf = g_bfrag + (size_t)wslot * 4096;
#pragma unroll
        for (int i = 0; i < 16; ++i)
            sB[i * 256 + tid] = bf[i * 256 + tid];
    }
    __syncthreads();

    const int rowg = blockIdx.x * 128 + warp * 16 + g;
    const int rowh = rowg + 8;
    const int r0 = (rowg < NN) ? rowg : (NN - 1);
    const int r1 = (rowh < NN) ? rowh : (NN - 1);

    const uint4* __restrict__ ap0 = g_ap + (size_t)r0 * 32;
    const uint4* __restrict__ ap1 = g_ap + (size_t)r1 * 32;

    float acc[16][4];
#pragma unroll
    for (int nb = 0; nb < 16; ++nb)
#pragma unroll
        for (int j = 0; j < 4; ++j) acc[nb][j] = 0.f;

#pragma unroll
    for (int ks = 0; ks < 8; ++ks) {
        uint4 Ag = ap0[ks * 4 + t];
        uint4 Ahh = ap1[ks * 4 + t];
#pragma unroll
        for (int nb = 0; nb < 16; ++nb) {
            uint4 b = sB[(nb * 8 + ks) * 32 + lane];
            mma16816(acc[nb][0], acc[nb][1], acc[nb][2], acc[nb][3],
                     Ag.x, Ahh.x, Ag.y, Ahh.y, b.x, b.y);
            mma16816(acc[nb][0], acc[nb][1], acc[nb][2], acc[nb][3],
                     Ag.x, Ahh.x, Ag.y, Ahh.y, b.z, b.w);
            mma16816(acc[nb][0], acc[nb][1], acc[nb][2], acc[nb][3],
                     Ag.z, Ahh.z, Ag.w, Ahh.w, b.x, b.y);
        }
    }

    const bool vg = rowg < NN;
    const bool vh = rowh < NN;

    if (mode == 0) {
        uint4* apg = g_ap + (size_t)rowg * 32;
        uint4* aph = g_ap + (size_t)rowh * 32;
#pragma unroll
        for (int k = 0; k < 8; ++k) {
            const int nb0 = 2 * k, nb1 = 2 * k + 1;
            const int c0 = nb0 * 8 + 2 * t, c1 = nb1 * 8 + 2 * t;
            float b00 = __ldg(bias + c0), b01 = __ldg(bias + c0 + 1);
            float b10 = __ldg(bias + c1), b11 = __ldg(bias + c1 + 1);
            float f0 = acc[nb0][0] + b00, f1 = acc[nb0][1] + b01;
            float f2 = acc[nb0][2] + b00, f3 = acc[nb0][3] + b01;
            float f4 = acc[nb1][0] + b10, f5 = acc[nb1][1] + b11;
            float f6 = acc[nb1][2] + b10, f7 = acc[nb1][3] + b11;
            f0 = (f0 > 0.f) ? f0 : 0.01f * f0;
            f1 = (f1 > 0.f) ? f1 : 0.01f * f1;
            f2 = (f2 > 0.f) ? f2 : 0.01f * f2;
            f3 = (f3 > 0.f) ? f3 : 0.01f * f3;
            f4 = (f4 > 0.f) ? f4 : 0.01f * f4;
            f5 = (f5 > 0.f) ? f5 : 0.01f * f5;
            f6 = (f6 > 0.f) ? f6 : 0.01f * f6;
            f7 = (f7 > 0.f) ? f7 : 0.01f * f7;
            if (vg) {
                uint4 o;
                o.x = bf2(f0, f1);
                o.y = bf2(f4, f5);
                o.z = bf2(bf_res(f0), bf_res(f1));
                o.w = bf2(bf_res(f4), bf_res(f5));
                apg[k * 4 + t] = o;
            }
            if (vh) {
                uint4 o;
                o.x = bf2(f2, f3);
                o.y = bf2(f6, f7);
                o.z = bf2(bf_res(f2), bf_res(f3));
                o.w = bf2(bf_res(f6), bf_res(f7));
                aph[k * 4 + t] = o;
            }
        }
    } else {
        float sg = 0.f, dg = 0.f, sh = 0.f, dh = 0.f;
        u32* hg = (u32*)g_h2h + (size_t)rowg * 64;
        u32* hh = (u32*)g_h2h + (size_t)rowh * 64;
#pragma unroll
        for (int nb = 0; nb < 16; ++nb) {
            const int c0 = nb * 8 + 2 * t;
            float s0 = __ldg(attS + c0), s1 = __ldg(attS + c0 + 1);
            float d0 = __ldg(attD + c0), d1 = __ldg(attD + c0 + 1);
            float f0 = acc[nb][0], f1 = acc[nb][1];
            float f2 = acc[nb][2], f3 = acc[nb][3];
            sg += f0 * s0 + f1 * s1;
            dg += f0 * d0 + f1 * d1;
            sh += f2 * s0 + f3 * s1;
            dh += f2 * d0 + f3 * d1;
            const int ui = nb * 4 + t;
            if (vg) hg[ui] = hf2(f0, f1);
            if (vh) hh[ui] = hf2(f2, f3);
        }
#pragma unroll
        for (int o = 1; o <= 2; o <<= 1) {
            sg += __shfl_xor_sync(0xffffffffu, sg, o);
            dg += __shfl_xor_sync(0xffffffffu, dg, o);
            sh += __shfl_xor_sync(0xffffffffu, sh, o);
            dh += __shfl_xor_sync(0xffffffffu, dh, o);
        }
        if (t == 0) {
            if (vg) { g_as[rowg] = sg; g_ad[rowg] = dg; }
            if (vh) { g_as[rowh] = sh; g_ad[rowh] = dh; }
        }
    }
}

// ------- warp-per-node softmax aggregate -------------------------------------
// Pass A: per-edge numerators w = exp(leaky(as[src]+ad[v])) -> g_ew (no max
// subtraction; logits are bounded so exp is safe; softmax shift-invariant).
// Pass B: 4 edges per warp iteration (2 per 16-lane group, 2-deep unroll);
// weights read sequentially from g_ew, rows gathered as uint4 per lane.
// outf != null (last layer): write fp32; else write packed bf16 fragments.
__global__ __launch_bounds__(256) void k_agg(
    const float* __restrict__ bias, const float* __restrict__ gamma,
    const float* __restrict__ beta, float* __restrict__ outf)
{
    __shared__ u32 s_hi[8][64];
    __shared__ u32 s_lo[8][64];

    const int warp = threadIdx.x >> 5;
    const int v = (blockIdx.x * blockDim.x + threadIdx.x) >> 5;
    const int lane = threadIdx.x & 31;
    if (v >= NN) return;

    const int beg = g_rowptr[v];
    const int end = g_rowptr[v + 1];
    const float adv = g_ad[v];

    // pass A: numerators + denominator
    float dn = 0.f;
    for (int j = beg + lane; j < end; j += 32) {
        float e = g_as[g_srcs[j]] + adv;
        e = (e > 0.f) ? e : 0.2f * e;
        float w = __expf(e);
        g_ew[j] = w;
        dn += w;
    }
#pragma unroll
    for (int o = 16; o > 0; o >>= 1)
        dn += __shfl_xor_sync(0xffffffffu, dn, o);
    const float winv = (end > beg) ? 1.f / (dn + 1e-16f) : 0.f;

    // pass B: payload accumulate, 4 edges per warp iteration
    const int part = lane & 15;
    const int eid = lane >> 4;
    float acc[8];
#pragma unroll
    for (int i = 0; i < 8; ++i) acc[i] = 0.f;

    for (int j0 = beg; j0 < end; j0 += 4) {
        const int ja = j0 + eid;
        const int jb = j0 + 2 + eid;
        const bool va = ja < end;
        const bool vb = jb < end;
        const int sa = g_srcs[va ? ja : beg];
        const int sb = g_srcs[vb ? jb : beg];
        const float wa = va ? g_ew[ja] * winv : 0.f;
        const float wb = vb ? g_ew[jb] * winv : 0.f;
        uint4 hva = ((const uint4*)g_h2h)[(size_t)sa * 16 + part];
        uint4 hvb = ((const uint4*)g_h2h)[(size_t)sb * 16 + part];
        float2 a0 = __half22float2(*reinterpret_cast<__half2*>(&hva.x));
        float2 a1 = __half22float2(*reinterpret_cast<__half2*>(&hva.y));
        float2 a2 = __half22float2(*reinterpret_cast<__half2*>(&hva.z));
        float2 a3 = __half22float2(*reinterpret_cast<__half2*>(&hva.w));
        float2 b0 = __half22float2(*reinterpret_cast<__half2*>(&hvb.x));
        float2 b1 = __half22float2(*reinterpret_cast<__half2*>(&hvb.y));
        float2 b2 = __half22float2(*reinterpret_cast<__half2*>(&hvb.z));
        float2 b3 = __half22float2(*reinterpret_cast<__half2*>(&hvb.w));
        acc[0] += wa * a0.x + wb * b0.x;
        acc[1] += wa * a0.y + wb * b0.y;
        acc[2] += wa * a1.x + wb * b1.x;
        acc[3] += wa * a1.y + wb * b1.y;
        acc[4] += wa * a2.x + wb * b2.x;
        acc[5] += wa * a2.y + wb * b2.y;
        acc[6] += wa * a3.x + wb * b3.x;
        acc[7] += wa * a3.y + wb * b3.y;
    }
    // merge the two edge groups (lane ^ 16 holds the same columns)
#pragma unroll
    for (int i = 0; i < 8; ++i)
        acc[i] += __shfl_xor_sync(0xffffffffu, acc[i], 16);

    // + bias (cols 8*part .. 8*part+7)
    float4 b40 = ((const float4*)bias)[2 * part];
    float4 b41 = ((const float4*)bias)[2 * part + 1];
    acc[0] += b40.x; acc[1] += b40.y; acc[2] += b40.z; acc[3] += b40.w;
    acc[4] += b41.x; acc[5] += b41.y; acc[6] += b41.z; acc[7] += b41.w;

    // LayerNorm over 128 (reduce across the 16-lane group)
    float sum = 0.f, sq = 0.f;
#pragma unroll
    for (int i = 0; i < 8; ++i) { sum += acc[i]; sq += acc[i] * acc[i]; }
#pragma unroll
    for (int o = 1; o < 16; o <<= 1) {
        sum += __shfl_xor_sync(0xffffffffu, sum, o);
        sq  += __shfl_xor_sync(0xffffffffu, sq, o);
    }
    const float mu = sum * (1.f / 128.f);
    const float var = sq * (1.f / 128.f) - mu * mu;
    const float rstd = rsqrtf(var + 1e-5f);

    float4 g40 = ((const float4*)gamma)[2 * part];
    float4 g41 = ((const float4*)gamma)[2 * part + 1];
    float4 e40 = ((const float4*)beta)[2 * part];
    float4 e41 = ((const float4*)beta)[2 * part + 1];
    float gm[8] = {g40.x, g40.y, g40.z, g40.w, g41.x, g41.y, g41.z, g41.w};
    float bt[8] = {e40.x, e40.y, e40.z, e40.w, e41.x, e41.y, e41.z, e41.w};

    float o8[8];
#pragma unroll
    for (int i = 0; i < 8; ++i) {
        float t = (acc[i] - mu) * rstd * gm[i] + bt[i];
        o8[i] = (t > 0.f) ? t : 0.01f * t;
    }

    if (outf) {
        if (eid == 0) {
            float4* dst = (float4*)(outf + (size_t)v * 128);
            dst[2 * part]     = make_float4(o8[0], o8[1], o8[2], o8[3]);
            dst[2 * part + 1] = make_float4(o8[4], o8[5], o8[6], o8[7]);
        }
    } else {
        // stage hi/lo u32s in smem, read back in fragment order
        if (eid == 0) {
#pragma unroll
            for (int q = 0; q < 4; ++q) {
                float a = o8[2 * q], b = o8[2 * q + 1];
                s_hi[warp][4 * part + q] = bf2(a, b);
                s_lo[warp][4 * part + q] = bf2(bf_res(a), bf_res(b));
            }
        }
        __syncwarp();
        const int ks = lane >> 2;
        const int t = lane & 3;
        const int kw = ks * 8 + t;
        uint4 o;
        o.x = s_hi[warp][kw];
        o.y = s_hi[warp][kw + 4];
        o.z = s_lo[warp][kw];
        o.w = s_lo[warp][kw + 4];
        g_ap[(size_t)v * 32 + lane] = o;
    }
}

// ---------------- launcher --------------------------------------------------
extern "C" void kernel_launch(void* const* d_in, const int* in_sizes, int n_in,
                              void* d_out, int out_size) {
    const float* x       = (const float*)d_in[0];
    const int*   ei      = (const int*)  d_in[1];
    const float* W_in    = (const float*)d_in[2];
    const float* b_in    = (const float*)d_in[3];
    const float* Wl      = (const float*)d_in[4];
    const float* att_src = (const float*)d_in[5];
    const float* att_dst = (const float*)d_in[6];
    const float* bias_l  = (const float*)d_in[7];
    const float* gamma   = (const float*)d_in[8];
    const float* beta    = (const float*)d_in[9];
    float* out = (float*)d_out;

    const int SMEM_B = 65536;
    static int smem_set = 0;
    if (!smem_set) {
        cudaFuncSetAttribute(mma_gemm, cudaFuncAttributeMaxDynamicSharedMemorySize, SMEM_B);
        smem_set = 1;
    }

    const int gemm_blocks = (NN + 127) / 128;         // 782
    const int node_warp_blocks = (NN + 7) / 8;        // 12500

    // order keeps the profiled launch (#3) on the GEMM
    k_prep_bfrag<<<(20480 + 255) / 256, 256>>>(W_in, Wl);            // 0
    k_convert_x<<<node_warp_blocks, 256>>>(x);                       // 1
    k_zero<<<(NN + 1023) / 1024, 1024>>>();                          // 2
    mma_gemm<<<gemm_blocks, 256, SMEM_B>>>(0, 0, b_in,               // 3 <- profiled
                                           nullptr, nullptr);
    k_hist<<<(EE + 255) / 256, 256>>>(ei);                           // 4
    k_scan_block<<<NB, SCAN_B>>>();                                  // 5
    k_scan_bsums<<<1, 128>>>();                                      // 6
    k_scan_fix<<<NB, SCAN_B>>>();                                    // 7
    k_scatter<<<(EE + 255) / 256, 256>>>(ei);                        // 8

    for (int i = 0; i < 4; i++) {
        mma_gemm<<<gemm_blocks, 256, SMEM_B>>>(i + 1, 1, nullptr,
                                               att_src + i * 128, att_dst + i * 128);
        float* dst = (i == 3) ? out : nullptr;
        k_agg<<<node_warp_blocks, 256>>>(bias_l + i * 128, gamma + i * 128,
                                         beta + i * 128, dst);
    }
}

// round 9
// speedup vs baseline: 2.0344x; 1.0114x over previous
#include <cuda_runtime.h>
#include <cuda_fp16.h>
#include <cuda_bf16.h>
#include <cstdint>

#define NN 100000
#define EE 1600000
#define SCAN_B 1024
#define NB ((NN + SCAN_B - 1) / SCAN_B)   // 98

typedef unsigned long long u64;
typedef unsigned int u32;

// ---------------- scratch (device globals; no allocation allowed) ----------
// A operand, packed per row in mma-fragment order:
// g_ap[row*32 + ks*4 + t] = uint4{ hi[kw], hi[kw+4], lo[kw], lo[kw+4] }, kw=ks*8+t
__device__ uint4 g_ap[NN * 32];
__device__ uint4 g_bfrag[5 * 16 * 8 * 32];     // W fragments: {bh0,bh1,bl0,bl1} per lane
__device__ uint2 g_h2h[NN * 32];           // fp16 copy of h2 rows
__device__ float g_as[NN];
__device__ float g_ad[NN];
__device__ uint2 g_ews[EE];                // {exp-weight bits, src} per CSR slot
__device__ int   g_deg[NN];
__device__ int   g_incl[NN];
__device__ int   g_cursor[NN];
__device__ int   g_rowptr[NN + 1];
__device__ int   g_srcs[EE];
__device__ int   g_bsums[128];

// ---------------- small helpers --------------------------------------------
__device__ __forceinline__ u32 bf2(float a, float b) {
    __nv_bfloat162 t = __floats2bfloat162_rn(a, b);
    return *reinterpret_cast<u32*>(&t);
}
__device__ __forceinline__ u32 hf2(float a, float b) {
    __half2 t = __floats2half2_rn(a, b);
    return *reinterpret_cast<u32*>(&t);
}
__device__ __forceinline__ float bf_res(float v) {   // residual after bf16-hi
    return v - __bfloat162float(__float2bfloat16_rn(v));
}

// Shuffle a row (lane l owns u32 indices 2l, 2l+1 of hi and lo) into the
// packed fragment uint4 for this lane's (ks = l>>2, t = l&3) slot.
__device__ __forceinline__ uint4 pack_row_frag(u32 hx, u32 hy, u32 lx, u32 ly, int lane) {
    const int src0 = ((lane >> 2) << 2) + ((lane & 3) >> 1);  // kw>>1
    const int sel = lane & 1;                                  // kw&1
    u32 h0a = __shfl_sync(0xffffffffu, hx, src0);
    u32 h0b = __shfl_sync(0xffffffffu, hy, src0);
    u32 h1a = __shfl_sync(0xffffffffu, hx, src0 + 2);
    u32 h1b = __shfl_sync(0xffffffffu, hy, src0 + 2);
    u32 l0a = __shfl_sync(0xffffffffu, lx, src0);
    u32 l0b = __shfl_sync(0xffffffffu, ly, src0);
    u32 l1a = __shfl_sync(0xffffffffu, lx, src0 + 2);
    u32 l1b = __shfl_sync(0xffffffffu, ly, src0 + 2);
    uint4 r;
    r.x = sel ? h0b : h0a;
    r.y = sel ? h1b : h1a;
    r.z = sel ? l0b : l0a;
    r.w = sel ? l1b : l1a;
    return r;
}

// mma.sync m16n8k16 bf16 x fp32-acc (baseline sm_80+ instruction; no *_a arch)
__device__ __forceinline__ void mma16816(
    float& c0, float& c1, float& c2, float& c3,
    u32 a0, u32 a1, u32 a2, u32 a3, u32 b0, u32 b1)
{
    asm volatile(
        "mma.sync.aligned.m16n8k16.row.col.f32.bf16.bf16.f32 "
        "{%0,%1,%2,%3}, {%4,%5,%6,%7}, {%8,%9}, {%0,%1,%2,%3};"
        : "+f"(c0), "+f"(c1), "+f"(c2), "+f"(c3)
        : "r"(a0), "r"(a1), "r"(a2), "r"(a3), "r"(b0), "r"(b1));
}

// ---------------- fused setup: W fragments + x conversion + zeroing --------
// block ranges: [0,80) prep_bfrag; [80, 80+12500) convert_x; rest zero.
__global__ __launch_bounds__(256) void k_setup(
    const float* __restrict__ x,
    const float* __restrict__ W_in, const float* __restrict__ Wl)
{
    const int bid = blockIdx.x;
    const int tid = threadIdx.x;
    if (bid < 80) {
        int idx = bid * 256 + tid;                 // over 20480
        int lane = idx & 31;
        int ks = (idx >> 5) & 7;
        int nb = (idx >> 8) & 15;
        int l = idx >> 12;
        int g = lane >> 2;
        int t = lane & 3;
        int n = nb * 8 + g;
        int kw = ks * 8 + t;
        const float* W = (l == 0) ? W_in : (Wl + (size_t)(l - 1) * 16384);
        float v00 = W[(2 * kw) * 128 + n];
        float v01 = W[(2 * kw + 1) * 128 + n];
        float v10 = W[(2 * kw + 8) * 128 + n];
        float v11 = W[(2 * kw + 9) * 128 + n];
        uint4 f;
        f.x = bf2(v00, v01);
        f.y = bf2(v10, v11);
        f.z = bf2(bf_res(v00), bf_res(v01));
        f.w = bf2(bf_res(v10), bf_res(v11));
        g_bfrag[idx] = f;
    } else if (bid < 80 + 12500) {
        int row = ((bid - 80) << 3) + (tid >> 5);  // 8 rows per block
        int lane = tid & 31;
        if (row < NN) {
            float4 v = ((const float4*)x)[(size_t)row * 32 + lane];
            u32 hx = bf2(v.x, v.y), hy = bf2(v.z, v.w);
            u32 lx = bf2(bf_res(v.x), bf_res(v.y)), ly = bf2(bf_res(v.z), bf_res(v.w));
            g_ap[(size_t)row * 32 + lane] = pack_row_frag(hx, hy, lx, ly, lane);
        }
    } else {
        int i = (bid - 80 - 12500) * 256 + tid;
        if (i < NN) { g_deg[i] = 0; g_cursor[i] = 0; }
    }
}

// ---------------- CSR construction -----------------------------------------
__global__ void k_hist(const int* __restrict__ ei) {
    int e = blockIdx.x * blockDim.x + threadIdx.x;
    if (e < EE) atomicAdd(&g_deg[ei[EE + e]], 1);
}
__global__ void k_scan_block() {
    __shared__ int sh[SCAN_B];
    int i = blockIdx.x * SCAN_B + threadIdx.x;
    int v = (i < NN) ? g_deg[i] : 0;
    sh[threadIdx.x] = v;
    __syncthreads();
    for (int off = 1; off < SCAN_B; off <<= 1) {
        int t = 0;
        if (threadIdx.x >= off) t = sh[threadIdx.x - off];
        __syncthreads();
        if (threadIdx.x >= off) sh[threadIdx.x] += t;
        __syncthreads();
    }
    if (i < NN) g_incl[i] = sh[threadIdx.x];
    if (threadIdx.x == SCAN_B - 1) g_bsums[blockIdx.x] = sh[SCAN_B - 1];
}
__global__ void k_scan_bsums() {
    __shared__ int sh[128];
    int t = threadIdx.x;
    sh[t] = (t < NB) ? g_bsums[t] : 0;
    __syncthreads();
    for (int off = 1; off < 128; off <<= 1) {
        int v = 0;
        if (t >= off) v = sh[t - off];
        __syncthreads();
        if (t >= off) sh[t] += v;
        __syncthreads();
    }
    if (t < NB) g_bsums[t] = sh[t];
}
__global__ void k_scan_fix() {
    int i = blockIdx.x * SCAN_B + threadIdx.x;
    if (i < NN) {
        int off = (blockIdx.x > 0) ? g_bsums[blockIdx.x - 1] : 0;
        g_rowptr[i + 1] = g_incl[i] + off;
    }
    if (i == 0) g_rowptr[0] = 0;
}
__global__ void k_scatter(const int* __restrict__ ei) {
    int e = blockIdx.x * blockDim.x + threadIdx.x;
    if (e >= EE) return;
    int s = ei[e];
    int d = ei[EE + e];
    int pos = g_rowptr[d] + atomicAdd(&g_cursor[d], 1);
    g_srcs[pos] = s;
}

// ---------------- HMMA GEMM: tile M=128, N=128, K=128, split bf16 ----------
__global__ __launch_bounds__(256) void mma_gemm(
    int wslot, int mode,
    const float* __restrict__ bias,
    const float* __restrict__ attS, const float* __restrict__ attD)
{
    extern __shared__ uint4 sB[];   // 4096 uint4 = 64 KB
    const int tid  = threadIdx.x;
    const int warp = tid >> 5;
    const int lane = tid & 31;
    const int g = lane >> 2;
    const int t = lane & 3;

    {
        const uint4* bf = g_bfrag + (size_t)wslot * 4096;
#pragma unroll
        for (int i = 0; i < 16; ++i)
            sB[i * 256 + tid] = bf[i * 256 + tid];
    }
    __syncthreads();

    const int rowg = blockIdx.x * 128 + warp * 16 + g;
    const int rowh = rowg + 8;
    const int r0 = (rowg < NN) ? rowg : (NN - 1);
    const int r1 = (rowh < NN) ? rowh : (NN - 1);

    const uint4* __restrict__ ap0 = g_ap + (size_t)r0 * 32;
    const uint4* __restrict__ ap1 = g_ap + (size_t)r1 * 32;

    float acc[16][4];
#pragma unroll
    for (int nb = 0; nb < 16; ++nb)
#pragma unroll
        for (int j = 0; j < 4; ++j) acc[nb][j] = 0.f;

#pragma unroll
    for (int ks = 0; ks < 8; ++ks) {
        uint4 Ag = ap0[ks * 4 + t];
        uint4 Ahh = ap1[ks * 4 + t];
#pragma unroll
        for (int nb = 0; nb < 16; ++nb) {
            uint4 b = sB[(nb * 8 + ks) * 32 + lane];
            mma16816(acc[nb][0], acc[nb][1], acc[nb][2], acc[nb][3],
                     Ag.x, Ahh.x, Ag.y, Ahh.y, b.x, b.y);
            mma16816(acc[nb][0], acc[nb][1], acc[nb][2], acc[nb][3],
                     Ag.x, Ahh.x, Ag.y, Ahh.y, b.z, b.w);
            mma16816(acc[nb][0], acc[nb][1], acc[nb][2], acc[nb][3],
                     Ag.z, Ahh.z, Ag.w, Ahh.w, b.x, b.y);
        }
    }

    const bool vg = rowg < NN;
    const bool vh = rowh < NN;

    if (mode == 0) {
        uint4* apg = g_ap + (size_t)rowg * 32;
        uint4* aph = g_ap + (size_t)rowh * 32;
#pragma unroll
        for (int k = 0; k < 8; ++k) {
            const int nb0 = 2 * k, nb1 = 2 * k + 1;
            const int c0 = nb0 * 8 + 2 * t, c1 = nb1 * 8 + 2 * t;
            float b00 = __ldg(bias + c0), b01 = __ldg(bias + c0 + 1);
            float b10 = __ldg(bias + c1), b11 = __ldg(bias + c1 + 1);
            float f0 = acc[nb0][0] + b00, f1 = acc[nb0][1] + b01;
            float f2 = acc[nb0][2] + b00, f3 = acc[nb0][3] + b01;
            float f4 = acc[nb1][0] + b10, f5 = acc[nb1][1] + b11;
            float f6 = acc[nb1][2] + b10, f7 = acc[nb1][3] + b11;
            f0 = (f0 > 0.f) ? f0 : 0.01f * f0;
            f1 = (f1 > 0.f) ? f1 : 0.01f * f1;
            f2 = (f2 > 0.f) ? f2 : 0.01f * f2;
            f3 = (f3 > 0.f) ? f3 : 0.01f * f3;
            f4 = (f4 > 0.f) ? f4 : 0.01f * f4;
            f5 = (f5 > 0.f) ? f5 : 0.01f * f5;
            f6 = (f6 > 0.f) ? f6 : 0.01f * f6;
            f7 = (f7 > 0.f) ? f7 : 0.01f * f7;
            if (vg) {
                uint4 o;
                o.x = bf2(f0, f1);
                o.y = bf2(f4, f5);
                o.z = bf2(bf_res(f0), bf_res(f1));
                o.w = bf2(bf_res(f4), bf_res(f5));
                apg[k * 4 + t] = o;
            }
            if (vh) {
                uint4 o;
                o.x = bf2(f2, f3);
                o.y = bf2(f6, f7);
                o.z = bf2(bf_res(f2), bf_res(f3));
                o.w = bf2(bf_res(f6), bf_res(f7));
                aph[k * 4 + t] = o;
            }
        }
    } else {
        float sg = 0.f, dg = 0.f, sh = 0.f, dh = 0.f;
        u32* hg = (u32*)g_h2h + (size_t)rowg * 64;
        u32* hh = (u32*)g_h2h + (size_t)rowh * 64;
#pragma unroll
        for (int nb = 0; nb < 16; ++nb) {
            const int c0 = nb * 8 + 2 * t;
            float s0 = __ldg(attS + c0), s1 = __ldg(attS + c0 + 1);
            float d0 = __ldg(attD + c0), d1 = __ldg(attD + c0 + 1);
            float f0 = acc[nb][0], f1 = acc[nb][1];
            float f2 = acc[nb][2], f3 = acc[nb][3];
            sg += f0 * s0 + f1 * s1;
            dg += f0 * d0 + f1 * d1;
            sh += f2 * s0 + f3 * s1;
            dh += f2 * d0 + f3 * d1;
            const int ui = nb * 4 + t;
            if (vg) hg[ui] = hf2(f0, f1);
            if (vh) hh[ui] = hf2(f2, f3);
        }
#pragma unroll
        for (int o = 1; o <= 2; o <<= 1) {
            sg += __shfl_xor_sync(0xffffffffu, sg, o);
            dg += __shfl_xor_sync(0xffffffffu, dg, o);
            sh += __shfl_xor_sync(0xffffffffu, sh, o);
            dh += __shfl_xor_sync(0xffffffffu, dh, o);
        }
        if (t == 0) {
            if (vg) { g_as[rowg] = sg; g_ad[rowg] = dg; }
            if (vh) { g_as[rowh] = sh; g_ad[rowh] = dh; }
        }
    }
}

// ------- warp-per-node softmax aggregate -------------------------------------
// Pass A: per-edge {w=exp(leaky(as[src]+ad[v])), src} -> g_ews (fused stream).
// Pass B: 8 edges per warp iteration (4 per 16-lane group), 4 independent
// uint4 row gathers in flight per lane.
// outf != null (last layer): write fp32; else write packed bf16 fragments.
__global__ __launch_bounds__(256) void k_agg(
    const float* __restrict__ bias, const float* __restrict__ gamma,
    const float* __restrict__ beta, float* __restrict__ outf)
{
    __shared__ u32 s_hi[8][64];
    __shared__ u32 s_lo[8][64];

    const int warp = threadIdx.x >> 5;
    const int v = (blockIdx.x * blockDim.x + threadIdx.x) >> 5;
    const int lane = threadIdx.x & 31;
    if (v >= NN) return;

    const int beg = g_rowptr[v];
    const int end = g_rowptr[v + 1];
    const float adv = g_ad[v];

    // pass A: fused weight+src stream, denominator
    float dn = 0.f;
    for (int j = beg + lane; j < end; j += 32) {
        int s = g_srcs[j];
        float e = g_as[s] + adv;
        e = (e > 0.f) ? e : 0.2f * e;
        float w = __expf(e);
        uint2 p;
        p.x = __float_as_uint(w);
        p.y = (u32)s;
        g_ews[j] = p;
        dn += w;
    }
#pragma unroll
    for (int o = 16; o > 0; o >>= 1)
        dn += __shfl_xor_sync(0xffffffffu, dn, o);
    const float winv = (end > beg) ? 1.f / (dn + 1e-16f) : 0.f;

    // pass B: payload accumulate, 8 edges per warp iteration
    const int part = lane & 15;
    const int eid = lane >> 4;
    float acc[8];
#pragma unroll
    for (int i = 0; i < 8; ++i) acc[i] = 0.f;

    for (int j0 = beg; j0 < end; j0 += 8) {
        float w[4];
        uint4 hv[4];
#pragma unroll
        for (int q = 0; q < 4; ++q) {
            const int j = j0 + 2 * q + eid;
            const bool val = j < end;
            uint2 ws = g_ews[val ? j : beg];
            w[q] = val ? __uint_as_float(ws.x) * winv : 0.f;
            hv[q] = ((const uint4*)g_h2h)[(size_t)(int)ws.y * 16 + part];
        }
#pragma unroll
        for (int q = 0; q < 4; ++q) {
            float2 f0 = __half22float2(*reinterpret_cast<__half2*>(&hv[q].x));
            float2 f1 = __half22float2(*reinterpret_cast<__half2*>(&hv[q].y));
            float2 f2 = __half22float2(*reinterpret_cast<__half2*>(&hv[q].z));
            float2 f3 = __half22float2(*reinterpret_cast<__half2*>(&hv[q].w));
            acc[0] += w[q] * f0.x; acc[1] += w[q] * f0.y;
            acc[2] += w[q] * f1.x; acc[3] += w[q] * f1.y;
            acc[4] += w[q] * f2.x; acc[5] += w[q] * f2.y;
            acc[6] += w[q] * f3.x; acc[7] += w[q] * f3.y;
        }
    }
    // merge the two edge groups (lane ^ 16 holds the same columns)
#pragma unroll
    for (int i = 0; i < 8; ++i)
        acc[i] += __shfl_xor_sync(0xffffffffu, acc[i], 16);

    // + bias (cols 8*part .. 8*part+7)
    float4 b40 = ((const float4*)bias)[2 * part];
    float4 b41 = ((const float4*)bias)[2 * part + 1];
    acc[0] += b40.x; acc[1] += b40.y; acc[2] += b40.z; acc[3] += b40.w;
    acc[4] += b41.x; acc[5] += b41.y; acc[6] += b41.z; acc[7] += b41.w;

    // LayerNorm over 128 (reduce across the 16-lane group)
    float sum = 0.f, sq = 0.f;
#pragma unroll
    for (int i = 0; i < 8; ++i) { sum += acc[i]; sq += acc[i] * acc[i]; }
#pragma unroll
    for (int o = 1; o < 16; o <<= 1) {
        sum += __shfl_xor_sync(0xffffffffu, sum, o);
        sq  += __shfl_xor_sync(0xffffffffu, sq, o);
    }
    const float mu = sum * (1.f / 128.f);
    const float var = sq * (1.f / 128.f) - mu * mu;
    const float rstd = rsqrtf(var + 1e-5f);

    float4 g40 = ((const float4*)gamma)[2 * part];
    float4 g41 = ((const float4*)gamma)[2 * part + 1];
    float4 e40 = ((const float4*)beta)[2 * part];
    float4 e41 = ((const float4*)beta)[2 * part + 1];
    float gm[8] = {g40.x, g40.y, g40.z, g40.w, g41.x, g41.y, g41.z, g41.w};
    float bt[8] = {e40.x, e40.y, e40.z, e40.w, e41.x, e41.y, e41.z, e41.w};

    float o8[8];
#pragma unroll
    for (int i = 0; i < 8; ++i) {
        float t = (acc[i] - mu) * rstd * gm[i] + bt[i];
        o8[i] = (t > 0.f) ? t : 0.01f * t;
    }

    if (outf) {
        if (eid == 0) {
            float4* dst = (float4*)(outf + (size_t)v * 128);
            dst[2 * part]     = make_float4(o8[0], o8[1], o8[2], o8[3]);
            dst[2 * part + 1] = make_float4(o8[4], o8[5], o8[6], o8[7]);
        }
    } else {
        // stage hi/lo u32s in smem, read back in fragment order
        if (eid == 0) {
#pragma unroll
            for (int q = 0; q < 4; ++q) {
                float a = o8[2 * q], b = o8[2 * q + 1];
                s_hi[warp][4 * part + q] = bf2(a, b);
                s_lo[warp][4 * part + q] = bf2(bf_res(a), bf_res(b));
            }
        }
        __syncwarp();
        const int ks = lane >> 2;
        const int t = lane & 3;
        const int kw = ks * 8 + t;
        uint4 o;
        o.x = s_hi[warp][kw];
        o.y = s_hi[warp][kw + 4];
        o.z = s_lo[warp][kw];
        o.w = s_lo[warp][kw + 4];
        g_ap[(size_t)v * 32 + lane] = o;
    }
}

// ---------------- launcher --------------------------------------------------
extern "C" void kernel_launch(void* const* d_in, const int* in_sizes, int n_in,
                              void* d_out, int out_size) {
    const float* x       = (const float*)d_in[0];
    const int*   ei      = (const int*)  d_in[1];
    const float* W_in    = (const float*)d_in[2];
    const float* b_in    = (const float*)d_in[3];
    const float* Wl      = (const float*)d_in[4];
    const float* att_src = (const float*)d_in[5];
    const float* att_dst = (const float*)d_in[6];
    const float* bias_l  = (const float*)d_in[7];
    const float* gamma   = (const float*)d_in[8];
    const float* beta    = (const float*)d_in[9];
    float* out = (float*)d_out;

    const int SMEM_B = 65536;
    static int smem_set = 0;
    if (!smem_set) {
        cudaFuncSetAttribute(mma_gemm, cudaFuncAttributeMaxDynamicSharedMemorySize, SMEM_B);
        smem_set = 1;
    }

    const int gemm_blocks = (NN + 127) / 128;         // 782
    const int node_warp_blocks = (NN + 7) / 8;        // 12500
    const int setup_blocks = 80 + 12500 + (NN + 255) / 256;   // 12971

    // order keeps the profiled launch (#3) on the GEMM
    k_setup<<<setup_blocks, 256>>>(x, W_in, Wl);                     // 0
    k_hist<<<(EE + 255) / 256, 256>>>(ei);                           // 1
    k_scan_block<<<NB, SCAN_B>>>();                                  // 2
    mma_gemm<<<gemm_blocks, 256, SMEM_B>>>(0, 0, b_in,               // 3 <- profiled
                                           nullptr, nullptr);
    k_scan_bsums<<<1, 128>>>();                                      // 4
    k_scan_fix<<<NB, SCAN_B>>>();                                    // 5
    k_scatter<<<(EE + 255) / 256, 256>>>(ei);                        // 6

    for (int i = 0; i < 4; i++) {
        mma_gemm<<<gemm_blocks, 256, SMEM_B>>>(i + 1, 1, nullptr,
                                               att_src + i * 128, att_dst + i * 128);
        float* dst = (i == 3) ? out : nullptr;
        k_agg<<<node_warp_blocks, 256>>>(bias_l + i * 128, gamma + i * 128,
                                         beta + i * 128, dst);
    }
}

// round 11
// speedup vs baseline: 2.0570x; 1.0111x over previous
#include <cuda_runtime.h>
#include <cuda_fp16.h>
#include <cuda_bf16.h>
#include <cstdint>

#define NN 100000
#define EE 1600000
#define SCAN_B 1024
#define NB ((NN + SCAN_B - 1) / SCAN_B)   // 98

typedef unsigned long long u64;
typedef unsigned int u32;

// ---------------- scratch (device globals; no allocation allowed) ----------
// A operand, packed per row in mma-fragment order:
// g_ap[row*32 + ks*4 + t] = uint4{ hi[kw], hi[kw+4], lo[kw], lo[kw+4] }, kw=ks*8+t
__device__ uint4 g_ap[NN * 32];            // h fragments (GEMM A operand, layers 1..4)
__device__ uint4 g_apx[NN * 32];           // x fragments (input projection source)
__device__ uint4 g_bfrag[5 * 16 * 8 * 32]; // W fragments: {bh0,bh1,bl0,bl1} per lane
__device__ uint2 g_h2h[NN * 32];           // fp16 copy of h2 rows
__device__ float g_as2[NN * 2];            // att-src dot, per N-half partial
__device__ float g_ad2[NN * 2];            // att-dst dot, per N-half partial
__device__ uint2 g_ews[EE];                // {exp-weight bits, src} per CSR slot
__device__ int   g_deg[NN];
__device__ int   g_incl[NN];
__device__ int   g_cursor[NN];
__device__ int   g_rowptr[NN + 1];
__device__ int   g_srcs[EE];
__device__ int   g_bsums[128];

// ---------------- small helpers --------------------------------------------
__device__ __forceinline__ u32 bf2(float a, float b) {
    __nv_bfloat162 t = __floats2bfloat162_rn(a, b);
    return *reinterpret_cast<u32*>(&t);
}
__device__ __forceinline__ u32 hf2(float a, float b) {
    __half2 t = __floats2half2_rn(a, b);
    return *reinterpret_cast<u32*>(&t);
}
__device__ __forceinline__ float bf_res(float v) {   // residual after bf16-hi
    return v - __bfloat162float(__float2bfloat16_rn(v));
}

// Shuffle a row (lane l owns u32 indices 2l, 2l+1 of hi and lo) into the
// packed fragment uint4 for this lane's (ks = l>>2, t = l&3) slot.
__device__ __forceinline__ uint4 pack_row_frag(u32 hx, u32 hy, u32 lx, u32 ly, int lane) {
    const int src0 = ((lane >> 2) << 2) + ((lane & 3) >> 1);  // kw>>1
    const int sel = lane & 1;                                  // kw&1
    u32 h0a = __shfl_sync(0xffffffffu, hx, src0);
    u32 h0b = __shfl_sync(0xffffffffu, hy, src0);
    u32 h1a = __shfl_sync(0xffffffffu, hx, src0 + 2);
    u32 h1b = __shfl_sync(0xffffffffu, hy, src0 + 2);
    u32 l0a = __shfl_sync(0xffffffffu, lx, src0);
    u32 l0b = __shfl_sync(0xffffffffu, ly, src0);
    u32 l1a = __shfl_sync(0xffffffffu, lx, src0 + 2);
    u32 l1b = __shfl_sync(0xffffffffu, ly, src0 + 2);
    uint4 r;
    r.x = sel ? h0b : h0a;
    r.y = sel ? h1b : h1a;
    r.z = sel ? l0b : l0a;
    r.w = sel ? l1b : l1a;
    return r;
}

// mma.sync m16n8k16 bf16 x fp32-acc (baseline sm_80+ instruction; no *_a arch)
__device__ __forceinline__ void mma16816(
    float& c0, float& c1, float& c2, float& c3,
    u32 a0, u32 a1, u32 a2, u32 a3, u32 b0, u32 b1)
{
    asm volatile(
        "mma.sync.aligned.m16n8k16.row.col.f32.bf16.bf16.f32 "
        "{%0,%1,%2,%3}, {%4,%5,%6,%7}, {%8,%9}, {%0,%1,%2,%3};"
        : "+f"(c0), "+f"(c1), "+f"(c2), "+f"(c3)
        : "r"(a0), "r"(a1), "r"(a2), "r"(a3), "r"(b0), "r"(b1));
}

// ---------------- fused setup: W fragments + x conversion + zeroing --------
// block ranges: [0,80) prep_bfrag; [80, 80+12500) convert_x; rest zero.
__global__ __launch_bounds__(256) void k_setup(
    const float* __restrict__ x,
    const float* __restrict__ W_in, const float* __restrict__ Wl)
{
    const int bid = blockIdx.x;
    const int tid = threadIdx.x;
    if (bid < 80) {
        int idx = bid * 256 + tid;                 // over 20480
        int lane = idx & 31;
        int ks = (idx >> 5) & 7;
        int nb = (idx >> 8) & 15;
        int l = idx >> 12;
        int g = lane >> 2;
        int t = lane & 3;
        int n = nb * 8 + g;
        int kw = ks * 8 + t;
        const float* W = (l == 0) ? W_in : (Wl + (size_t)(l - 1) * 16384);
        float v00 = W[(2 * kw) * 128 + n];
        float v01 = W[(2 * kw + 1) * 128 + n];
        float v10 = W[(2 * kw + 8) * 128 + n];
        float v11 = W[(2 * kw + 9) * 128 + n];
        uint4 f;
        f.x = bf2(v00, v01);
        f.y = bf2(v10, v11);
        f.z = bf2(bf_res(v00), bf_res(v01));
        f.w = bf2(bf_res(v10), bf_res(v11));
        g_bfrag[idx] = f;
    } else if (bid < 80 + 12500) {
        int row = ((bid - 80) << 3) + (tid >> 5);  // 8 rows per block
        int lane = tid & 31;
        if (row < NN) {
            float4 v = ((const float4*)x)[(size_t)row * 32 + lane];
            u32 hx = bf2(v.x, v.y), hy = bf2(v.z, v.w);
            u32 lx = bf2(bf_res(v.x), bf_res(v.y)), ly = bf2(bf_res(v.z), bf_res(v.w));
            g_apx[(size_t)row * 32 + lane] = pack_row_frag(hx, hy, lx, ly, lane);
        }
    } else {
        int i = (bid - 80 - 12500) * 256 + tid;
        if (i < NN) { g_deg[i] = 0; g_cursor[i] = 0; }
    }
}

// ---------------- CSR construction -----------------------------------------
__global__ void k_hist(const int* __restrict__ ei) {
    int e = blockIdx.x * blockDim.x + threadIdx.x;
    if (e < EE) atomicAdd(&g_deg[ei[EE + e]], 1);
}
__global__ void k_scan_block() {
    __shared__ int sh[SCAN_B];
    int i = blockIdx.x * SCAN_B + threadIdx.x;
    int v = (i < NN) ? g_deg[i] : 0;
    sh[threadIdx.x] = v;
    __syncthreads();
    for (int off = 1; off < SCAN_B; off <<= 1) {
        int t = 0;
        if (threadIdx.x >= off) t = sh[threadIdx.x - off];
        __syncthreads();
        if (threadIdx.x >= off) sh[threadIdx.x] += t;
        __syncthreads();
    }
    if (i < NN) g_incl[i] = sh[threadIdx.x];
    if (threadIdx.x == SCAN_B - 1) g_bsums[blockIdx.x] = sh[SCAN_B - 1];
}
__global__ void k_scan_bsums() {
    __shared__ int sh[128];
    int t = threadIdx.x;
    sh[t] = (t < NB) ? g_bsums[t] : 0;
    __syncthreads();
    for (int off = 1; off < 128; off <<= 1) {
        int v = 0;
        if (t >= off) v = sh[t - off];
        __syncthreads();
        if (t >= off) sh[t] += v;
        __syncthreads();
    }
    if (t < NB) g_bsums[t] = sh[t];
}
__global__ void k_scan_fix() {
    int i = blockIdx.x * SCAN_B + threadIdx.x;
    if (i < NN) {
        int off = (blockIdx.x > 0) ? g_bsums[blockIdx.x - 1] : 0;
        g_rowptr[i + 1] = g_incl[i] + off;
    }
    if (i == 0) g_rowptr[0] = 0;
}
__global__ void k_scatter(const int* __restrict__ ei) {
    int e = blockIdx.x * blockDim.x + threadIdx.x;
    if (e >= EE) return;
    int s = ei[e];
    int d = ei[EE + e];
    int pos = g_rowptr[d] + atomicAdd(&g_cursor[d], 1);
    g_srcs[pos] = s;
}

// ---------------- HMMA GEMM: tile M=128 x N=64 per CTA, K=128, split bf16 --
// grid (782, 2): blockIdx.y selects the N-half. 8 warps; each computes
// 16 rows x 64 cols. 3 CTAs/SM (24 warps) via reduced regs + 32 KB smem.
// A is read from Ain (g_apx for layer 0, g_ap afterwards); mode-0 writes go
// to g_ap — distinct buffers, so the two N-half CTAs never race.
// mode 0: leaky(acc+bias) -> packed bf16 fragments into this half's g_ap slots
// mode 1: partial att dots -> g_as2/g_ad2[row*2+by]; fp16 row copy -> g_h2h
__global__ __launch_bounds__(256, 3) void mma_gemm(
    const uint4* __restrict__ Ain,
    int wslot, int mode,
    const float* __restrict__ bias,
    const float* __restrict__ attS, const float* __restrict__ attD)
{
    __shared__ uint4 sB[2048];   // 32 KB: this half's B fragments
    const int tid  = threadIdx.x;
    const int warp = tid >> 5;
    const int lane = tid & 31;
    const int g = lane >> 2;
    const int t = lane & 3;
    const int by = blockIdx.y;

    {
        const uint4* bf = g_bfrag + (size_t)wslot * 4096 + (size_t)by * 2048;
#pragma unroll
        for (int i = 0; i < 8; ++i)
            sB[i * 256 + tid] = bf[i * 256 + tid];
    }
    __syncthreads();

    const int rowg = blockIdx.x * 128 + warp * 16 + g;
    const int rowh = rowg + 8;
    const int r0 = (rowg < NN) ? rowg : (NN - 1);
    const int r1 = (rowh < NN) ? rowh : (NN - 1);

    const uint4* __restrict__ ap0 = Ain + (size_t)r0 * 32;
    const uint4* __restrict__ ap1 = Ain + (size_t)r1 * 32;

    float acc[8][4];
#pragma unroll
    for (int nb = 0; nb < 8; ++nb)
#pragma unroll
        for (int j = 0; j < 4; ++j) acc[nb][j] = 0.f;

#pragma unroll
    for (int ks = 0; ks < 8; ++ks) {
        uint4 Ag = ap0[ks * 4 + t];
        uint4 Ahh = ap1[ks * 4 + t];
#pragma unroll
        for (int nb = 0; nb < 8; ++nb) {
            uint4 b = sB[(nb * 8 + ks) * 32 + lane];
            mma16816(acc[nb][0], acc[nb][1], acc[nb][2], acc[nb][3],
                     Ag.x, Ahh.x, Ag.y, Ahh.y, b.x, b.y);
            mma16816(acc[nb][0], acc[nb][1], acc[nb][2], acc[nb][3],
                     Ag.x, Ahh.x, Ag.y, Ahh.y, b.z, b.w);
            mma16816(acc[nb][0], acc[nb][1], acc[nb][2], acc[nb][3],
                     Ag.z, Ahh.z, Ag.w, Ahh.w, b.x, b.y);
        }
    }

    const bool vg = rowg < NN;
    const bool vh = rowh < NN;

    if (mode == 0) {
        // this half owns packed slots [by*16, by*16+16) of each row
        uint4* apg = g_ap + (size_t)rowg * 32 + by * 16;
        uint4* aph = g_ap + (size_t)rowh * 32 + by * 16;
#pragma unroll
        for (int k = 0; k < 4; ++k) {
            const int nb0 = 2 * k, nb1 = 2 * k + 1;
            const int c0 = by * 64 + nb0 * 8 + 2 * t;
            const int c1 = by * 64 + nb1 * 8 + 2 * t;
            float b00 = __ldg(bias + c0), b01 = __ldg(bias + c0 + 1);
            float b10 = __ldg(bias + c1), b11 = __ldg(bias + c1 + 1);
            float f0 = acc[nb0][0] + b00, f1 = acc[nb0][1] + b01;
            float f2 = acc[nb0][2] + b00, f3 = acc[nb0][3] + b01;
            float f4 = acc[nb1][0] + b10, f5 = acc[nb1][1] + b11;
            float f6 = acc[nb1][2] + b10, f7 = acc[nb1][3] + b11;
            f0 = (f0 > 0.f) ? f0 : 0.01f * f0;
            f1 = (f1 > 0.f) ? f1 : 0.01f * f1;
            f2 = (f2 > 0.f) ? f2 : 0.01f * f2;
            f3 = (f3 > 0.f) ? f3 : 0.01f * f3;
            f4 = (f4 > 0.f) ? f4 : 0.01f * f4;
            f5 = (f5 > 0.f) ? f5 : 0.01f * f5;
            f6 = (f6 > 0.f) ? f6 : 0.01f * f6;
            f7 = (f7 > 0.f) ? f7 : 0.01f * f7;
            if (vg) {
                uint4 o;
                o.x = bf2(f0, f1);
                o.y = bf2(f4, f5);
                o.z = bf2(bf_res(f0), bf_res(f1));
                o.w = bf2(bf_res(f4), bf_res(f5));
                apg[k * 4 + t] = o;
            }
            if (vh) {
                uint4 o;
                o.x = bf2(f2, f3);
                o.y = bf2(f6, f7);
                o.z = bf2(bf_res(f2), bf_res(f3));
                o.w = bf2(bf_res(f6), bf_res(f7));
                aph[k * 4 + t] = o;
            }
        }
    } else {
        float sg = 0.f, dg = 0.f, sh = 0.f, dh = 0.f;
        u32* hg = (u32*)g_h2h + (size_t)rowg * 64;
        u32* hh = (u32*)g_h2h + (size_t)rowh * 64;
#pragma unroll
        for (int nb = 0; nb < 8; ++nb) {
            const int c0 = by * 64 + nb * 8 + 2 * t;
            float s0 = __ldg(attS + c0), s1 = __ldg(attS + c0 + 1);
            float d0 = __ldg(attD + c0), d1 = __ldg(attD + c0 + 1);
            float f0 = acc[nb][0], f1 = acc[nb][1];
            float f2 = acc[nb][2], f3 = acc[nb][3];
            sg += f0 * s0 + f1 * s1;
            dg += f0 * d0 + f1 * d1;
            sh += f2 * s0 + f3 * s1;
            dh += f2 * d0 + f3 * d1;
            const int ui = (by * 8 + nb) * 4 + t;
            if (vg) hg[ui] = hf2(f0, f1);
            if (vh) hh[ui] = hf2(f2, f3);
        }
#pragma unroll
        for (int o = 1; o <= 2; o <<= 1) {
            sg += __shfl_xor_sync(0xffffffffu, sg, o);
            dg += __shfl_xor_sync(0xffffffffu, dg, o);
            sh += __shfl_xor_sync(0xffffffffu, sh, o);
            dh += __shfl_xor_sync(0xffffffffu, dh, o);
        }
        if (t == 0) {
            if (vg) { g_as2[rowg * 2 + by] = sg; g_ad2[rowg * 2 + by] = dg; }
            if (vh) { g_as2[rowh * 2 + by] = sh; g_ad2[rowh * 2 + by] = dh; }
        }
    }
}

// ------- warp-per-node softmax aggregate -------------------------------------
// Pass A: per-edge {w=exp(leaky(as[src]+ad[v])), src} -> g_ews; as/ad read as
// per-half pairs (sum of two partials). Pass B: 8 edges per warp iteration.
// outf != null (last layer): write fp32; else write packed bf16 fragments.
__global__ __launch_bounds__(256) void k_agg(
    const float* __restrict__ bias, const float* __restrict__ gamma,
    const float* __restrict__ beta, float* __restrict__ outf)
{
    __shared__ u32 s_hi[8][64];
    __shared__ u32 s_lo[8][64];

    const int warp = threadIdx.x >> 5;
    const int v = (blockIdx.x * blockDim.x + threadIdx.x) >> 5;
    const int lane = threadIdx.x & 31;
    if (v >= NN) return;

    const int beg = g_rowptr[v];
    const int end = g_rowptr[v + 1];
    float2 adp = ((const float2*)g_ad2)[v];
    const float adv = adp.x + adp.y;

    // pass A: fused weight+src stream, denominator
    float dn = 0.f;
    for (int j = beg + lane; j < end; j += 32) {
        int s = g_srcs[j];
        float2 ap = ((const float2*)g_as2)[s];
        float e = ap.x + ap.y + adv;
        e = (e > 0.f) ? e : 0.2f * e;
        float w = __expf(e);
        uint2 p;
        p.x = __float_as_uint(w);
        p.y = (u32)s;
        g_ews[j] = p;
        dn += w;
    }
#pragma unroll
    for (int o = 16; o > 0; o >>= 1)
        dn += __shfl_xor_sync(0xffffffffu, dn, o);
    const float winv = (end > beg) ? 1.f / (dn + 1e-16f) : 0.f;

    // pass B: payload accumulate, 8 edges per warp iteration
    const int part = lane & 15;
    const int eid = lane >> 4;
    float acc[8];
#pragma unroll
    for (int i = 0; i < 8; ++i) acc[i] = 0.f;

    for (int j0 = beg; j0 < end; j0 += 8) {
        float w[4];
        uint4 hv[4];
#pragma unroll
        for (int q = 0; q < 4; ++q) {
            const int j = j0 + 2 * q + eid;
            const bool val = j < end;
            uint2 ws = g_ews[val ? j : beg];
            w[q] = val ? __uint_as_float(ws.x) * winv : 0.f;
            hv[q] = ((const uint4*)g_h2h)[(size_t)(int)ws.y * 16 + part];
        }
#pragma unroll
        for (int q = 0; q < 4; ++q) {
            float2 f0 = __half22float2(*reinterpret_cast<__half2*>(&hv[q].x));
            float2 f1 = __half22float2(*reinterpret_cast<__half2*>(&hv[q].y));
            float2 f2 = __half22float2(*reinterpret_cast<__half2*>(&hv[q].z));
            float2 f3 = __half22float2(*reinterpret_cast<__half2*>(&hv[q].w));
            acc[0] += w[q] * f0.x; acc[1] += w[q] * f0.y;
            acc[2] += w[q] * f1.x; acc[3] += w[q] * f1.y;
            acc[4] += w[q] * f2.x; acc[5] += w[q] * f2.y;
            acc[6] += w[q] * f3.x; acc[7] += w[q] * f3.y;
        }
    }
    // merge the two edge groups (lane ^ 16 holds the same columns)
#pragma unroll
    for (int i = 0; i < 8; ++i)
        acc[i] += __shfl_xor_sync(0xffffffffu, acc[i], 16);

    // + bias (cols 8*part .. 8*part+7)
    float4 b40 = ((const float4*)bias)[2 * part];
    float4 b41 = ((const float4*)bias)[2 * part + 1];
    acc[0] += b40.x; acc[1] += b40.y; acc[2] += b40.z; acc[3] += b40.w;
    acc[4] += b41.x; acc[5] += b41.y; acc[6] += b41.z; acc[7] += b41.w;

    // LayerNorm over 128 (reduce across the 16-lane group)
    float sum = 0.f, sq = 0.f;
#pragma unroll
    for (int i = 0; i < 8; ++i) { sum += acc[i]; sq += acc[i] * acc[i]; }
#pragma unroll
    for (int o = 1; o < 16; o <<= 1) {
        sum += __shfl_xor_sync(0xffffffffu, sum, o);
        sq  += __shfl_xor_sync(0xffffffffu, sq, o);
    }
    const float mu = sum * (1.f / 128.f);
    const float var = sq * (1.f / 128.f) - mu * mu;
    const float rstd = rsqrtf(var + 1e-5f);

    float4 g40 = ((const float4*)gamma)[2 * part];
    float4 g41 = ((const float4*)gamma)[2 * part + 1];
    float4 e40 = ((const float4*)beta)[2 * part];
    float4 e41 = ((const float4*)beta)[2 * part + 1];
    float gm[8] = {g40.x, g40.y, g40.z, g40.w, g41.x, g41.y, g41.z, g41.w};
    float bt[8] = {e40.x, e40.y, e40.z, e40.w, e41.x, e41.y, e41.z, e41.w};

    float o8[8];
#pragma unroll
    for (int i = 0; i < 8; ++i) {
        float t = (acc[i] - mu) * rstd * gm[i] + bt[i];
        o8[i] = (t > 0.f) ? t : 0.01f * t;
    }

    if (outf) {
        if (eid == 0) {
            float4* dst = (float4*)(outf + (size_t)v * 128);
            dst[2 * part]     = make_float4(o8[0], o8[1], o8[2], o8[3]);
            dst[2 * part + 1] = make_float4(o8[4], o8[5], o8[6], o8[7]);
        }
    } else {
        // stage hi/lo u32s in smem, read back in fragment order
        if (eid == 0) {
#pragma unroll
            for (int q = 0; q < 4; ++q) {
                float a = o8[2 * q], b = o8[2 * q + 1];
                s_hi[warp][4 * part + q] = bf2(a, b);
                s_lo[warp][4 * part + q] = bf2(bf_res(a), bf_res(b));
            }
        }
        __syncwarp();
        const int ks = lane >> 2;
        const int t = lane & 3;
        const int kw = ks * 8 + t;
        uint4 o;
        o.x = s_hi[warp][kw];
        o.y = s_hi[warp][kw + 4];
        o.z = s_lo[warp][kw];
        o.w = s_lo[warp][kw + 4];
        g_ap[(size_t)v * 32 + lane] = o;
    }
}

// ---------------- launcher --------------------------------------------------
extern "C" void kernel_launch(void* const* d_in, const int* in_sizes, int n_in,
                              void* d_out, int out_size) {
    const float* x       = (const float*)d_in[0];
    const int*   ei      = (const int*)  d_in[1];
    const float* W_in    = (const float*)d_in[2];
    const float* b_in    = (const float*)d_in[3];
    const float* Wl      = (const float*)d_in[4];
    const float* att_src = (const float*)d_in[5];
    const float* att_dst = (const float*)d_in[6];
    const float* bias_l  = (const float*)d_in[7];
    const float* gamma   = (const float*)d_in[8];
    const float* beta    = (const float*)d_in[9];
    float* out = (float*)d_out;

    uint4 *pap = nullptr, *papx = nullptr;
    cudaGetSymbolAddress((void**)&pap, g_ap);
    cudaGetSymbolAddress((void**)&papx, g_apx);

    const dim3 gemm_grid((NN + 127) / 128, 2);        // 782 x 2
    const int node_warp_blocks = (NN + 7) / 8;        // 12500
    const int setup_blocks = 80 + 12500 + (NN + 255) / 256;   // 12971

    // order keeps the profiled launch (#3) on the GEMM
    k_setup<<<setup_blocks, 256>>>(x, W_in, Wl);                     // 0
    k_hist<<<(EE + 255) / 256, 256>>>(ei);                           // 1
    k_scan_block<<<NB, SCAN_B>>>();                                  // 2
    mma_gemm<<<gemm_grid, 256>>>(papx, 0, 0, b_in, nullptr, nullptr); // 3 <- profiled
    k_scan_bsums<<<1, 128>>>();                                      // 4
    k_scan_fix<<<NB, SCAN_B>>>();                                    // 5
    k_scatter<<<(EE + 255) / 256, 256>>>(ei);                        // 6

    for (int i = 0; i < 4; i++) {
        mma_gemm<<<gemm_grid, 256>>>(pap, i + 1, 1, nullptr,
                                     att_src + i * 128, att_dst + i * 128);
        float* dst = (i == 3) ? out : nullptr;
        k_agg<<<node_warp_blocks, 256>>>(bias_l + i * 128, gamma + i * 128,
                                         beta + i * 128, dst);
    }
}

// round 12
// speedup vs baseline: 2.1140x; 1.0277x over previous
#include <cuda_runtime.h>
#include <cuda_fp16.h>
#include <cuda_bf16.h>
#include <cstdint>

#define NN 100000
#define EE 1600000
#define SCAN_B 1024
#define NB ((NN + SCAN_B - 1) / SCAN_B)   // 98

typedef unsigned long long u64;
typedef unsigned int u32;

// ---------------- scratch (device globals; no allocation allowed) ----------
__device__ uint4 g_ap[NN * 32];            // h fragments (GEMM A operand, layers 1..4)
__device__ uint4 g_apx[NN * 32];           // x fragments (input projection source)
__device__ uint4 g_bfrag[5 * 16 * 8 * 32]; // W fragments: {bh0,bh1,bl0,bl1} per lane
__device__ uint2 g_h2h[NN * 32];           // fp16 copy of h2 rows
__device__ float g_as2[NN * 2];            // att-src dot, per N-half partial
__device__ float g_ad2[NN * 2];            // att-dst dot, per N-half partial
__device__ uint2 g_ews[EE];                // {exp-weight bits, src} per CSR slot
__device__ int   g_deg[NN];
__device__ int   g_incl[NN];
__device__ int   g_cursor[NN];
__device__ int   g_rowptr[NN + 1];
__device__ int   g_srcs[EE];
__device__ int   g_bsums[128];

// ---------------- small helpers --------------------------------------------
__device__ __forceinline__ u32 bf2(float a, float b) {
    __nv_bfloat162 t = __floats2bfloat162_rn(a, b);
    return *reinterpret_cast<u32*>(&t);
}
__device__ __forceinline__ u32 hf2(float a, float b) {
    __half2 t = __floats2half2_rn(a, b);
    return *reinterpret_cast<u32*>(&t);
}
__device__ __forceinline__ float bf_res(float v) {   // residual after bf16-hi
    return v - __bfloat162float(__float2bfloat16_rn(v));
}

__device__ __forceinline__ uint4 pack_row_frag(u32 hx, u32 hy, u32 lx, u32 ly, int lane) {
    const int src0 = ((lane >> 2) << 2) + ((lane & 3) >> 1);  // kw>>1
    const int sel = lane & 1;                                  // kw&1
    u32 h0a = __shfl_sync(0xffffffffu, hx, src0);
    u32 h0b = __shfl_sync(0xffffffffu, hy, src0);
    u32 h1a = __shfl_sync(0xffffffffu, hx, src0 + 2);
    u32 h1b = __shfl_sync(0xffffffffu, hy, src0 + 2);
    u32 l0a = __shfl_sync(0xffffffffu, lx, src0);
    u32 l0b = __shfl_sync(0xffffffffu, ly, src0);
    u32 l1a = __shfl_sync(0xffffffffu, lx, src0 + 2);
    u32 l1b = __shfl_sync(0xffffffffu, ly, src0 + 2);
    uint4 r;
    r.x = sel ? h0b : h0a;
    r.y = sel ? h1b : h1a;
    r.z = sel ? l0b : l0a;
    r.w = sel ? l1b : l1a;
    return r;
}

__device__ __forceinline__ void mma16816(
    float& c0, float& c1, float& c2, float& c3,
    u32 a0, u32 a1, u32 a2, u32 a3, u32 b0, u32 b1)
{
    asm volatile(
        "mma.sync.aligned.m16n8k16.row.col.f32.bf16.bf16.f32 "
        "{%0,%1,%2,%3}, {%4,%5,%6,%7}, {%8,%9}, {%0,%1,%2,%3};"
        : "+f"(c0), "+f"(c1), "+f"(c2), "+f"(c3)
        : "r"(a0), "r"(a1), "r"(a2), "r"(a3), "r"(b0), "r"(b1));
}

// ---------------- fused setup: W fragments + x conversion -------------------
// block ranges: [0,80) prep_bfrag; [80, 80+12500) convert_x.
__global__ __launch_bounds__(256) void k_setup(
    const float* __restrict__ x,
    const float* __restrict__ W_in, const float* __restrict__ Wl)
{
    const int bid = blockIdx.x;
    const int tid = threadIdx.x;
    if (bid < 80) {
        int idx = bid * 256 + tid;                 // over 20480
        int lane = idx & 31;
        int ks = (idx >> 5) & 7;
        int nb = (idx >> 8) & 15;
        int l = idx >> 12;
        int g = lane >> 2;
        int t = lane & 3;
        int n = nb * 8 + g;
        int kw = ks * 8 + t;
        const float* W = (l == 0) ? W_in : (Wl + (size_t)(l - 1) * 16384);
        float v00 = W[(2 * kw) * 128 + n];
        float v01 = W[(2 * kw + 1) * 128 + n];
        float v10 = W[(2 * kw + 8) * 128 + n];
        float v11 = W[(2 * kw + 9) * 128 + n];
        uint4 f;
        f.x = bf2(v00, v01);
        f.y = bf2(v10, v11);
        f.z = bf2(bf_res(v00), bf_res(v01));
        f.w = bf2(bf_res(v10), bf_res(v11));
        g_bfrag[idx] = f;
    } else {
        int row = ((bid - 80) << 3) + (tid >> 5);  // 8 rows per block
        int lane = tid & 31;
        if (row < NN) {
            float4 v = ((const float4*)x)[(size_t)row * 32 + lane];
            u32 hx = bf2(v.x, v.y), hy = bf2(v.z, v.w);
            u32 lx = bf2(bf_res(v.x), bf_res(v.y)), ly = bf2(bf_res(v.z), bf_res(v.w));
            g_apx[(size_t)row * 32 + lane] = pack_row_frag(hx, hy, lx, ly, lane);
        }
    }
}

// ---------------- CSR construction -----------------------------------------
__global__ void k_zero() {
    int i = blockIdx.x * blockDim.x + threadIdx.x;
    if (i < NN) { g_deg[i] = 0; g_cursor[i] = 0; }
}
__global__ void k_hist(const int* __restrict__ ei) {
    int e = blockIdx.x * blockDim.x + threadIdx.x;
    if (e < EE) atomicAdd(&g_deg[ei[EE + e]], 1);
}
__global__ void k_scan_block() {
    __shared__ int sh[SCAN_B];
    int i = blockIdx.x * SCAN_B + threadIdx.x;
    int v = (i < NN) ? g_deg[i] : 0;
    sh[threadIdx.x] = v;
    __syncthreads();
    for (int off = 1; off < SCAN_B; off <<= 1) {
        int t = 0;
        if (threadIdx.x >= off) t = sh[threadIdx.x - off];
        __syncthreads();
        if (threadIdx.x >= off) sh[threadIdx.x] += t;
        __syncthreads();
    }
    if (i < NN) g_incl[i] = sh[threadIdx.x];
    if (threadIdx.x == SCAN_B - 1) g_bsums[blockIdx.x] = sh[SCAN_B - 1];
}
__global__ void k_scan_bsums() {
    __shared__ int sh[128];
    int t = threadIdx.x;
    sh[t] = (t < NB) ? g_bsums[t] : 0;
    __syncthreads();
    for (int off = 1; off < 128; off <<= 1) {
        int v = 0;
        if (t >= off) v = sh[t - off];
        __syncthreads();
        if (t >= off) sh[t] += v;
        __syncthreads();
    }
    if (t < NB) g_bsums[t] = sh[t];
}
__global__ void k_scan_fix() {
    int i = blockIdx.x * SCAN_B + threadIdx.x;
    if (i < NN) {
        int off = (blockIdx.x > 0) ? g_bsums[blockIdx.x - 1] : 0;
        g_rowptr[i + 1] = g_incl[i] + off;
    }
    if (i == 0) g_rowptr[0] = 0;
}
__global__ void k_scatter(const int* __restrict__ ei) {
    int e = blockIdx.x * blockDim.x + threadIdx.x;
    if (e >= EE) return;
    int s = ei[e];
    int d = ei[EE + e];
    int pos = g_rowptr[d] + atomicAdd(&g_cursor[d], 1);
    g_srcs[pos] = s;
}

// ---------------- HMMA GEMM: tile M=128 x N=64 per CTA, K=128, split bf16 --
__global__ __launch_bounds__(256, 3) void mma_gemm(
    const uint4* __restrict__ Ain,
    int wslot, int mode,
    const float* __restrict__ bias,
    const float* __restrict__ attS, const float* __restrict__ attD)
{
    __shared__ uint4 sB[2048];   // 32 KB: this half's B fragments
    const int tid  = threadIdx.x;
    const int warp = tid >> 5;
    const int lane = tid & 31;
    const int g = lane >> 2;
    const int t = lane & 3;
    const int by = blockIdx.y;

    {
        const uint4* bf = g_bfrag + (size_t)wslot * 4096 + (size_t)by * 2048;
#pragma unroll
        for (int i = 0; i < 8; ++i)
            sB[i * 256 + tid] = bf[i * 256 + tid];
    }
    __syncthreads();

    const int rowg = blockIdx.x * 128 + warp * 16 + g;
    const int rowh = rowg + 8;
    const int r0 = (rowg < NN) ? rowg : (NN - 1);
    const int r1 = (rowh < NN) ? rowh : (NN - 1);

    const uint4* __restrict__ ap0 = Ain + (size_t)r0 * 32;
    const uint4* __restrict__ ap1 = Ain + (size_t)r1 * 32;

    float acc[8][4];
#pragma unroll
    for (int nb = 0; nb < 8; ++nb)
#pragma unroll
        for (int j = 0; j < 4; ++j) acc[nb][j] = 0.f;

#pragma unroll
    for (int ks = 0; ks < 8; ++ks) {
        uint4 Ag = ap0[ks * 4 + t];
        uint4 Ahh = ap1[ks * 4 + t];
#pragma unroll
        for (int nb = 0; nb < 8; ++nb) {
            uint4 b = sB[(nb * 8 + ks) * 32 + lane];
            mma16816(acc[nb][0], acc[nb][1], acc[nb][2], acc[nb][3],
                     Ag.x, Ahh.x, Ag.y, Ahh.y, b.x, b.y);
            mma16816(acc[nb][0], acc[nb][1], acc[nb][2], acc[nb][3],
                     Ag.x, Ahh.x, Ag.y, Ahh.y, b.z, b.w);
            mma16816(acc[nb][0], acc[nb][1], acc[nb][2], acc[nb][3],
                     Ag.z, Ahh.z, Ag.w, Ahh.w, b.x, b.y);
        }
    }

    const bool vg = rowg < NN;
    const bool vh = rowh < NN;

    if (mode == 0) {
        uint4* apg = g_ap + (size_t)rowg * 32 + by * 16;
        uint4* aph = g_ap + (size_t)rowh * 32 + by * 16;
#pragma unroll
        for (int k = 0; k < 4; ++k) {
            const int nb0 = 2 * k, nb1 = 2 * k + 1;
            const int c0 = by * 64 + nb0 * 8 + 2 * t;
            const int c1 = by * 64 + nb1 * 8 + 2 * t;
            float b00 = __ldg(bias + c0), b01 = __ldg(bias + c0 + 1);
            float b10 = __ldg(bias + c1), b11 = __ldg(bias + c1 + 1);
            float f0 = acc[nb0][0] + b00, f1 = acc[nb0][1] + b01;
            float f2 = acc[nb0][2] + b00, f3 = acc[nb0][3] + b01;
            float f4 = acc[nb1][0] + b10, f5 = acc[nb1][1] + b11;
            float f6 = acc[nb1][2] + b10, f7 = acc[nb1][3] + b11;
            f0 = (f0 > 0.f) ? f0 : 0.01f * f0;
            f1 = (f1 > 0.f) ? f1 : 0.01f * f1;
            f2 = (f2 > 0.f) ? f2 : 0.01f * f2;
            f3 = (f3 > 0.f) ? f3 : 0.01f * f3;
            f4 = (f4 > 0.f) ? f4 : 0.01f * f4;
            f5 = (f5 > 0.f) ? f5 : 0.01f * f5;
            f6 = (f6 > 0.f) ? f6 : 0.01f * f6;
            f7 = (f7 > 0.f) ? f7 : 0.01f * f7;
            if (vg) {
                uint4 o;
                o.x = bf2(f0, f1);
                o.y = bf2(f4, f5);
                o.z = bf2(bf_res(f0), bf_res(f1));
                o.w = bf2(bf_res(f4), bf_res(f5));
                apg[k * 4 + t] = o;
            }
            if (vh) {
                uint4 o;
                o.x = bf2(f2, f3);
                o.y = bf2(f6, f7);
                o.z = bf2(bf_res(f2), bf_res(f3));
                o.w = bf2(bf_res(f6), bf_res(f7));
                aph[k * 4 + t] = o;
            }
        }
    } else {
        float sg = 0.f, dg = 0.f, sh = 0.f, dh = 0.f;
        u32* hg = (u32*)g_h2h + (size_t)rowg * 64;
        u32* hh = (u32*)g_h2h + (size_t)rowh * 64;
#pragma unroll
        for (int nb = 0; nb < 8; ++nb) {
            const int c0 = by * 64 + nb * 8 + 2 * t;
            float s0 = __ldg(attS + c0), s1 = __ldg(attS + c0 + 1);
            float d0 = __ldg(attD + c0), d1 = __ldg(attD + c0 + 1);
            float f0 = acc[nb][0], f1 = acc[nb][1];
            float f2 = acc[nb][2], f3 = acc[nb][3];
            sg += f0 * s0 + f1 * s1;
            dg += f0 * d0 + f1 * d1;
            sh += f2 * s0 + f3 * s1;
            dh += f2 * d0 + f3 * d1;
            const int ui = (by * 8 + nb) * 4 + t;
            if (vg) hg[ui] = hf2(f0, f1);
            if (vh) hh[ui] = hf2(f2, f3);
        }
#pragma unroll
        for (int o = 1; o <= 2; o <<= 1) {
            sg += __shfl_xor_sync(0xffffffffu, sg, o);
            dg += __shfl_xor_sync(0xffffffffu, dg, o);
            sh += __shfl_xor_sync(0xffffffffu, sh, o);
            dh += __shfl_xor_sync(0xffffffffu, dh, o);
        }
        if (t == 0) {
            if (vg) { g_as2[rowg * 2 + by] = sg; g_ad2[rowg * 2 + by] = dg; }
            if (vh) { g_as2[rowh * 2 + by] = sh; g_ad2[rowh * 2 + by] = dh; }
        }
    }
}

// ------- warp-per-node softmax aggregate -------------------------------------
// Pass A: per-edge {w, src} -> g_ews. Pass B: 8 edges/iter with the next
// iteration's g_ews batch prefetched before consuming this iteration's rows,
// so the ews->row dependency chain pipelines across iterations.
__global__ __launch_bounds__(256) void k_agg(
    const float* __restrict__ bias, const float* __restrict__ gamma,
    const float* __restrict__ beta, float* __restrict__ outf)
{
    __shared__ u32 s_hi[8][64];
    __shared__ u32 s_lo[8][64];

    const int warp = threadIdx.x >> 5;
    const int v = (blockIdx.x * blockDim.x + threadIdx.x) >> 5;
    const int lane = threadIdx.x & 31;
    if (v >= NN) return;

    const int beg = g_rowptr[v];
    const int end = g_rowptr[v + 1];
    float2 adp = ((const float2*)g_ad2)[v];
    const float adv = adp.x + adp.y;

    // pass A: fused weight+src stream, denominator
    float dn = 0.f;
    for (int j = beg + lane; j < end; j += 32) {
        int s = g_srcs[j];
        float2 ap = ((const float2*)g_as2)[s];
        float e = ap.x + ap.y + adv;
        e = (e > 0.f) ? e : 0.2f * e;
        float w = __expf(e);
        uint2 p;
        p.x = __float_as_uint(w);
        p.y = (u32)s;
        g_ews[j] = p;
        dn += w;
    }
#pragma unroll
    for (int o = 16; o > 0; o >>= 1)
        dn += __shfl_xor_sync(0xffffffffu, dn, o);
    const float winv = (end > beg) ? 1.f / (dn + 1e-16f) : 0.f;

    // pass B: payload accumulate, 8 edges/iter with ews prefetch
    const int part = lane & 15;
    const int eid = lane >> 4;
    float acc[8];
#pragma unroll
    for (int i = 0; i < 8; ++i) acc[i] = 0.f;

    uint2 cur[4];
#pragma unroll
    for (int q = 0; q < 4; ++q) {
        int j = beg + 2 * q + eid;
        cur[q] = g_ews[(j < end) ? j : beg];
    }

    for (int j0 = beg; j0 < end; j0 += 8) {
        // issue row gathers for this batch
        float w[4];
        uint4 hv[4];
#pragma unroll
        for (int q = 0; q < 4; ++q) {
            const int j = j0 + 2 * q + eid;
            w[q] = (j < end) ? __uint_as_float(cur[q].x) * winv : 0.f;
            hv[q] = ((const uint4*)g_h2h)[(size_t)(int)cur[q].y * 16 + part];
        }
        // prefetch next batch's ews before consuming hv
        uint2 nxt[4];
#pragma unroll
        for (int q = 0; q < 4; ++q) {
            int j = j0 + 8 + 2 * q + eid;
            nxt[q] = g_ews[(j < end) ? j : beg];
        }
#pragma unroll
        for (int q = 0; q < 4; ++q) {
            float2 f0 = __half22float2(*reinterpret_cast<__half2*>(&hv[q].x));
            float2 f1 = __half22float2(*reinterpret_cast<__half2*>(&hv[q].y));
            float2 f2 = __half22float2(*reinterpret_cast<__half2*>(&hv[q].z));
            float2 f3 = __half22float2(*reinterpret_cast<__half2*>(&hv[q].w));
            acc[0] += w[q] * f0.x; acc[1] += w[q] * f0.y;
            acc[2] += w[q] * f1.x; acc[3] += w[q] * f1.y;
            acc[4] += w[q] * f2.x; acc[5] += w[q] * f2.y;
            acc[6] += w[q] * f3.x; acc[7] += w[q] * f3.y;
        }
#pragma unroll
        for (int q = 0; q < 4; ++q) cur[q] = nxt[q];
    }
    // merge the two edge groups (lane ^ 16 holds the same columns)
#pragma unroll
    for (int i = 0; i < 8; ++i)
        acc[i] += __shfl_xor_sync(0xffffffffu, acc[i], 16);

    // + bias (cols 8*part .. 8*part+7)
    float4 b40 = ((const float4*)bias)[2 * part];
    float4 b41 = ((const float4*)bias)[2 * part + 1];
    acc[0] += b40.x; acc[1] += b40.y; acc[2] += b40.z; acc[3] += b40.w;
    acc[4] += b41.x; acc[5] += b41.y; acc[6] += b41.z; acc[7] += b41.w;

    // LayerNorm over 128 (reduce across the 16-lane group)
    float sum = 0.f, sq = 0.f;
#pragma unroll
    for (int i = 0; i < 8; ++i) { sum += acc[i]; sq += acc[i] * acc[i]; }
#pragma unroll
    for (int o = 1; o < 16; o <<= 1) {
        sum += __shfl_xor_sync(0xffffffffu, sum, o);
        sq  += __shfl_xor_sync(0xffffffffu, sq, o);
    }
    const float mu = sum * (1.f / 128.f);
    const float var = sq * (1.f / 128.f) - mu * mu;
    const float rstd = rsqrtf(var + 1e-5f);

    float4 g40 = ((const float4*)gamma)[2 * part];
    float4 g41 = ((const float4*)gamma)[2 * part + 1];
    float4 e40 = ((const float4*)beta)[2 * part];
    float4 e41 = ((const float4*)beta)[2 * part + 1];
    float gm[8] = {g40.x, g40.y, g40.z, g40.w, g41.x, g41.y, g41.z, g41.w};
    float bt[8] = {e40.x, e40.y, e40.z, e40.w, e41.x, e41.y, e41.z, e41.w};

    float o8[8];
#pragma unroll
    for (int i = 0; i < 8; ++i) {
        float t = (acc[i] - mu) * rstd * gm[i] + bt[i];
        o8[i] = (t > 0.f) ? t : 0.01f * t;
    }

    if (outf) {
        if (eid == 0) {
            float4* dst = (float4*)(outf + (size_t)v * 128);
            dst[2 * part]     = make_float4(o8[0], o8[1], o8[2], o8[3]);
            dst[2 * part + 1] = make_float4(o8[4], o8[5], o8[6], o8[7]);
        }
    } else {
        if (eid == 0) {
#pragma unroll
            for (int q = 0; q < 4; ++q) {
                float a = o8[2 * q], b = o8[2 * q + 1];
                s_hi[warp][4 * part + q] = bf2(a, b);
                s_lo[warp][4 * part + q] = bf2(bf_res(a), bf_res(b));
            }
        }
        __syncwarp();
        const int ks = lane >> 2;
        const int t = lane & 3;
        const int kw = ks * 8 + t;
        uint4 o;
        o.x = s_hi[warp][kw];
        o.y = s_hi[warp][kw + 4];
        o.z = s_lo[warp][kw];
        o.w = s_lo[warp][kw + 4];
        g_ap[(size_t)v * 32 + lane] = o;
    }
}

// ---------------- launcher --------------------------------------------------
extern "C" void kernel_launch(void* const* d_in, const int* in_sizes, int n_in,
                              void* d_out, int out_size) {
    const float* x       = (const float*)d_in[0];
    const int*   ei      = (const int*)  d_in[1];
    const float* W_in    = (const float*)d_in[2];
    const float* b_in    = (const float*)d_in[3];
    const float* Wl      = (const float*)d_in[4];
    const float* att_src = (const float*)d_in[5];
    const float* att_dst = (const float*)d_in[6];
    const float* bias_l  = (const float*)d_in[7];
    const float* gamma   = (const float*)d_in[8];
    const float* beta    = (const float*)d_in[9];
    float* out = (float*)d_out;

    uint4 *pap = nullptr, *papx = nullptr;
    cudaGetSymbolAddress((void**)&pap, g_ap);
    cudaGetSymbolAddress((void**)&papx, g_apx);

    // side stream + fork/join events (created once; capture-legal pattern)
    static cudaStream_t s2 = nullptr;
    static cudaEvent_t evFork = nullptr, evJoin = nullptr;
    if (!s2) {
        cudaStreamCreateWithFlags(&s2, cudaStreamNonBlocking);
        cudaEventCreateWithFlags(&evFork, cudaEventDisableTiming);
        cudaEventCreateWithFlags(&evJoin, cudaEventDisableTiming);
    }

    const dim3 gemm_grid((NN + 127) / 128, 2);        // 782 x 2
    const int node_warp_blocks = (NN + 7) / 8;        // 12500
    const int setup_blocks = 80 + 12500;              // 12580

    // fork: CSR build on side stream, overlapped with setup + first two GEMMs
    cudaEventRecord(evFork, 0);
    cudaStreamWaitEvent(s2, evFork, 0);
    k_zero<<<(NN + 1023) / 1024, 1024, 0, s2>>>();
    k_hist<<<(EE + 255) / 256, 256, 0, s2>>>(ei);
    k_scan_block<<<NB, SCAN_B, 0, s2>>>();
    k_scan_bsums<<<1, 128, 0, s2>>>();
    k_scan_fix<<<NB, SCAN_B, 0, s2>>>();
    k_scatter<<<(EE + 255) / 256, 256, 0, s2>>>(ei);
    cudaEventRecord(evJoin, s2);

    // main stream: setup -> input projection -> layer-0 mode-1 GEMM
    k_setup<<<setup_blocks, 256>>>(x, W_in, Wl);
    mma_gemm<<<gemm_grid, 256>>>(papx, 0, 0, b_in, nullptr, nullptr);
    mma_gemm<<<gemm_grid, 256>>>(pap, 1, 1, nullptr, att_src, att_dst);

    // join: k_agg needs the CSR
    cudaStreamWaitEvent(0, evJoin, 0);

    for (int i = 0; i < 4; i++) {
        if (i > 0)
            mma_gemm<<<gemm_grid, 256>>>(pap, i + 1, 1, nullptr,
                                         att_src + i * 128, att_dst + i * 128);
        float* dst = (i == 3) ? out : nullptr;
        k_agg<<<node_warp_blocks, 256>>>(bias_l + i * 128, gamma + i * 128,
                                         beta + i * 128, dst);
    }
}

// round 13
// speedup vs baseline: 2.1167x; 1.0013x over previous
#include <cuda_runtime.h>
#include <cuda_fp16.h>
#include <cuda_bf16.h>
#include <cstdint>

#define NN 100000
#define EE 1600000
#define SCAN_B 1024
#define NB ((NN + SCAN_B - 1) / SCAN_B)   // 98
#define NTILES (NN / 16)                  // 6250 (NN divisible by 16)

typedef unsigned long long u64;
typedef unsigned int u32;

// ---------------- scratch (device globals; no allocation allowed) ----------
// A operand in 16-row-tile-major fragment layout:
// addr(row, slot) = (row>>4)*512 + (slot>>2)*64 + (row&15)*4 + (slot&3)
// where slot = ks*4+t indexes uint4{ hi[kw], hi[kw+4], lo[kw], lo[kw+4] }, kw=ks*8+t
__device__ uint4 g_ap[NN * 32];            // h fragments (GEMM A operand, layers 1..4)
__device__ uint4 g_apx[NN * 32];           // x fragments (input projection source)
__device__ uint4 g_bfrag[5 * 16 * 8 * 32]; // W fragments: {bh0,bh1,bl0,bl1} per lane
__device__ uint2 g_h2h[NN * 32];           // fp16 copy of h2 rows
__device__ float g_as2[NN * 2];            // att-src dot, per N-half partial
__device__ float g_ad2[NN * 2];            // att-dst dot, per N-half partial
__device__ uint2 g_ews[EE];                // {exp-weight bits, src} per CSR slot
__device__ int   g_deg[NN];
__device__ int   g_incl[NN];
__device__ int   g_cursor[NN];
__device__ int   g_rowptr[NN + 1];
__device__ int   g_srcs[EE];
__device__ int   g_bsums[128];

// ---------------- small helpers --------------------------------------------
__device__ __forceinline__ u32 bf2(float a, float b) {
    __nv_bfloat162 t = __floats2bfloat162_rn(a, b);
    return *reinterpret_cast<u32*>(&t);
}
__device__ __forceinline__ u32 hf2(float a, float b) {
    __half2 t = __floats2half2_rn(a, b);
    return *reinterpret_cast<u32*>(&t);
}
__device__ __forceinline__ float bf_res(float v) {   // residual after bf16-hi
    return v - __bfloat162float(__float2bfloat16_rn(v));
}
__device__ __forceinline__ size_t ap_idx(int row, int slot) {
    return (size_t)(row >> 4) * 512 + (size_t)((slot >> 2) << 6)
         + (size_t)((row & 15) << 2) + (size_t)(slot & 3);
}

__device__ __forceinline__ uint4 pack_row_frag(u32 hx, u32 hy, u32 lx, u32 ly, int lane) {
    const int src0 = ((lane >> 2) << 2) + ((lane & 3) >> 1);  // kw>>1
    const int sel = lane & 1;                                  // kw&1
    u32 h0a = __shfl_sync(0xffffffffu, hx, src0);
    u32 h0b = __shfl_sync(0xffffffffu, hy, src0);
    u32 h1a = __shfl_sync(0xffffffffu, hx, src0 + 2);
    u32 h1b = __shfl_sync(0xffffffffu, hy, src0 + 2);
    u32 l0a = __shfl_sync(0xffffffffu, lx, src0);
    u32 l0b = __shfl_sync(0xffffffffu, ly, src0);
    u32 l1a = __shfl_sync(0xffffffffu, lx, src0 + 2);
    u32 l1b = __shfl_sync(0xffffffffu, ly, src0 + 2);
    uint4 r;
    r.x = sel ? h0b : h0a;
    r.y = sel ? h1b : h1a;
    r.z = sel ? l0b : l0a;
    r.w = sel ? l1b : l1a;
    return r;
}

__device__ __forceinline__ void mma16816(
    float& c0, float& c1, float& c2, float& c3,
    u32 a0, u32 a1, u32 a2, u32 a3, u32 b0, u32 b1)
{
    asm volatile(
        "mma.sync.aligned.m16n8k16.row.col.f32.bf16.bf16.f32 "
        "{%0,%1,%2,%3}, {%4,%5,%6,%7}, {%8,%9}, {%0,%1,%2,%3};"
        : "+f"(c0), "+f"(c1), "+f"(c2), "+f"(c3)
        : "r"(a0), "r"(a1), "r"(a2), "r"(a3), "r"(b0), "r"(b1));
}

// ---------------- fused setup: W fragments + x conversion -------------------
// block ranges: [0,80) prep_bfrag; [80, 80+12500) convert_x.
__global__ __launch_bounds__(256) void k_setup(
    const float* __restrict__ x,
    const float* __restrict__ W_in, const float* __restrict__ Wl)
{
    const int bid = blockIdx.x;
    const int tid = threadIdx.x;
    if (bid < 80) {
        int idx = bid * 256 + tid;                 // over 20480
        int lane = idx & 31;
        int ks = (idx >> 5) & 7;
        int nb = (idx >> 8) & 15;
        int l = idx >> 12;
        int g = lane >> 2;
        int t = lane & 3;
        int n = nb * 8 + g;
        int kw = ks * 8 + t;
        const float* W = (l == 0) ? W_in : (Wl + (size_t)(l - 1) * 16384);
        float v00 = W[(2 * kw) * 128 + n];
        float v01 = W[(2 * kw + 1) * 128 + n];
        float v10 = W[(2 * kw + 8) * 128 + n];
        float v11 = W[(2 * kw + 9) * 128 + n];
        uint4 f;
        f.x = bf2(v00, v01);
        f.y = bf2(v10, v11);
        f.z = bf2(bf_res(v00), bf_res(v01));
        f.w = bf2(bf_res(v10), bf_res(v11));
        g_bfrag[idx] = f;
    } else {
        int row = ((bid - 80) << 3) + (tid >> 5);  // 8 rows per block
        int lane = tid & 31;
        if (row < NN) {
            float4 v = ((const float4*)x)[(size_t)row * 32 + lane];
            u32 hx = bf2(v.x, v.y), hy = bf2(v.z, v.w);
            u32 lx = bf2(bf_res(v.x), bf_res(v.y)), ly = bf2(bf_res(v.z), bf_res(v.w));
            g_apx[ap_idx(row, lane)] = pack_row_frag(hx, hy, lx, ly, lane);
        }
    }
}

// ---------------- CSR construction -----------------------------------------
__global__ void k_zero() {
    int i = blockIdx.x * blockDim.x + threadIdx.x;
    if (i < NN) { g_deg[i] = 0; g_cursor[i] = 0; }
}
__global__ void k_hist(const int* __restrict__ ei) {
    int e = blockIdx.x * blockDim.x + threadIdx.x;
    if (e < EE) atomicAdd(&g_deg[ei[EE + e]], 1);
}
__global__ void k_scan_block() {
    __shared__ int sh[SCAN_B];
    int i = blockIdx.x * SCAN_B + threadIdx.x;
    int v = (i < NN) ? g_deg[i] : 0;
    sh[threadIdx.x] = v;
    __syncthreads();
    for (int off = 1; off < SCAN_B; off <<= 1) {
        int t = 0;
        if (threadIdx.x >= off) t = sh[threadIdx.x - off];
        __syncthreads();
        if (threadIdx.x >= off) sh[threadIdx.x] += t;
        __syncthreads();
    }
    if (i < NN) g_incl[i] = sh[threadIdx.x];
    if (threadIdx.x == SCAN_B - 1) g_bsums[blockIdx.x] = sh[SCAN_B - 1];
}
__global__ void k_scan_bsums() {
    __shared__ int sh[128];
    int t = threadIdx.x;
    sh[t] = (t < NB) ? g_bsums[t] : 0;
    __syncthreads();
    for (int off = 1; off < 128; off <<= 1) {
        int v = 0;
        if (t >= off) v = sh[t - off];
        __syncthreads();
        if (t >= off) sh[t] += v;
        __syncthreads();
    }
    if (t < NB) g_bsums[t] = sh[t];
}
__global__ void k_scan_fix() {
    int i = blockIdx.x * SCAN_B + threadIdx.x;
    if (i < NN) {
        int off = (blockIdx.x > 0) ? g_bsums[blockIdx.x - 1] : 0;
        g_rowptr[i + 1] = g_incl[i] + off;
    }
    if (i == 0) g_rowptr[0] = 0;
}
__global__ void k_scatter(const int* __restrict__ ei) {
    int e = blockIdx.x * blockDim.x + threadIdx.x;
    if (e >= EE) return;
    int s = ei[e];
    int d = ei[EE + e];
    int pos = g_rowptr[d] + atomicAdd(&g_cursor[d], 1);
    g_srcs[pos] = s;
}

// ---------------- HMMA GEMM: tile M=128 x N=64 per CTA, K=128, split bf16 --
// A reads are fully coalesced from the tile-major fragment layout:
// per ks, two contiguous 512 B LDG.128 (rows g and g+8 of the warp's tile).
__global__ __launch_bounds__(256, 3) void mma_gemm(
    const uint4* __restrict__ Ain,
    int wslot, int mode,
    const float* __restrict__ bias,
    const float* __restrict__ attS, const float* __restrict__ attD)
{
    __shared__ uint4 sB[2048];   // 32 KB: this half's B fragments
    const int tid  = threadIdx.x;
    const int warp = tid >> 5;
    const int lane = tid & 31;
    const int g = lane >> 2;
    const int t = lane & 3;
    const int by = blockIdx.y;

    {
        const uint4* bf = g_bfrag + (size_t)wslot * 4096 + (size_t)by * 2048;
#pragma unroll
        for (int i = 0; i < 8; ++i)
            sB[i * 256 + tid] = bf[i * 256 + tid];
    }
    __syncthreads();

    const int tile = blockIdx.x * 8 + warp;              // 16-row tile index
    const int tl = (tile < NTILES) ? tile : (NTILES - 1); // whole-tile clamp
    const int rowg = tile * 16 + g;
    const int rowh = rowg + 8;

    const uint4* __restrict__ at = Ain + (size_t)tl * 512;

    float acc[8][4];
#pragma unroll
    for (int nb = 0; nb < 8; ++nb)
#pragma unroll
        for (int j = 0; j < 4; ++j) acc[nb][j] = 0.f;

#pragma unroll
    for (int ks = 0; ks < 8; ++ks) {
        uint4 Ag  = at[ks * 64 + lane];        // rows tile*16+g,   slot ks*4+t
        uint4 Ahh = at[ks * 64 + 32 + lane];   // rows tile*16+8+g, slot ks*4+t
#pragma unroll
        for (int nb = 0; nb < 8; ++nb) {
            uint4 b = sB[(nb * 8 + ks) * 32 + lane];
            mma16816(acc[nb][0], acc[nb][1], acc[nb][2], acc[nb][3],
                     Ag.x, Ahh.x, Ag.y, Ahh.y, b.x, b.y);
            mma16816(acc[nb][0], acc[nb][1], acc[nb][2], acc[nb][3],
                     Ag.x, Ahh.x, Ag.y, Ahh.y, b.z, b.w);
            mma16816(acc[nb][0], acc[nb][1], acc[nb][2], acc[nb][3],
                     Ag.z, Ahh.z, Ag.w, Ahh.w, b.x, b.y);
        }
    }

    const bool vg = rowg < NN;
    const bool vh = rowh < NN;

    if (mode == 0) {
        // tile-major writes: per k, 512 B fully contiguous across the warp
        uint4* atw = g_ap + (size_t)tl * 512;
#pragma unroll
        for (int k = 0; k < 4; ++k) {
            const int nb0 = 2 * k, nb1 = 2 * k + 1;
            const int c0 = by * 64 + nb0 * 8 + 2 * t;
            const int c1 = by * 64 + nb1 * 8 + 2 * t;
            float b00 = __ldg(bias + c0), b01 = __ldg(bias + c0 + 1);
            float b10 = __ldg(bias + c1), b11 = __ldg(bias + c1 + 1);
            float f0 = acc[nb0][0] + b00, f1 = acc[nb0][1] + b01;
            float f2 = acc[nb0][2] + b00, f3 = acc[nb0][3] + b01;
            float f4 = acc[nb1][0] + b10, f5 = acc[nb1][1] + b11;
            float f6 = acc[nb1][2] + b10, f7 = acc[nb1][3] + b11;
            f0 = (f0 > 0.f) ? f0 : 0.01f * f0;
            f1 = (f1 > 0.f) ? f1 : 0.01f * f1;
            f2 = (f2 > 0.f) ? f2 : 0.01f * f2;
            f3 = (f3 > 0.f) ? f3 : 0.01f * f3;
            f4 = (f4 > 0.f) ? f4 : 0.01f * f4;
            f5 = (f5 > 0.f) ? f5 : 0.01f * f5;
            f6 = (f6 > 0.f) ? f6 : 0.01f * f6;
            f7 = (f7 > 0.f) ? f7 : 0.01f * f7;
            const int ksl = by * 4 + k;   // slot>>2 for this k
            if (vg) {
                uint4 o;
                o.x = bf2(f0, f1);
                o.y = bf2(f4, f5);
                o.z = bf2(bf_res(f0), bf_res(f1));
                o.w = bf2(bf_res(f4), bf_res(f5));
                atw[ksl * 64 + g * 4 + t] = o;
            }
            if (vh) {
                uint4 o;
                o.x = bf2(f2, f3);
                o.y = bf2(f6, f7);
                o.z = bf2(bf_res(f2), bf_res(f3));
                o.w = bf2(bf_res(f6), bf_res(f7));
                atw[ksl * 64 + 32 + g * 4 + t] = o;
            }
        }
    } else {
        float sg = 0.f, dg = 0.f, sh = 0.f, dh = 0.f;
        u32* hg = (u32*)g_h2h + (size_t)rowg * 64;
        u32* hh = (u32*)g_h2h + (size_t)rowh * 64;
#pragma unroll
        for (int nb = 0; nb < 8; ++nb) {
            const int c0 = by * 64 + nb * 8 + 2 * t;
            float s0 = __ldg(attS + c0), s1 = __ldg(attS + c0 + 1);
            float d0 = __ldg(attD + c0), d1 = __ldg(attD + c0 + 1);
            float f0 = acc[nb][0], f1 = acc[nb][1];
            float f2 = acc[nb][2], f3 = acc[nb][3];
            sg += f0 * s0 + f1 * s1;
            dg += f0 * d0 + f1 * d1;
            sh += f2 * s0 + f3 * s1;
            dh += f2 * d0 + f3 * d1;
            const int ui = (by * 8 + nb) * 4 + t;
            if (vg) hg[ui] = hf2(f0, f1);
            if (vh) hh[ui] = hf2(f2, f3);
        }
#pragma unroll
        for (int o = 1; o <= 2; o <<= 1) {
            sg += __shfl_xor_sync(0xffffffffu, sg, o);
            dg += __shfl_xor_sync(0xffffffffu, dg, o);
            sh += __shfl_xor_sync(0xffffffffu, sh, o);
            dh += __shfl_xor_sync(0xffffffffu, dh, o);
        }
        if (t == 0) {
            if (vg) { g_as2[rowg * 2 + by] = sg; g_ad2[rowg * 2 + by] = dg; }
            if (vh) { g_as2[rowh * 2 + by] = sh; g_ad2[rowh * 2 + by] = dh; }
        }
    }
}

// ------- warp-per-node softmax aggregate -------------------------------------
__global__ __launch_bounds__(256) void k_agg(
    const float* __restrict__ bias, const float* __restrict__ gamma,
    const float* __restrict__ beta, float* __restrict__ outf)
{
    __shared__ u32 s_hi[8][64];
    __shared__ u32 s_lo[8][64];

    const int warp = threadIdx.x >> 5;
    const int v = (blockIdx.x * blockDim.x + threadIdx.x) >> 5;
    const int lane = threadIdx.x & 31;
    if (v >= NN) return;

    const int beg = g_rowptr[v];
    const int end = g_rowptr[v + 1];
    float2 adp = ((const float2*)g_ad2)[v];
    const float adv = adp.x + adp.y;

    // pass A: fused weight+src stream, denominator
    float dn = 0.f;
    for (int j = beg + lane; j < end; j += 32) {
        int s = g_srcs[j];
        float2 ap = ((const float2*)g_as2)[s];
        float e = ap.x + ap.y + adv;
        e = (e > 0.f) ? e : 0.2f * e;
        float w = __expf(e);
        uint2 p;
        p.x = __float_as_uint(w);
        p.y = (u32)s;
        g_ews[j] = p;
        dn += w;
    }
#pragma unroll
    for (int o = 16; o > 0; o >>= 1)
        dn += __shfl_xor_sync(0xffffffffu, dn, o);
    const float winv = (end > beg) ? 1.f / (dn + 1e-16f) : 0.f;

    // pass B: payload accumulate, 8 edges/iter with ews prefetch
    const int part = lane & 15;
    const int eid = lane >> 4;
    float acc[8];
#pragma unroll
    for (int i = 0; i < 8; ++i) acc[i] = 0.f;

    uint2 cur[4];
#pragma unroll
    for (int q = 0; q < 4; ++q) {
        int j = beg + 2 * q + eid;
        cur[q] = g_ews[(j < end) ? j : beg];
    }

    for (int j0 = beg; j0 < end; j0 += 8) {
        float w[4];
        uint4 hv[4];
#pragma unroll
        for (int q = 0; q < 4; ++q) {
            const int j = j0 + 2 * q + eid;
            w[q] = (j < end) ? __uint_as_float(cur[q].x) * winv : 0.f;
            hv[q] = ((const uint4*)g_h2h)[(size_t)(int)cur[q].y * 16 + part];
        }
        uint2 nxt[4];
#pragma unroll
        for (int q = 0; q < 4; ++q) {
            int j = j0 + 8 + 2 * q + eid;
            nxt[q] = g_ews[(j < end) ? j : beg];
        }
#pragma unroll
        for (int q = 0; q < 4; ++q) {
            float2 f0 = __half22float2(*reinterpret_cast<__half2*>(&hv[q].x));
            float2 f1 = __half22float2(*reinterpret_cast<__half2*>(&hv[q].y));
            float2 f2 = __half22float2(*reinterpret_cast<__half2*>(&hv[q].z));
            float2 f3 = __half22float2(*reinterpret_cast<__half2*>(&hv[q].w));
            acc[0] += w[q] * f0.x; acc[1] += w[q] * f0.y;
            acc[2] += w[q] * f1.x; acc[3] += w[q] * f1.y;
            acc[4] += w[q] * f2.x; acc[5] += w[q] * f2.y;
            acc[6] += w[q] * f3.x; acc[7] += w[q] * f3.y;
        }
#pragma unroll
        for (int q = 0; q < 4; ++q) cur[q] = nxt[q];
    }
#pragma unroll
    for (int i = 0; i < 8; ++i)
        acc[i] += __shfl_xor_sync(0xffffffffu, acc[i], 16);

    float4 b40 = ((const float4*)bias)[2 * part];
    float4 b41 = ((const float4*)bias)[2 * part + 1];
    acc[0] += b40.x; acc[1] += b40.y; acc[2] += b40.z; acc[3] += b40.w;
    acc[4] += b41.x; acc[5] += b41.y; acc[6] += b41.z; acc[7] += b41.w;

    float sum = 0.f, sq = 0.f;
#pragma unroll
    for (int i = 0; i < 8; ++i) { sum += acc[i]; sq += acc[i] * acc[i]; }
#pragma unroll
    for (int o = 1; o < 16; o <<= 1) {
        sum += __shfl_xor_sync(0xffffffffu, sum, o);
        sq  += __shfl_xor_sync(0xffffffffu, sq, o);
    }
    const float mu = sum * (1.f / 128.f);
    const float var = sq * (1.f / 128.f) - mu * mu;
    const float rstd = rsqrtf(var + 1e-5f);

    float4 g40 = ((const float4*)gamma)[2 * part];
    float4 g41 = ((const float4*)gamma)[2 * part + 1];
    float4 e40 = ((const float4*)beta)[2 * part];
    float4 e41 = ((const float4*)beta)[2 * part + 1];
    float gm[8] = {g40.x, g40.y, g40.z, g40.w, g41.x, g41.y, g41.z, g41.w};
    float bt[8] = {e40.x, e40.y, e40.z, e40.w, e41.x, e41.y, e41.z, e41.w};

    float o8[8];
#pragma unroll
    for (int i = 0; i < 8; ++i) {
        float t = (acc[i] - mu) * rstd * gm[i] + bt[i];
        o8[i] = (t > 0.f) ? t : 0.01f * t;
    }

    if (outf) {
        if (eid == 0) {
            float4* dst = (float4*)(outf + (size_t)v * 128);
            dst[2 * part]     = make_float4(o8[0], o8[1], o8[2], o8[3]);
            dst[2 * part + 1] = make_float4(o8[4], o8[5], o8[6], o8[7]);
        }
    } else {
        if (eid == 0) {
#pragma unroll
            for (int q = 0; q < 4; ++q) {
                float a = o8[2 * q], b = o8[2 * q + 1];
                s_hi[warp][4 * part + q] = bf2(a, b);
                s_lo[warp][4 * part + q] = bf2(bf_res(a), bf_res(b));
            }
        }
        __syncwarp();
        const int ks = lane >> 2;
        const int t = lane & 3;
        const int kw = ks * 8 + t;
        uint4 o;
        o.x = s_hi[warp][kw];
        o.y = s_hi[warp][kw + 4];
        o.z = s_lo[warp][kw];
        o.w = s_lo[warp][kw + 4];
        g_ap[ap_idx(v, lane)] = o;
    }
}

// ---------------- launcher --------------------------------------------------
extern "C" void kernel_launch(void* const* d_in, const int* in_sizes, int n_in,
                              void* d_out, int out_size) {
    const float* x       = (const float*)d_in[0];
    const int*   ei      = (const int*)  d_in[1];
    const float* W_in    = (const float*)d_in[2];
    const float* b_in    = (const float*)d_in[3];
    const float* Wl      = (const float*)d_in[4];
    const float* att_src = (const float*)d_in[5];
    const float* att_dst = (const float*)d_in[6];
    const float* bias_l  = (const float*)d_in[7];
    const float* gamma   = (const float*)d_in[8];
    const float* beta    = (const float*)d_in[9];
    float* out = (float*)d_out;

    uint4 *pap = nullptr, *papx = nullptr;
    cudaGetSymbolAddress((void**)&pap, g_ap);
    cudaGetSymbolAddress((void**)&papx, g_apx);

    // side stream + fork/join events (created once; capture-legal pattern)
    static cudaStream_t s2 = nullptr;
    static cudaEvent_t evFork = nullptr, evJoin = nullptr;
    if (!s2) {
        cudaStreamCreateWithFlags(&s2, cudaStreamNonBlocking);
        cudaEventCreateWithFlags(&evFork, cudaEventDisableTiming);
        cudaEventCreateWithFlags(&evJoin, cudaEventDisableTiming);
    }

    const dim3 gemm_grid((NN + 127) / 128, 2);        // 782 x 2
    const int node_warp_blocks = (NN + 7) / 8;        // 12500
    const int setup_blocks = 80 + 12500;              // 12580

    // fork: CSR build on side stream, overlapped with setup + first two GEMMs
    cudaEventRecord(evFork, 0);
    cudaStreamWaitEvent(s2, evFork, 0);
    k_zero<<<(NN + 1023) / 1024, 1024, 0, s2>>>();
    k_hist<<<(EE + 255) / 256, 256, 0, s2>>>(ei);
    k_scan_block<<<NB, SCAN_B, 0, s2>>>();
    k_scan_bsums<<<1, 128, 0, s2>>>();
    k_scan_fix<<<NB, SCAN_B, 0, s2>>>();
    k_scatter<<<(EE + 255) / 256, 256, 0, s2>>>(ei);
    cudaEventRecord(evJoin, s2);

    // main stream: setup -> input projection -> layer-0 mode-1 GEMM
    k_setup<<<setup_blocks, 256>>>(x, W_in, Wl);
    mma_gemm<<<gemm_grid, 256>>>(papx, 0, 0, b_in, nullptr, nullptr);
    mma_gemm<<<gemm_grid, 256>>>(pap, 1, 1, nullptr, att_src, att_dst);

    // join: k_agg needs the CSR
    cudaStreamWaitEvent(0, evJoin, 0);

    for (int i = 0; i < 4; i++) {
        if (i > 0)
            mma_gemm<<<gemm_grid, 256>>>(pap, i + 1, 1, nullptr,
                                         att_src + i * 128, att_dst + i * 128);
        float* dst = (i == 3) ? out : nullptr;
        k_agg<<<node_warp_blocks, 256>>>(bias_l + i * 128, gamma + i * 128,
                                         beta + i * 128, dst);
    }
}